// round 1
// baseline (speedup 1.0000x reference)
#include <cuda_runtime.h>
#include <math.h>

#define ROWS 4096          // S*B = 512*8
#define NI 256
#define NO 256
#define SLOW_OUTS 1026

// Scratch (device globals — allocation-free per harness rules)
__device__ float g_A1[ROWS * NI];
__device__ float g_A2[ROWS * NI];
__device__ float g_S1[ROWS * NI];
__device__ float g_S2[ROWS * NI];
__device__ float g_sa[ROWS];
__device__ float g_ss[ROWS];
__device__ float g_DA[ROWS * ROWS];   // 64 MB
__device__ float g_DS[ROWS * ROWS];   // 64 MB

// ---------------------------------------------------------------------------
// Kernel 1: wu = X @ slow_W^T + slow_b ; split into A1/A2/S1/S2, sa/ss
// X: (4096, 256) row-major (rows = s*8+b). slow_W: (1026, 256) row-major.
// Tile: 64x64, K-chunk 16, 256 threads, 4x4 per thread.
// ---------------------------------------------------------------------------
__global__ void k_wu(const float* __restrict__ X,
                     const float* __restrict__ W,
                     const float* __restrict__ bias) {
    __shared__ float As[16][64];   // As[k][m]
    __shared__ float Bs[16][64];   // Bs[k][n]
    const int m0 = blockIdx.y * 64;
    const int n0 = blockIdx.x * 64;
    const int tid = threadIdx.x;
    const int tx = tid & 15, ty = tid >> 4;
    const int tx4 = tx * 4, ty4 = ty * 4;

    float acc[4][4];
#pragma unroll
    for (int i = 0; i < 4; i++)
#pragma unroll
        for (int j = 0; j < 4; j++) acc[i][j] = 0.f;

    const int lrow = tid >> 2;          // 0..63
    const int lcol = (tid & 3) * 4;     // 0,4,8,12

    for (int k0 = 0; k0 < 256; k0 += 16) {
        float4 va = *(const float4*)(X + (m0 + lrow) * 256 + k0 + lcol);
        As[lcol + 0][lrow] = va.x;
        As[lcol + 1][lrow] = va.y;
        As[lcol + 2][lrow] = va.z;
        As[lcol + 3][lrow] = va.w;
        int wrow = n0 + lrow;
        float4 vb = make_float4(0.f, 0.f, 0.f, 0.f);
        if (wrow < SLOW_OUTS)
            vb = *(const float4*)(W + wrow * 256 + k0 + lcol);
        Bs[lcol + 0][lrow] = vb.x;
        Bs[lcol + 1][lrow] = vb.y;
        Bs[lcol + 2][lrow] = vb.z;
        Bs[lcol + 3][lrow] = vb.w;
        __syncthreads();
#pragma unroll
        for (int kk = 0; kk < 16; kk++) {
            float a[4], b[4];
            *(float4*)a = *(const float4*)&As[kk][ty4];
            *(float4*)b = *(const float4*)&Bs[kk][tx4];
#pragma unroll
            for (int i = 0; i < 4; i++)
#pragma unroll
                for (int j = 0; j < 4; j++) acc[i][j] += a[i] * b[j];
        }
        __syncthreads();
    }

#pragma unroll
    for (int i = 0; i < 4; i++) {
        const int r = m0 + ty4 + i;
#pragma unroll
        for (int j = 0; j < 4; j++) {
            const int o = n0 + tx4 + j;
            if (o >= SLOW_OUTS) continue;
            float v = acc[i][j] + bias[o];
            if (o < 256)       g_A1[r * 256 + o] = v;
            else if (o < 512)  g_A2[r * 256 + (o - 256)] = v;
            else if (o < 768)  g_S1[r * 256 + (o - 512)] = v;
            else if (o < 1024) g_S2[r * 256 + (o - 768)] = v;
            else if (o == 1024) g_sa[r] = 1.f / (1.f + expf(-v));
            else                g_ss[r] = 1.f / (1.f + expf(-v));
        }
    }
}

// ---------------------------------------------------------------------------
// Kernel 2: base output  out = X @ W0^T   (4096 x 256)
// ---------------------------------------------------------------------------
__global__ void k_base(const float* __restrict__ X,
                       const float* __restrict__ W0,
                       float* __restrict__ out) {
    __shared__ float As[16][64];
    __shared__ float Bs[16][64];
    const int m0 = blockIdx.y * 64;
    const int n0 = blockIdx.x * 64;
    const int tid = threadIdx.x;
    const int tx = tid & 15, ty = tid >> 4;
    const int tx4 = tx * 4, ty4 = ty * 4;

    float acc[4][4];
#pragma unroll
    for (int i = 0; i < 4; i++)
#pragma unroll
        for (int j = 0; j < 4; j++) acc[i][j] = 0.f;

    const int lrow = tid >> 2;
    const int lcol = (tid & 3) * 4;

    for (int k0 = 0; k0 < 256; k0 += 16) {
        float4 va = *(const float4*)(X + (m0 + lrow) * 256 + k0 + lcol);
        As[lcol + 0][lrow] = va.x;
        As[lcol + 1][lrow] = va.y;
        As[lcol + 2][lrow] = va.z;
        As[lcol + 3][lrow] = va.w;
        float4 vb = *(const float4*)(W0 + (n0 + lrow) * 256 + k0 + lcol);
        Bs[lcol + 0][lrow] = vb.x;
        Bs[lcol + 1][lrow] = vb.y;
        Bs[lcol + 2][lrow] = vb.z;
        Bs[lcol + 3][lrow] = vb.w;
        __syncthreads();
#pragma unroll
        for (int kk = 0; kk < 16; kk++) {
            float a[4], b[4];
            *(float4*)a = *(const float4*)&As[kk][ty4];
            *(float4*)b = *(const float4*)&Bs[kk][tx4];
#pragma unroll
            for (int i = 0; i < 4; i++)
#pragma unroll
                for (int j = 0; j < 4; j++) acc[i][j] += a[i] * b[j];
        }
        __syncthreads();
    }
#pragma unroll
    for (int i = 0; i < 4; i++) {
        const int r = m0 + ty4 + i;
#pragma unroll
        for (int j = 0; j < 4; j++)
            out[r * 256 + n0 + tx4 + j] = acc[i][j];
    }
}

// ---------------------------------------------------------------------------
// Kernel 3: DA = X @ A2^T, DS = X @ S2^T (causal triangle of tiles only)
// blockIdx.x = key tile (64 keys), blockIdx.y = query tile, blockIdx.z = which
// ---------------------------------------------------------------------------
__global__ void k_qk(const float* __restrict__ X) {
    const int kt = blockIdx.x, qt = blockIdx.y;
    if (kt > qt) return;      // key-step > query-step: never read
    const float* Bm  = blockIdx.z ? g_S2 : g_A2;
    float*       Dst = blockIdx.z ? g_DS : g_DA;

    __shared__ float As[16][64];   // As[i][q]
    __shared__ float Bs[16][64];   // Bs[i][k]
    const int m0 = qt * 64;
    const int n0 = kt * 64;
    const int tid = threadIdx.x;
    const int tx = tid & 15, ty = tid >> 4;
    const int tx4 = tx * 4, ty4 = ty * 4;

    float acc[4][4];
#pragma unroll
    for (int i = 0; i < 4; i++)
#pragma unroll
        for (int j = 0; j < 4; j++) acc[i][j] = 0.f;

    const int lrow = tid >> 2;
    const int lcol = (tid & 3) * 4;

    for (int k0 = 0; k0 < 256; k0 += 16) {
        float4 va = *(const float4*)(X + (m0 + lrow) * 256 + k0 + lcol);
        As[lcol + 0][lrow] = va.x;
        As[lcol + 1][lrow] = va.y;
        As[lcol + 2][lrow] = va.z;
        As[lcol + 3][lrow] = va.w;
        float4 vb = *(const float4*)(Bm + (n0 + lrow) * 256 + k0 + lcol);
        Bs[lcol + 0][lrow] = vb.x;
        Bs[lcol + 1][lrow] = vb.y;
        Bs[lcol + 2][lrow] = vb.z;
        Bs[lcol + 3][lrow] = vb.w;
        __syncthreads();
#pragma unroll
        for (int kk = 0; kk < 16; kk++) {
            float a[4], b[4];
            *(float4*)a = *(const float4*)&As[kk][ty4];
            *(float4*)b = *(const float4*)&Bs[kk][tx4];
#pragma unroll
            for (int i = 0; i < 4; i++)
#pragma unroll
                for (int j = 0; j < 4; j++) acc[i][j] += a[i] * b[j];
        }
        __syncthreads();
    }
#pragma unroll
    for (int i = 0; i < 4; i++) {
        const int q = m0 + ty4 + i;
#pragma unroll
        for (int j = 0; j < 4; j += 4) {
            float4 v = make_float4(acc[i][0], acc[i][1], acc[i][2], acc[i][3]);
            *(float4*)(Dst + q * ROWS + n0 + tx4) = v;
        }
    }
}

// ---------------------------------------------------------------------------
// Kernel 4: out += (mask*sa .* DA) @ A1  -  (mask*ss .* DS) @ S1
// 256 blocks: qt (descending for balance) x 4 output-column tiles.
// ---------------------------------------------------------------------------
__global__ void k_av(float* __restrict__ out) {
    const int idx = blockIdx.x;
    const int qt = 63 - (idx >> 2);
    const int ot = idx & 3;
    const int q0 = qt * 64;
    const int o0 = ot * 64;

    __shared__ float PA[16][64];   // PA[k][q]  scaled DA
    __shared__ float PS[16][64];   // PS[k][q]  scaled DS
    __shared__ float VA[16][64];   // VA[k][o]  A1
    __shared__ float VS[16][64];   // VS[k][o]  S1

    const int tid = threadIdx.x;
    const int tx = tid & 15, ty = tid >> 4;
    const int tx4 = tx * 4, ty4 = ty * 4;

    float acc[4][4];
#pragma unroll
    for (int i = 0; i < 4; i++)
#pragma unroll
        for (int j = 0; j < 4; j++) acc[i][j] = 0.f;

    // P-load mapping: 64 q-rows x 16 k-cols
    const int prow = tid >> 2;           // 0..63  (q offset)
    const int pcol = (tid & 3) * 4;      // 0,4,8,12 (k offset)
    const int q    = q0 + prow;
    const int b    = q & 7;
    const int s    = q >> 3;
    // V-load mapping: 16 k-rows x 64 o-cols
    const int vrow = tid >> 4;           // 0..15
    const int vcol = (tid & 15) * 4;     // 0..60

    const int nk = (qt + 1) * 64;        // causal key count (step granularity)

    for (int k0 = 0; k0 < nk; k0 += 16) {
        const int kabs = k0 + pcol;       // multiple of 4; t constant over 4
        const int t = kabs >> 3;
        const bool live = (t <= s);
        const float scA = live ? g_sa[(t << 3) + b] : 0.f;
        const float scS = live ? g_ss[(t << 3) + b] : 0.f;
        float4 da = *(const float4*)(g_DA + q * ROWS + kabs);
        float4 ds = *(const float4*)(g_DS + q * ROWS + kabs);
        PA[pcol + 0][prow] = da.x * scA;
        PA[pcol + 1][prow] = da.y * scA;
        PA[pcol + 2][prow] = da.z * scA;
        PA[pcol + 3][prow] = da.w * scA;
        PS[pcol + 0][prow] = ds.x * scS;
        PS[pcol + 1][prow] = ds.y * scS;
        PS[pcol + 2][prow] = ds.z * scS;
        PS[pcol + 3][prow] = ds.w * scS;

        *(float4*)&VA[vrow][vcol] = *(const float4*)(g_A1 + (k0 + vrow) * 256 + o0 + vcol);
        *(float4*)&VS[vrow][vcol] = *(const float4*)(g_S1 + (k0 + vrow) * 256 + o0 + vcol);
        __syncthreads();
#pragma unroll
        for (int kk = 0; kk < 16; kk++) {
            float aA[4], aS[4], bA[4], bS[4];
            *(float4*)aA = *(const float4*)&PA[kk][ty4];
            *(float4*)aS = *(const float4*)&PS[kk][ty4];
            *(float4*)bA = *(const float4*)&VA[kk][tx4];
            *(float4*)bS = *(const float4*)&VS[kk][tx4];
#pragma unroll
            for (int i = 0; i < 4; i++)
#pragma unroll
                for (int j = 0; j < 4; j++)
                    acc[i][j] += aA[i] * bA[j] - aS[i] * bS[j];
        }
        __syncthreads();
    }

#pragma unroll
    for (int i = 0; i < 4; i++) {
        const int r = q0 + ty4 + i;
#pragma unroll
        for (int j = 0; j < 4; j++)
            out[r * 256 + o0 + tx4 + j] += acc[i][j];
    }
}

// ---------------------------------------------------------------------------
extern "C" void kernel_launch(void* const* d_in, const int* in_sizes, int n_in,
                              void* d_out, int out_size) {
    const float* x      = (const float*)d_in[0];   // (512,8,256)
    const float* slow_W = (const float*)d_in[1];   // (1026,256)
    const float* slow_b = (const float*)d_in[2];   // (1026,)
    const float* fw0    = (const float*)d_in[3];   // (256,256)
    float* out = (float*)d_out;                    // (512,8,256)

    k_wu  <<<dim3(17, 64), 256>>>(x, slow_W, slow_b);
    k_base<<<dim3(4, 64), 256>>>(x, fw0, out);
    k_qk  <<<dim3(64, 64, 2), 256>>>(x);
    k_av  <<<256, 256>>>(out);
}

// round 5
// speedup vs baseline: 2.5155x; 2.5155x over previous
#include <cuda_runtime.h>
#include <cuda_bf16.h>
#include <math.h>
#include <stdint.h>

#define ROWS 4096          // S*B = 512*8
#define KCAT 8192          // concat keys: [A (4096) | S (4096)]
#define NI 256
#define SLOW_OUTS 1026

// ---------------------------------------------------------------------------
// Scratch (device globals)
// ---------------------------------------------------------------------------
__device__ __align__(16) float g_A1[ROWS * NI];
__device__ __align__(16) float g_A2[ROWS * NI];
__device__ __align__(16) float g_S1[ROWS * NI];
__device__ __align__(16) float g_S2[ROWS * NI];
__device__ float g_sa[ROWS];
__device__ float g_ss[ROWS];

__device__ __align__(16) __nv_bfloat16 g_Xhi[ROWS * NI];
__device__ __align__(16) __nv_bfloat16 g_Xlo[ROWS * NI];
__device__ __align__(16) __nv_bfloat16 g_Khi[KCAT * NI];   // rows: [A2 ; S2]
__device__ __align__(16) __nv_bfloat16 g_Klo[KCAT * NI];
__device__ __align__(16) __nv_bfloat16 g_VThi[NI * KCAT];  // VT[o][kcat] = [A1;S1][k][o]
__device__ __align__(16) __nv_bfloat16 g_VTlo[NI * KCAT];
__device__ __align__(16) __nv_bfloat16 g_Phi[(size_t)ROWS * KCAT];  // 64 MB
__device__ __align__(16) __nv_bfloat16 g_Plo[(size_t)ROWS * KCAT];  // 64 MB

// ---------------------------------------------------------------------------
// Helpers
// ---------------------------------------------------------------------------
__device__ __forceinline__ uint32_t smem_to_u32(const void* p) {
    uint32_t a;
    asm("{ .reg .u64 t; cvta.to.shared.u64 t, %1; cvt.u32.u64 %0, t; }" : "=r"(a) : "l"(p));
    return a;
}

__device__ __forceinline__ void cpa16(uint32_t s, const __nv_bfloat16* g) {
    asm volatile("cp.async.cg.shared.global [%0], [%1], 16;"
        :: "r"(s), "l"(__cvta_generic_to_global((const void*)g)));
}
#define CP_COMMIT() asm volatile("cp.async.commit_group;")

__device__ __forceinline__ void ldx4(uint32_t* r, uint32_t addr) {
    asm volatile("ldmatrix.sync.aligned.m8n8.x4.shared.b16 {%0,%1,%2,%3}, [%4];"
        : "=r"(r[0]), "=r"(r[1]), "=r"(r[2]), "=r"(r[3]) : "r"(addr));
}

__device__ __forceinline__ void mma16816(float* c, const uint32_t* a, const uint32_t* b) {
    asm volatile(
        "mma.sync.aligned.m16n8k16.row.col.f32.bf16.bf16.f32 "
        "{%0,%1,%2,%3}, {%4,%5,%6,%7}, {%8,%9}, {%0,%1,%2,%3};"
        : "+f"(c[0]), "+f"(c[1]), "+f"(c[2]), "+f"(c[3])
        : "r"(a[0]), "r"(a[1]), "r"(a[2]), "r"(a[3]), "r"(b[0]), "r"(b[1]));
}

// Stage layout: 4 operand arrays (Ah, Al, Bh, Bl), each 128 rows x 32 bf16,
// rows padded to 40 bf16 (80 bytes) -> conflict-free ldmatrix (rows distinct mod 128B).
#define ROWB    80
#define OFF_AH  0
#define OFF_AL  10240
#define OFF_BH  20480
#define OFF_BL  30720
#define STAGE   40960
#define GEMM_SMEM (2 * STAGE)

__device__ __forceinline__ void load_stage(uint32_t st,
    const __nv_bfloat16* Ah, const __nv_bfloat16* Al,
    const __nv_bfloat16* Bh, const __nv_bfloat16* Bl,
    int sA, int sB, int tid)
{
#pragma unroll
    for (int h = 0; h < 2; h++) {
        int c = tid + h * 256;
        int row = c >> 2, seg = c & 3;
        uint32_t d = st + row * ROWB + seg * 16;
        int go = seg * 8;
        cpa16(d + OFF_AH, Ah + row * sA + go);
        cpa16(d + OFF_AL, Al + row * sA + go);
        cpa16(d + OFF_BH, Bh + row * sB + go);
        cpa16(d + OFF_BL, Bl + row * sB + go);
    }
}

// 3-term split-compensated bf16 MMA over one 32-wide K stage.
// acc[mf][nf][4]: warp tile 32(M) x 64(N).
__device__ __forceinline__ void compute_stage(uint32_t st, int warp_m, int warp_n,
                                              int lane, float acc[2][8][4])
{
    const int rowsel = lane & 15;
    const uint32_t halfsel = (lane >> 4) * 16;
#pragma unroll
    for (int k16 = 0; k16 < 2; k16++) {
        const uint32_t off = k16 * 32 + halfsel;
        uint32_t ah[2][4], al[2][4], bh[8][2], bl[8][2];
#pragma unroll
        for (int mf = 0; mf < 2; mf++) {
            uint32_t base = st + (warp_m + mf * 16 + rowsel) * ROWB + off;
            ldx4(ah[mf], base + OFF_AH);
            ldx4(al[mf], base + OFF_AL);
        }
#pragma unroll
        for (int np = 0; np < 4; np++) {
            uint32_t base = st + (warp_n + np * 16 + rowsel) * ROWB + off;
            uint32_t r[4];
            ldx4(r, base + OFF_BH);
            bh[2*np][0] = r[0]; bh[2*np][1] = r[2];
            bh[2*np+1][0] = r[1]; bh[2*np+1][1] = r[3];
            ldx4(r, base + OFF_BL);
            bl[2*np][0] = r[0]; bl[2*np][1] = r[2];
            bl[2*np+1][0] = r[1]; bl[2*np+1][1] = r[3];
        }
#pragma unroll
        for (int mf = 0; mf < 2; mf++)
#pragma unroll
            for (int nf = 0; nf < 8; nf++) {
                mma16816(acc[mf][nf], ah[mf], bh[nf]);
                mma16816(acc[mf][nf], ah[mf], bl[nf]);
                mma16816(acc[mf][nf], al[mf], bh[nf]);
            }
    }
}

// ---------------------------------------------------------------------------
// Kernel: wu = X @ slow_W^T + slow_b  (fp32 SIMT; splits into A1..S2, sa, ss)
// ---------------------------------------------------------------------------
__global__ void k_wu(const float* __restrict__ X,
                     const float* __restrict__ W,
                     const float* __restrict__ bias) {
    __shared__ float As[16][64];
    __shared__ float Bs[16][64];
    const int m0 = blockIdx.y * 64;
    const int n0 = blockIdx.x * 64;
    const int tid = threadIdx.x;
    const int tx = tid & 15, ty = tid >> 4;
    const int tx4 = tx * 4, ty4 = ty * 4;

    float acc[4][4];
#pragma unroll
    for (int i = 0; i < 4; i++)
#pragma unroll
        for (int j = 0; j < 4; j++) acc[i][j] = 0.f;

    const int lrow = tid >> 2;
    const int lcol = (tid & 3) * 4;

    for (int k0 = 0; k0 < 256; k0 += 16) {
        float4 va = *(const float4*)(X + (m0 + lrow) * 256 + k0 + lcol);
        As[lcol + 0][lrow] = va.x; As[lcol + 1][lrow] = va.y;
        As[lcol + 2][lrow] = va.z; As[lcol + 3][lrow] = va.w;
        int wrow = n0 + lrow;
        float4 vb = make_float4(0.f, 0.f, 0.f, 0.f);
        if (wrow < SLOW_OUTS) vb = *(const float4*)(W + wrow * 256 + k0 + lcol);
        Bs[lcol + 0][lrow] = vb.x; Bs[lcol + 1][lrow] = vb.y;
        Bs[lcol + 2][lrow] = vb.z; Bs[lcol + 3][lrow] = vb.w;
        __syncthreads();
#pragma unroll
        for (int kk = 0; kk < 16; kk++) {
            float a[4], b[4];
            *(float4*)a = *(const float4*)&As[kk][ty4];
            *(float4*)b = *(const float4*)&Bs[kk][tx4];
#pragma unroll
            for (int i = 0; i < 4; i++)
#pragma unroll
                for (int j = 0; j < 4; j++) acc[i][j] += a[i] * b[j];
        }
        __syncthreads();
    }

#pragma unroll
    for (int i = 0; i < 4; i++) {
        const int r = m0 + ty4 + i;
#pragma unroll
        for (int j = 0; j < 4; j++) {
            const int o = n0 + tx4 + j;
            if (o >= SLOW_OUTS) continue;
            float v = acc[i][j] + bias[o];
            if (o < 256)       g_A1[r * 256 + o] = v;
            else if (o < 512)  g_A2[r * 256 + (o - 256)] = v;
            else if (o < 768)  g_S1[r * 256 + (o - 512)] = v;
            else if (o < 1024) g_S2[r * 256 + (o - 768)] = v;
            else if (o == 1024) g_sa[r] = 1.f / (1.f + expf(-v));
            else                g_ss[r] = 1.f / (1.f + expf(-v));
        }
    }
}

// ---------------------------------------------------------------------------
// Kernel: base output  out = X @ W0^T  (fp32 SIMT)
// ---------------------------------------------------------------------------
__global__ void k_base(const float* __restrict__ X,
                       const float* __restrict__ W0,
                       float* __restrict__ out) {
    __shared__ float As[16][64];
    __shared__ float Bs[16][64];
    const int m0 = blockIdx.y * 64;
    const int n0 = blockIdx.x * 64;
    const int tid = threadIdx.x;
    const int tx = tid & 15, ty = tid >> 4;
    const int tx4 = tx * 4, ty4 = ty * 4;

    float acc[4][4];
#pragma unroll
    for (int i = 0; i < 4; i++)
#pragma unroll
        for (int j = 0; j < 4; j++) acc[i][j] = 0.f;

    const int lrow = tid >> 2;
    const int lcol = (tid & 3) * 4;

    for (int k0 = 0; k0 < 256; k0 += 16) {
        float4 va = *(const float4*)(X + (m0 + lrow) * 256 + k0 + lcol);
        As[lcol + 0][lrow] = va.x; As[lcol + 1][lrow] = va.y;
        As[lcol + 2][lrow] = va.z; As[lcol + 3][lrow] = va.w;
        float4 vb = *(const float4*)(W0 + (n0 + lrow) * 256 + k0 + lcol);
        Bs[lcol + 0][lrow] = vb.x; Bs[lcol + 1][lrow] = vb.y;
        Bs[lcol + 2][lrow] = vb.z; Bs[lcol + 3][lrow] = vb.w;
        __syncthreads();
#pragma unroll
        for (int kk = 0; kk < 16; kk++) {
            float a[4], b[4];
            *(float4*)a = *(const float4*)&As[kk][ty4];
            *(float4*)b = *(const float4*)&Bs[kk][tx4];
#pragma unroll
            for (int i = 0; i < 4; i++)
#pragma unroll
                for (int j = 0; j < 4; j++) acc[i][j] += a[i] * b[j];
        }
        __syncthreads();
    }
#pragma unroll
    for (int i = 0; i < 4; i++) {
        const int r = m0 + ty4 + i;
#pragma unroll
        for (int j = 0; j < 4; j++)
            out[r * 256 + n0 + tx4 + j] = acc[i][j];
    }
}

// ---------------------------------------------------------------------------
// Prep kernels: bf16 hi/lo splits + V transpose
// ---------------------------------------------------------------------------
__global__ void k_split_X(const float* __restrict__ x) {
    int i = blockIdx.x * blockDim.x + threadIdx.x;
    if (i >= ROWS * NI) return;
    float v = x[i];
    __nv_bfloat16 h = __float2bfloat16(v);
    g_Xhi[i] = h;
    g_Xlo[i] = __float2bfloat16(v - __bfloat162float(h));
}

__global__ void k_split_K() {
    int i = blockIdx.x * blockDim.x + threadIdx.x;
    if (i >= KCAT * NI) return;
    const int half = ROWS * NI;
    float v = (i < half) ? g_A2[i] : g_S2[i - half];
    __nv_bfloat16 h = __float2bfloat16(v);
    g_Khi[i] = h;
    g_Klo[i] = __float2bfloat16(v - __bfloat162float(h));
}

__global__ void k_trans_V() {
    __shared__ float t[32][33];
    const int rz = blockIdx.z;
    const float* src = rz ? g_S1 : g_A1;
    const int k0 = blockIdx.x * 32, o0 = blockIdx.y * 32;
    const int tx = threadIdx.x, ty = threadIdx.y;   // 32 x 8
#pragma unroll
    for (int i = 0; i < 32; i += 8)
        t[ty + i][tx] = src[(k0 + ty + i) * 256 + o0 + tx];
    __syncthreads();
#pragma unroll
    for (int i = 0; i < 32; i += 8) {
        float v = t[tx][ty + i];
        __nv_bfloat16 h = __float2bfloat16(v);
        int dst = (o0 + ty + i) * KCAT + rz * ROWS + k0 + tx;
        g_VThi[dst] = h;
        g_VTlo[dst] = __float2bfloat16(v - __bfloat162float(h));
    }
}

// ---------------------------------------------------------------------------
// GEMM1: P[q, kcat] = mask * gate * (X @ [A2;S2]^T)   (mma.sync bf16, 3-term)
// grid 1056: 2 regions x lower-triangular tiles (nt <= mt) of 128x128
// ---------------------------------------------------------------------------
__global__ void __launch_bounds__(256, 1) k_gemm1() {
    extern __shared__ char smem[];
    const uint32_t sb = smem_to_u32(smem);
    const int tid = threadIdx.x, lane = tid & 31, wid = tid >> 5;
    const int warp_m = (wid >> 1) * 32, warp_n = (wid & 1) * 64;

    int i = blockIdx.x, rg = 0;
    if (i >= 528) { rg = 1; i -= 528; }
    int mt = 0;
    while ((mt + 1) * (mt + 2) / 2 <= i) mt++;
    const int nt = i - mt * (mt + 1) / 2;
    const int m0 = mt * 128;
    const int keybase = nt * 128;

    const __nv_bfloat16* Ah = g_Xhi + m0 * NI;
    const __nv_bfloat16* Al = g_Xlo + m0 * NI;
    const __nv_bfloat16* Bh = g_Khi + (rg * ROWS + keybase) * NI;
    const __nv_bfloat16* Bl = g_Klo + (rg * ROWS + keybase) * NI;

    float acc[2][8][4];
#pragma unroll
    for (int a = 0; a < 2; a++)
#pragma unroll
        for (int b = 0; b < 8; b++)
#pragma unroll
            for (int c = 0; c < 4; c++) acc[a][b][c] = 0.f;

    load_stage(sb, Ah, Al, Bh, Bl, NI, NI, tid);
    CP_COMMIT();
#pragma unroll 1
    for (int kc = 0; kc < 8; kc++) {
        if (kc < 7) {
            const int ko = (kc + 1) * 32;
            load_stage(sb + ((kc + 1) & 1) * STAGE, Ah + ko, Al + ko, Bh + ko, Bl + ko,
                       NI, NI, tid);
            CP_COMMIT();
            asm volatile("cp.async.wait_group 1;");
        } else {
            asm volatile("cp.async.wait_group 0;");
        }
        __syncthreads();
        compute_stage(sb + (kc & 1) * STAGE, warp_m, warp_n, lane, acc);
        __syncthreads();
    }

    // Epilogue: scale by causal mask * gate, split to bf16 hi/lo, store.
    const int g = lane >> 2, t2 = (lane & 3) * 2;
#pragma unroll
    for (int mf = 0; mf < 2; mf++) {
        const int q0 = m0 + warp_m + mf * 16 + g;  // second row = q0 + 8, same b
        const int s0 = q0 >> 3, b = q0 & 7;
#pragma unroll
        for (int nf = 0; nf < 8; nf++) {
            const int col = keybase + warp_n + nf * 8 + t2;   // even, region-local
            const int t = col >> 3;
            const float gv = rg ? -g_ss[t * 8 + b] : g_sa[t * 8 + b];
            const float sc0 = (t <= s0) ? gv : 0.f;
            const float sc1 = (t <= s0 + 1) ? gv : 0.f;
            const float* c = acc[mf][nf];
            const size_t p0 = (size_t)q0 * KCAT + rg * ROWS + col;
            const size_t p1 = p0 + (size_t)8 * KCAT;

            float v0 = c[0] * sc0, v1 = c[1] * sc0;
            __nv_bfloat16 h0 = __float2bfloat16(v0), h1 = __float2bfloat16(v1);
            *(__nv_bfloat162*)(g_Phi + p0) = __nv_bfloat162(h0, h1);
            *(__nv_bfloat162*)(g_Plo + p0) = __nv_bfloat162(
                __float2bfloat16(v0 - __bfloat162float(h0)),
                __float2bfloat16(v1 - __bfloat162float(h1)));

            float w0 = c[2] * sc1, w1 = c[3] * sc1;
            __nv_bfloat16 k0 = __float2bfloat16(w0), k1 = __float2bfloat16(w1);
            *(__nv_bfloat162*)(g_Phi + p1) = __nv_bfloat162(k0, k1);
            *(__nv_bfloat162*)(g_Plo + p1) = __nv_bfloat162(
                __float2bfloat16(w0 - __bfloat162float(k0)),
                __float2bfloat16(w1 - __bfloat162float(k1)));
        }
    }
}

// ---------------------------------------------------------------------------
// GEMM2: out[q, o] += P[q, :] @ [A1;S1][:, o]   (mma.sync bf16, split-K+atomics)
// Logical k in [0, 256*(mt+1)) maps to phys [0, half) U [4096, 4096+half).
// grid (32 mt, 2 ot, 8 kc), early-exit on dead kc.
// ---------------------------------------------------------------------------
__global__ void __launch_bounds__(256, 1) k_gemm2(float* __restrict__ out) {
    const int mt = blockIdx.x, ot = blockIdx.y, kc = blockIdx.z;
    const int nch = (mt + 4) >> 2;
    if (kc >= nch) return;
    const int klive = 256 * (mt + 1);
    const int kstart = kc * 1024;
    const int kend = (kstart + 1024 < klive) ? kstart + 1024 : klive;
    const int half = 128 * (mt + 1);
    const int m0 = mt * 128, o0 = ot * 128;
    const int nsteps = (kend - kstart) >> 5;

    extern __shared__ char smem[];
    const uint32_t sb = smem_to_u32(smem);
    const int tid = threadIdx.x, lane = tid & 31, wid = tid >> 5;
    const int warp_m = (wid >> 1) * 32, warp_n = (wid & 1) * 64;

    const __nv_bfloat16* Ah = g_Phi + (size_t)m0 * KCAT;
    const __nv_bfloat16* Al = g_Plo + (size_t)m0 * KCAT;
    const __nv_bfloat16* Bh = g_VThi + (size_t)o0 * KCAT;
    const __nv_bfloat16* Bl = g_VTlo + (size_t)o0 * KCAT;

    float acc[2][8][4];
#pragma unroll
    for (int a = 0; a < 2; a++)
#pragma unroll
        for (int b = 0; b < 8; b++)
#pragma unroll
            for (int c = 0; c < 4; c++) acc[a][b][c] = 0.f;

    int lk0 = kstart;
    int pk0 = (lk0 < half) ? lk0 : lk0 + ROWS - half;
    load_stage(sb, Ah + pk0, Al + pk0, Bh + pk0, Bl + pk0, KCAT, KCAT, tid);
    CP_COMMIT();
#pragma unroll 1
    for (int s = 0; s < nsteps; s++) {
        if (s < nsteps - 1) {
            const int lk = kstart + (s + 1) * 32;
            const int pk = (lk < half) ? lk : lk + ROWS - half;
            load_stage(sb + ((s + 1) & 1) * STAGE, Ah + pk, Al + pk, Bh + pk, Bl + pk,
                       KCAT, KCAT, tid);
            CP_COMMIT();
            asm volatile("cp.async.wait_group 1;");
        } else {
            asm volatile("cp.async.wait_group 0;");
        }
        __syncthreads();
        compute_stage(sb + (s & 1) * STAGE, warp_m, warp_n, lane, acc);
        __syncthreads();
    }

    // Epilogue: atomic accumulate into out[q, o]
    const int g = lane >> 2, t2 = (lane & 3) * 2;
#pragma unroll
    for (int mf = 0; mf < 2; mf++) {
        const int q = m0 + warp_m + mf * 16 + g;
#pragma unroll
        for (int nf = 0; nf < 8; nf++) {
            const int o = o0 + warp_n + nf * 8 + t2;
            const float* c = acc[mf][nf];
            atomicAdd(out + q * 256 + o,           c[0]);
            atomicAdd(out + q * 256 + o + 1,       c[1]);
            atomicAdd(out + (q + 8) * 256 + o,     c[2]);
            atomicAdd(out + (q + 8) * 256 + o + 1, c[3]);
        }
    }
}

// ---------------------------------------------------------------------------
extern "C" void kernel_launch(void* const* d_in, const int* in_sizes, int n_in,
                              void* d_out, int out_size) {
    const float* x      = (const float*)d_in[0];   // (512,8,256)
    const float* slow_W = (const float*)d_in[1];   // (1026,256)
    const float* slow_b = (const float*)d_in[2];   // (1026,)
    const float* fw0    = (const float*)d_in[3];   // (256,256)
    float* out = (float*)d_out;                    // (512,8,256)

    // Unconditional every call: kernel_launch must do identical work on every
    // invocation (no static guards — harness contract).
    cudaFuncSetAttribute(k_gemm1, cudaFuncAttributeMaxDynamicSharedMemorySize, GEMM_SMEM);
    cudaFuncSetAttribute(k_gemm2, cudaFuncAttributeMaxDynamicSharedMemorySize, GEMM_SMEM);

    k_wu     <<<dim3(17, 64), 256>>>(x, slow_W, slow_b);
    k_base   <<<dim3(4, 64), 256>>>(x, fw0, out);
    k_split_X<<<(ROWS * NI + 255) / 256, 256>>>(x);
    k_split_K<<<(KCAT * NI + 255) / 256, 256>>>();
    k_trans_V<<<dim3(128, 8, 2), dim3(32, 8)>>>();
    k_gemm1  <<<1056, 256, GEMM_SMEM>>>();
    k_gemm2  <<<dim3(32, 2, 8), 256, GEMM_SMEM>>>(out);
}

// round 6
// speedup vs baseline: 2.9842x; 1.1863x over previous
#include <cuda_runtime.h>
#include <cuda_bf16.h>
#include <math.h>
#include <stdint.h>

#define ROWS 4096          // S*B = 512*8
#define KCAT 8192          // concat keys: [A (4096) | S (4096)]
#define NI 256
#define SLOW_OUTS 1026

// ---------------------------------------------------------------------------
// Scratch (device globals)
// ---------------------------------------------------------------------------
__device__ __align__(16) float g_A1[ROWS * NI];
__device__ __align__(16) float g_S1[ROWS * NI];
__device__ float g_sa[ROWS];
__device__ float g_ss[ROWS];

__device__ __align__(16) __nv_bfloat16 g_Xhi[ROWS * NI];
__device__ __align__(16) __nv_bfloat16 g_Xlo[ROWS * NI];
__device__ __align__(16) __nv_bfloat16 g_Whi[1024 * NI];   // slow_W rows 0..1023
__device__ __align__(16) __nv_bfloat16 g_Wlo[1024 * NI];
__device__ __align__(16) __nv_bfloat16 g_W0hi[NI * NI];    // fast_W0
__device__ __align__(16) __nv_bfloat16 g_W0lo[NI * NI];
__device__ __align__(16) __nv_bfloat16 g_Khi[KCAT * NI];   // rows: [A2 ; S2]
__device__ __align__(16) __nv_bfloat16 g_Klo[KCAT * NI];
__device__ __align__(16) __nv_bfloat16 g_VThi[NI * KCAT];  // VT[o][kcat] = [A1;S1][k][o]
__device__ __align__(16) __nv_bfloat16 g_VTlo[NI * KCAT];
__device__ __align__(16) __nv_bfloat16 g_Phi[(size_t)ROWS * KCAT];  // 64 MB
__device__ __align__(16) __nv_bfloat16 g_Plo[(size_t)ROWS * KCAT];  // 64 MB

// ---------------------------------------------------------------------------
// Helpers
// ---------------------------------------------------------------------------
__device__ __forceinline__ uint32_t smem_to_u32(const void* p) {
    uint32_t a;
    asm("{ .reg .u64 t; cvta.to.shared.u64 t, %1; cvt.u32.u64 %0, t; }" : "=r"(a) : "l"(p));
    return a;
}

__device__ __forceinline__ void cpa16(uint32_t s, const __nv_bfloat16* g) {
    asm volatile("cp.async.cg.shared.global [%0], [%1], 16;"
        :: "r"(s), "l"(__cvta_generic_to_global((const void*)g)));
}
#define CP_COMMIT() asm volatile("cp.async.commit_group;")

__device__ __forceinline__ void ldx4(uint32_t* r, uint32_t addr) {
    asm volatile("ldmatrix.sync.aligned.m8n8.x4.shared.b16 {%0,%1,%2,%3}, [%4];"
        : "=r"(r[0]), "=r"(r[1]), "=r"(r[2]), "=r"(r[3]) : "r"(addr));
}

__device__ __forceinline__ void mma16816(float* c, const uint32_t* a, const uint32_t* b) {
    asm volatile(
        "mma.sync.aligned.m16n8k16.row.col.f32.bf16.bf16.f32 "
        "{%0,%1,%2,%3}, {%4,%5,%6,%7}, {%8,%9}, {%0,%1,%2,%3};"
        : "+f"(c[0]), "+f"(c[1]), "+f"(c[2]), "+f"(c[3])
        : "r"(a[0]), "r"(a[1]), "r"(a[2]), "r"(a[3]), "r"(b[0]), "r"(b[1]));
}

// Stage layout: 4 operand arrays (Ah, Al, Bh, Bl), each 128 rows x 32 bf16,
// rows padded to 40 bf16 (80 bytes) -> conflict-free ldmatrix.
#define ROWB    80
#define OFF_AH  0
#define OFF_AL  10240
#define OFF_BH  20480
#define OFF_BL  30720
#define STAGE   40960
#define GEMM_SMEM (2 * STAGE)

__device__ __forceinline__ void load_stage(uint32_t st,
    const __nv_bfloat16* Ah, const __nv_bfloat16* Al,
    const __nv_bfloat16* Bh, const __nv_bfloat16* Bl,
    int sA, int sB, int tid)
{
#pragma unroll
    for (int h = 0; h < 2; h++) {
        int c = tid + h * 256;
        int row = c >> 2, seg = c & 3;
        uint32_t d = st + row * ROWB + seg * 16;
        int go = seg * 8;
        cpa16(d + OFF_AH, Ah + row * sA + go);
        cpa16(d + OFF_AL, Al + row * sA + go);
        cpa16(d + OFF_BH, Bh + row * sB + go);
        cpa16(d + OFF_BL, Bl + row * sB + go);
    }
}

// 3-term split-compensated bf16 MMA over one 32-wide K stage.
__device__ __forceinline__ void compute_stage(uint32_t st, int warp_m, int warp_n,
                                              int lane, float acc[2][8][4])
{
    const int rowsel = lane & 15;
    const uint32_t halfsel = (lane >> 4) * 16;
#pragma unroll
    for (int k16 = 0; k16 < 2; k16++) {
        const uint32_t off = k16 * 32 + halfsel;
        uint32_t ah[2][4], al[2][4], bh[8][2], bl[8][2];
#pragma unroll
        for (int mf = 0; mf < 2; mf++) {
            uint32_t base = st + (warp_m + mf * 16 + rowsel) * ROWB + off;
            ldx4(ah[mf], base + OFF_AH);
            ldx4(al[mf], base + OFF_AL);
        }
#pragma unroll
        for (int np = 0; np < 4; np++) {
            uint32_t base = st + (warp_n + np * 16 + rowsel) * ROWB + off;
            uint32_t r[4];
            ldx4(r, base + OFF_BH);
            bh[2*np][0] = r[0]; bh[2*np][1] = r[2];
            bh[2*np+1][0] = r[1]; bh[2*np+1][1] = r[3];
            ldx4(r, base + OFF_BL);
            bl[2*np][0] = r[0]; bl[2*np][1] = r[2];
            bl[2*np+1][0] = r[1]; bl[2*np+1][1] = r[3];
        }
#pragma unroll
        for (int mf = 0; mf < 2; mf++)
#pragma unroll
            for (int nf = 0; nf < 8; nf++) {
                mma16816(acc[mf][nf], ah[mf], bh[nf]);
                mma16816(acc[mf][nf], ah[mf], bl[nf]);
                mma16816(acc[mf][nf], al[mf], bh[nf]);
            }
    }
}

#define GEMM_PROLOGUE()                                                        \
    extern __shared__ char smem[];                                             \
    const uint32_t sb = smem_to_u32(smem);                                     \
    const int tid = threadIdx.x, lane = tid & 31, wid = tid >> 5;              \
    const int warp_m = (wid >> 1) * 32, warp_n = (wid & 1) * 64;               \
    float acc[2][8][4];                                                        \
    _Pragma("unroll") for (int a_ = 0; a_ < 2; a_++)                           \
    _Pragma("unroll") for (int b_ = 0; b_ < 8; b_++)                           \
    _Pragma("unroll") for (int c_ = 0; c_ < 4; c_++) acc[a_][b_][c_] = 0.f;

// Double-buffered 8-stage (K=256) mainloop over fixed-stride operands.
#define GEMM_K256_LOOP(Ah, Al, Bh, Bl)                                         \
    load_stage(sb, Ah, Al, Bh, Bl, NI, NI, tid);                               \
    CP_COMMIT();                                                               \
    _Pragma("unroll 1") for (int kc = 0; kc < 8; kc++) {                       \
        if (kc < 7) {                                                          \
            const int ko = (kc + 1) * 32;                                      \
            load_stage(sb + ((kc + 1) & 1) * STAGE, (Ah) + ko, (Al) + ko,      \
                       (Bh) + ko, (Bl) + ko, NI, NI, tid);                     \
            CP_COMMIT();                                                       \
            asm volatile("cp.async.wait_group 1;");                            \
        } else {                                                               \
            asm volatile("cp.async.wait_group 0;");                            \
        }                                                                      \
        __syncthreads();                                                       \
        compute_stage(sb + (kc & 1) * STAGE, warp_m, warp_n, lane, acc);       \
        __syncthreads();                                                       \
    }

// ---------------------------------------------------------------------------
// Prep: bf16 hi/lo splits of inputs
// ---------------------------------------------------------------------------
__global__ void k_split_X(const float* __restrict__ x) {
    int i = blockIdx.x * blockDim.x + threadIdx.x;
    if (i >= ROWS * NI) return;
    float v = x[i];
    __nv_bfloat16 h = __float2bfloat16(v);
    g_Xhi[i] = h;
    g_Xlo[i] = __float2bfloat16(v - __bfloat162float(h));
}

__global__ void k_split_W(const float* __restrict__ W, const float* __restrict__ W0) {
    int i = blockIdx.x * blockDim.x + threadIdx.x;
    if (i < 1024 * NI) {
        float v = W[i];
        __nv_bfloat16 h = __float2bfloat16(v);
        g_Whi[i] = h;
        g_Wlo[i] = __float2bfloat16(v - __bfloat162float(h));
    } else if (i < 1024 * NI + NI * NI) {
        int j = i - 1024 * NI;
        float v = W0[j];
        __nv_bfloat16 h = __float2bfloat16(v);
        g_W0hi[j] = h;
        g_W0lo[j] = __float2bfloat16(v - __bfloat162float(h));
    }
}

// ---------------------------------------------------------------------------
// k_wu_mma: wu[:, 0:1024] = X @ slow_W[0:1024]^T + b   (tensor, 3-term)
// grid (8 ntile, 32 mt). Epilogue routes per region:
//   ntile 0-1 -> A1 (fp32 g_A1), 2-3 -> A2 (split to g_K), 4-5 -> S1, 6-7 -> S2.
// ---------------------------------------------------------------------------
__global__ void __launch_bounds__(256, 1) k_wu_mma(const float* __restrict__ bias) {
    GEMM_PROLOGUE();
    const int mt = blockIdx.y, ntile = blockIdx.x;
    const int m0 = mt * 128, n0 = ntile * 128;
    const int region = ntile >> 1;

    const __nv_bfloat16* Ah = g_Xhi + m0 * NI;
    const __nv_bfloat16* Al = g_Xlo + m0 * NI;
    const __nv_bfloat16* Bh = g_Whi + n0 * NI;
    const __nv_bfloat16* Bl = g_Wlo + n0 * NI;
    GEMM_K256_LOOP(Ah, Al, Bh, Bl);

    const int g = lane >> 2, t2 = (lane & 3) * 2;
#pragma unroll
    for (int mf = 0; mf < 2; mf++) {
        const int q0 = m0 + warp_m + mf * 16 + g;
#pragma unroll
        for (int nf = 0; nf < 8; nf++) {
            const int col = n0 + warp_n + nf * 8 + t2;
            const float b0 = bias[col], b1 = bias[col + 1];
            const float* c = acc[mf][nf];
            const float v0 = c[0] + b0, v1 = c[1] + b1;
            const float w0 = c[2] + b0, w1 = c[3] + b1;
            const int cc = col & 255;
            if (region == 0) {
                *(float2*)(g_A1 + q0 * 256 + cc)       = make_float2(v0, v1);
                *(float2*)(g_A1 + (q0 + 8) * 256 + cc) = make_float2(w0, w1);
            } else if (region == 2) {
                *(float2*)(g_S1 + q0 * 256 + cc)       = make_float2(v0, v1);
                *(float2*)(g_S1 + (q0 + 8) * 256 + cc) = make_float2(w0, w1);
            } else {
                const int kr = (region == 1 ? q0 : 4096 + q0);
                __nv_bfloat16 h0 = __float2bfloat16(v0), h1 = __float2bfloat16(v1);
                *(__nv_bfloat162*)(g_Khi + kr * 256 + cc) = __nv_bfloat162(h0, h1);
                *(__nv_bfloat162*)(g_Klo + kr * 256 + cc) = __nv_bfloat162(
                    __float2bfloat16(v0 - __bfloat162float(h0)),
                    __float2bfloat16(v1 - __bfloat162float(h1)));
                __nv_bfloat16 k0 = __float2bfloat16(w0), k1 = __float2bfloat16(w1);
                *(__nv_bfloat162*)(g_Khi + (kr + 8) * 256 + cc) = __nv_bfloat162(k0, k1);
                *(__nv_bfloat162*)(g_Klo + (kr + 8) * 256 + cc) = __nv_bfloat162(
                    __float2bfloat16(w0 - __bfloat162float(k0)),
                    __float2bfloat16(w1 - __bfloat162float(k1)));
            }
        }
    }
}

// ---------------------------------------------------------------------------
// k_gates: wu[:, 1024] & wu[:, 1025] -> sigmoid gates (fp32 exact, warp/row)
// ---------------------------------------------------------------------------
__global__ void k_gates(const float* __restrict__ x, const float* __restrict__ W,
                        const float* __restrict__ b) {
    const int q = blockIdx.x * 8 + (threadIdx.x >> 5);
    const int lane = threadIdx.x & 31;
    const float4* xr = (const float4*)(x + q * 256);
    const float4* w1 = (const float4*)(W + 1024 * 256);
    const float4* w2 = (const float4*)(W + 1025 * 256);
    float s1 = 0.f, s2 = 0.f;
#pragma unroll
    for (int i = 0; i < 2; i++) {
        const int idx = lane + i * 32;
        float4 xv = xr[idx], wa = w1[idx], wb = w2[idx];
        s1 += xv.x * wa.x + xv.y * wa.y + xv.z * wa.z + xv.w * wa.w;
        s2 += xv.x * wb.x + xv.y * wb.y + xv.z * wb.z + xv.w * wb.w;
    }
#pragma unroll
    for (int off = 16; off; off >>= 1) {
        s1 += __shfl_xor_sync(0xFFFFFFFFu, s1, off);
        s2 += __shfl_xor_sync(0xFFFFFFFFu, s2, off);
    }
    if (lane == 0) {
        g_sa[q] = 1.f / (1.f + expf(-(s1 + b[1024])));
        g_ss[q] = 1.f / (1.f + expf(-(s2 + b[1025])));
    }
}

// ---------------------------------------------------------------------------
// k_base_mma: out = X @ W0^T   (tensor, 3-term). grid (2 ot, 32 mt).
// ---------------------------------------------------------------------------
__global__ void __launch_bounds__(256, 1) k_base_mma(float* __restrict__ out) {
    GEMM_PROLOGUE();
    const int mt = blockIdx.y, ot = blockIdx.x;
    const int m0 = mt * 128, o0 = ot * 128;

    const __nv_bfloat16* Ah = g_Xhi + m0 * NI;
    const __nv_bfloat16* Al = g_Xlo + m0 * NI;
    const __nv_bfloat16* Bh = g_W0hi + o0 * NI;
    const __nv_bfloat16* Bl = g_W0lo + o0 * NI;
    GEMM_K256_LOOP(Ah, Al, Bh, Bl);

    const int g = lane >> 2, t2 = (lane & 3) * 2;
#pragma unroll
    for (int mf = 0; mf < 2; mf++) {
        const int q = m0 + warp_m + mf * 16 + g;
#pragma unroll
        for (int nf = 0; nf < 8; nf++) {
            const int o = o0 + warp_n + nf * 8 + t2;
            const float* c = acc[mf][nf];
            *(float2*)(out + q * 256 + o)       = make_float2(c[0], c[1]);
            *(float2*)(out + (q + 8) * 256 + o) = make_float2(c[2], c[3]);
        }
    }
}

// ---------------------------------------------------------------------------
// k_trans_V: g_A1/g_S1 (fp32) -> transposed split bf16 VT
// ---------------------------------------------------------------------------
__global__ void k_trans_V() {
    __shared__ float t[32][33];
    const int rz = blockIdx.z;
    const float* src = rz ? g_S1 : g_A1;
    const int k0 = blockIdx.x * 32, o0 = blockIdx.y * 32;
    const int tx = threadIdx.x, ty = threadIdx.y;   // 32 x 8
#pragma unroll
    for (int i = 0; i < 32; i += 8)
        t[ty + i][tx] = src[(k0 + ty + i) * 256 + o0 + tx];
    __syncthreads();
#pragma unroll
    for (int i = 0; i < 32; i += 8) {
        float v = t[tx][ty + i];
        __nv_bfloat16 h = __float2bfloat16(v);
        int dst = (o0 + ty + i) * KCAT + rz * ROWS + k0 + tx;
        g_VThi[dst] = h;
        g_VTlo[dst] = __float2bfloat16(v - __bfloat162float(h));
    }
}

// ---------------------------------------------------------------------------
// GEMM1: P[q, kcat] = mask * gate * (X @ [A2;S2]^T)
// grid 1056: 2 regions x lower-triangular tiles (nt <= mt) of 128x128
// ---------------------------------------------------------------------------
__global__ void __launch_bounds__(256, 1) k_gemm1() {
    GEMM_PROLOGUE();
    int i = blockIdx.x, rg = 0;
    if (i >= 528) { rg = 1; i -= 528; }
    int mt = 0;
    while ((mt + 1) * (mt + 2) / 2 <= i) mt++;
    const int nt = i - mt * (mt + 1) / 2;
    const int m0 = mt * 128;
    const int keybase = nt * 128;

    const __nv_bfloat16* Ah = g_Xhi + m0 * NI;
    const __nv_bfloat16* Al = g_Xlo + m0 * NI;
    const __nv_bfloat16* Bh = g_Khi + (rg * ROWS + keybase) * NI;
    const __nv_bfloat16* Bl = g_Klo + (rg * ROWS + keybase) * NI;
    GEMM_K256_LOOP(Ah, Al, Bh, Bl);

    // Epilogue: scale by causal mask * gate, split to bf16 hi/lo, store.
    const int g = lane >> 2, t2 = (lane & 3) * 2;
#pragma unroll
    for (int mf = 0; mf < 2; mf++) {
        const int q0 = m0 + warp_m + mf * 16 + g;  // second row = q0 + 8, same b
        const int s0 = q0 >> 3, b = q0 & 7;
#pragma unroll
        for (int nf = 0; nf < 8; nf++) {
            const int col = keybase + warp_n + nf * 8 + t2;   // even, region-local
            const int t = col >> 3;
            const float gv = rg ? -g_ss[t * 8 + b] : g_sa[t * 8 + b];
            const float sc0 = (t <= s0) ? gv : 0.f;
            const float sc1 = (t <= s0 + 1) ? gv : 0.f;
            const float* c = acc[mf][nf];
            const size_t p0 = (size_t)q0 * KCAT + rg * ROWS + col;
            const size_t p1 = p0 + (size_t)8 * KCAT;

            float v0 = c[0] * sc0, v1 = c[1] * sc0;
            __nv_bfloat16 h0 = __float2bfloat16(v0), h1 = __float2bfloat16(v1);
            *(__nv_bfloat162*)(g_Phi + p0) = __nv_bfloat162(h0, h1);
            *(__nv_bfloat162*)(g_Plo + p0) = __nv_bfloat162(
                __float2bfloat16(v0 - __bfloat162float(h0)),
                __float2bfloat16(v1 - __bfloat162float(h1)));

            float w0 = c[2] * sc1, w1 = c[3] * sc1;
            __nv_bfloat16 k0 = __float2bfloat16(w0), k1 = __float2bfloat16(w1);
            *(__nv_bfloat162*)(g_Phi + p1) = __nv_bfloat162(k0, k1);
            *(__nv_bfloat162*)(g_Plo + p1) = __nv_bfloat162(
                __float2bfloat16(w0 - __bfloat162float(k0)),
                __float2bfloat16(w1 - __bfloat162float(k1)));
        }
    }
}

// ---------------------------------------------------------------------------
// GEMM2: out[q, o] += P[q, :] @ [A1;S1][:, o]   (split-K + f32 atomics)
// Logical k in [0, 256*(mt+1)) maps to phys [0, half) U [4096, 4096+half).
// ---------------------------------------------------------------------------
__global__ void __launch_bounds__(256, 1) k_gemm2(float* __restrict__ out) {
    const int mt = blockIdx.x, ot = blockIdx.y, kc = blockIdx.z;
    const int nch = (mt + 4) >> 2;
    if (kc >= nch) return;
    const int klive = 256 * (mt + 1);
    const int kstart = kc * 1024;
    const int kend = (kstart + 1024 < klive) ? kstart + 1024 : klive;
    const int half = 128 * (mt + 1);
    const int m0 = mt * 128, o0 = ot * 128;
    const int nsteps = (kend - kstart) >> 5;

    GEMM_PROLOGUE();

    const __nv_bfloat16* Ah = g_Phi + (size_t)m0 * KCAT;
    const __nv_bfloat16* Al = g_Plo + (size_t)m0 * KCAT;
    const __nv_bfloat16* Bh = g_VThi + (size_t)o0 * KCAT;
    const __nv_bfloat16* Bl = g_VTlo + (size_t)o0 * KCAT;

    int pk0 = (kstart < half) ? kstart : kstart + ROWS - half;
    load_stage(sb, Ah + pk0, Al + pk0, Bh + pk0, Bl + pk0, KCAT, KCAT, tid);
    CP_COMMIT();
#pragma unroll 1
    for (int s = 0; s < nsteps; s++) {
        if (s < nsteps - 1) {
            const int lk = kstart + (s + 1) * 32;
            const int pk = (lk < half) ? lk : lk + ROWS - half;
            load_stage(sb + ((s + 1) & 1) * STAGE, Ah + pk, Al + pk, Bh + pk, Bl + pk,
                       KCAT, KCAT, tid);
            CP_COMMIT();
            asm volatile("cp.async.wait_group 1;");
        } else {
            asm volatile("cp.async.wait_group 0;");
        }
        __syncthreads();
        compute_stage(sb + (s & 1) * STAGE, warp_m, warp_n, lane, acc);
        __syncthreads();
    }

    const int g = lane >> 2, t2 = (lane & 3) * 2;
#pragma unroll
    for (int mf = 0; mf < 2; mf++) {
        const int q = m0 + warp_m + mf * 16 + g;
#pragma unroll
        for (int nf = 0; nf < 8; nf++) {
            const int o = o0 + warp_n + nf * 8 + t2;
            const float* c = acc[mf][nf];
            atomicAdd(out + q * 256 + o,           c[0]);
            atomicAdd(out + q * 256 + o + 1,       c[1]);
            atomicAdd(out + (q + 8) * 256 + o,     c[2]);
            atomicAdd(out + (q + 8) * 256 + o + 1, c[3]);
        }
    }
}

// ---------------------------------------------------------------------------
extern "C" void kernel_launch(void* const* d_in, const int* in_sizes, int n_in,
                              void* d_out, int out_size) {
    const float* x      = (const float*)d_in[0];   // (512,8,256)
    const float* slow_W = (const float*)d_in[1];   // (1026,256)
    const float* slow_b = (const float*)d_in[2];   // (1026,)
    const float* fw0    = (const float*)d_in[3];   // (256,256)
    float* out = (float*)d_out;                    // (512,8,256)

    // Unconditional every call (no static guards — harness contract).
    cudaFuncSetAttribute(k_wu_mma,   cudaFuncAttributeMaxDynamicSharedMemorySize, GEMM_SMEM);
    cudaFuncSetAttribute(k_base_mma, cudaFuncAttributeMaxDynamicSharedMemorySize, GEMM_SMEM);
    cudaFuncSetAttribute(k_gemm1,    cudaFuncAttributeMaxDynamicSharedMemorySize, GEMM_SMEM);
    cudaFuncSetAttribute(k_gemm2,    cudaFuncAttributeMaxDynamicSharedMemorySize, GEMM_SMEM);

    k_split_X<<<(ROWS * NI + 255) / 256, 256>>>(x);
    k_split_W<<<(1024 * NI + NI * NI + 255) / 256, 256>>>(slow_W, fw0);
    k_wu_mma <<<dim3(8, 32), 256, GEMM_SMEM>>>(slow_b);
    k_gates  <<<512, 256>>>(x, slow_W, slow_b);
    k_base_mma<<<dim3(2, 32), 256, GEMM_SMEM>>>(out);
    k_trans_V<<<dim3(128, 8, 2), dim3(32, 8)>>>();
    k_gemm1  <<<1056, 256, GEMM_SMEM>>>();
    k_gemm2  <<<dim3(32, 2, 8), 256, GEMM_SMEM>>>(out);
}

// round 7
// speedup vs baseline: 3.0798x; 1.0321x over previous
#include <cuda_runtime.h>
#include <cuda_bf16.h>
#include <math.h>
#include <stdint.h>

#define ROWS 4096          // S*B = 512*8
#define KCAT 8192          // concat keys: [A (4096) | S (4096)]
#define NI 256
#define SLOW_OUTS 1026

// ---------------------------------------------------------------------------
// Scratch (device globals)
// ---------------------------------------------------------------------------
__device__ __align__(16) float g_A1[ROWS * NI];
__device__ __align__(16) float g_S1[ROWS * NI];
__device__ float g_sa[ROWS];
__device__ float g_ss[ROWS];

__device__ __align__(16) __nv_bfloat16 g_Xhi[ROWS * NI];
__device__ __align__(16) __nv_bfloat16 g_Xlo[ROWS * NI];
__device__ __align__(16) __nv_bfloat16 g_Whi[1024 * NI];   // slow_W rows 0..1023
__device__ __align__(16) __nv_bfloat16 g_Wlo[1024 * NI];
__device__ __align__(16) __nv_bfloat16 g_W0hi[NI * NI];    // fast_W0
__device__ __align__(16) __nv_bfloat16 g_W0lo[NI * NI];
__device__ __align__(16) __nv_bfloat16 g_Khi[KCAT * NI];   // rows: [A2 ; S2]
__device__ __align__(16) __nv_bfloat16 g_Klo[KCAT * NI];
__device__ __align__(16) __nv_bfloat16 g_VThi[NI * KCAT];  // VT[o][kcat] = [A1;S1][k][o]
__device__ __align__(16) __nv_bfloat16 g_VTlo[NI * KCAT];
__device__ __align__(16) __nv_bfloat16 g_Phi[(size_t)ROWS * KCAT];  // 64 MB
__device__ __align__(16) __nv_bfloat16 g_Plo[(size_t)ROWS * KCAT];  // 64 MB

// ---------------------------------------------------------------------------
// Helpers
// ---------------------------------------------------------------------------
__device__ __forceinline__ uint32_t smem_to_u32(const void* p) {
    uint32_t a;
    asm("{ .reg .u64 t; cvta.to.shared.u64 t, %1; cvt.u32.u64 %0, t; }" : "=r"(a) : "l"(p));
    return a;
}

__device__ __forceinline__ void cpa16(uint32_t s, const __nv_bfloat16* g) {
    asm volatile("cp.async.cg.shared.global [%0], [%1], 16;"
        :: "r"(s), "l"(__cvta_generic_to_global((const void*)g)));
}
#define CP_COMMIT() asm volatile("cp.async.commit_group;")

__device__ __forceinline__ void ldx4(uint32_t* r, uint32_t addr) {
    asm volatile("ldmatrix.sync.aligned.m8n8.x4.shared.b16 {%0,%1,%2,%3}, [%4];"
        : "=r"(r[0]), "=r"(r[1]), "=r"(r[2]), "=r"(r[3]) : "r"(addr));
}

__device__ __forceinline__ void mma16816(float* c, const uint32_t* a, const uint32_t* b) {
    asm volatile(
        "mma.sync.aligned.m16n8k16.row.col.f32.bf16.bf16.f32 "
        "{%0,%1,%2,%3}, {%4,%5,%6,%7}, {%8,%9}, {%0,%1,%2,%3};"
        : "+f"(c[0]), "+f"(c[1]), "+f"(c[2]), "+f"(c[3])
        : "r"(a[0]), "r"(a[1]), "r"(a[2]), "r"(a[3]), "r"(b[0]), "r"(b[1]));
}

// Stage layout: 4 operand arrays (Ah, Al, Bh, Bl), each 128 rows x 32 bf16,
// rows padded to 40 bf16 (80 bytes) -> conflict-free ldmatrix.
// 3-stage ring: one __syncthreads per stage, prefetch depth 2.
#define ROWB    80
#define OFF_AH  0
#define OFF_AL  10240
#define OFF_BH  20480
#define OFF_BL  30720
#define STAGE   40960
#define GEMM_SMEM (3 * STAGE)

__device__ __forceinline__ void load_stage(uint32_t st,
    const __nv_bfloat16* Ah, const __nv_bfloat16* Al,
    const __nv_bfloat16* Bh, const __nv_bfloat16* Bl,
    int sA, int sB, int tid)
{
#pragma unroll
    for (int h = 0; h < 2; h++) {
        int c = tid + h * 256;
        int row = c >> 2, seg = c & 3;
        uint32_t d = st + row * ROWB + seg * 16;
        int go = seg * 8;
        cpa16(d + OFF_AH, Ah + row * sA + go);
        cpa16(d + OFF_AL, Al + row * sA + go);
        cpa16(d + OFF_BH, Bh + row * sB + go);
        cpa16(d + OFF_BL, Bl + row * sB + go);
    }
}

// 3-term split-compensated bf16 MMA over one 32-wide K stage.
__device__ __forceinline__ void compute_stage(uint32_t st, int warp_m, int warp_n,
                                              int lane, float acc[2][8][4])
{
    const int rowsel = lane & 15;
    const uint32_t halfsel = (lane >> 4) * 16;
#pragma unroll
    for (int k16 = 0; k16 < 2; k16++) {
        const uint32_t off = k16 * 32 + halfsel;
        uint32_t ah[2][4], al[2][4], bh[8][2], bl[8][2];
#pragma unroll
        for (int mf = 0; mf < 2; mf++) {
            uint32_t base = st + (warp_m + mf * 16 + rowsel) * ROWB + off;
            ldx4(ah[mf], base + OFF_AH);
            ldx4(al[mf], base + OFF_AL);
        }
#pragma unroll
        for (int np = 0; np < 4; np++) {
            uint32_t base = st + (warp_n + np * 16 + rowsel) * ROWB + off;
            uint32_t r[4];
            ldx4(r, base + OFF_BH);
            bh[2*np][0] = r[0]; bh[2*np][1] = r[2];
            bh[2*np+1][0] = r[1]; bh[2*np+1][1] = r[3];
            ldx4(r, base + OFF_BL);
            bl[2*np][0] = r[0]; bl[2*np][1] = r[2];
            bl[2*np+1][0] = r[1]; bl[2*np+1][1] = r[3];
        }
#pragma unroll
        for (int mf = 0; mf < 2; mf++)
#pragma unroll
            for (int nf = 0; nf < 8; nf++) {
                mma16816(acc[mf][nf], ah[mf], bh[nf]);
                mma16816(acc[mf][nf], ah[mf], bl[nf]);
                mma16816(acc[mf][nf], al[mf], bh[nf]);
            }
    }
}

#define GEMM_PROLOGUE()                                                        \
    extern __shared__ char smem[];                                             \
    const uint32_t sb = smem_to_u32(smem);                                     \
    const int tid = threadIdx.x, lane = tid & 31, wid = tid >> 5;              \
    const int warp_m = (wid >> 1) * 32, warp_n = (wid & 1) * 64;               \
    float acc[2][8][4];                                                        \
    _Pragma("unroll") for (int a_ = 0; a_ < 2; a_++)                           \
    _Pragma("unroll") for (int b_ = 0; b_ < 8; b_++)                           \
    _Pragma("unroll") for (int c_ = 0; c_ < 4; c_++) acc[a_][b_][c_] = 0.f;

// 3-stage ring over K=256 (8 stages), fixed stride NI, ONE sync per stage.
// Safety: load(kc+2) writes buf (kc+2)%3 == buf((kc-1)%3), whose compute
// (iter kc-1) is retired by the sync at top of iter kc.
#define GEMM_K256_RING(Ah, Al, Bh, Bl)                                         \
    load_stage(sb, (Ah), (Al), (Bh), (Bl), NI, NI, tid); CP_COMMIT();          \
    load_stage(sb + STAGE, (Ah) + 32, (Al) + 32, (Bh) + 32, (Bl) + 32,         \
               NI, NI, tid);                                                   \
    CP_COMMIT();                                                               \
    _Pragma("unroll 1") for (int kc = 0; kc < 8; kc++) {                       \
        asm volatile("cp.async.wait_group 1;");                                \
        __syncthreads();                                                       \
        if (kc + 2 < 8) {                                                      \
            const int ko = (kc + 2) * 32;                                      \
            load_stage(sb + ((kc + 2) % 3) * STAGE, (Ah) + ko, (Al) + ko,      \
                       (Bh) + ko, (Bl) + ko, NI, NI, tid);                     \
        }                                                                      \
        CP_COMMIT();                                                           \
        compute_stage(sb + (kc % 3) * STAGE, warp_m, warp_n, lane, acc);       \
    }

// ---------------------------------------------------------------------------
// k_prep: one launch does X split, W split, W0 split, and sigmoid gates.
// grid 5888 x 256.
// ---------------------------------------------------------------------------
__global__ void k_prep(const float* __restrict__ x, const float* __restrict__ W,
                       const float* __restrict__ W0, const float* __restrict__ b) {
    const int blk = blockIdx.x;
    const int tid = threadIdx.x;
    if (blk < 4096) {                       // split X: ROWS*NI elements
        const int i = blk * 256 + tid;
        float v = x[i];
        __nv_bfloat16 h = __float2bfloat16(v);
        g_Xhi[i] = h;
        g_Xlo[i] = __float2bfloat16(v - __bfloat162float(h));
    } else if (blk < 5120) {                // split slow_W rows 0..1023
        const int i = (blk - 4096) * 256 + tid;
        float v = W[i];
        __nv_bfloat16 h = __float2bfloat16(v);
        g_Whi[i] = h;
        g_Wlo[i] = __float2bfloat16(v - __bfloat162float(h));
    } else if (blk < 5376) {                // split fast_W0
        const int i = (blk - 5120) * 256 + tid;
        float v = W0[i];
        __nv_bfloat16 h = __float2bfloat16(v);
        g_W0hi[i] = h;
        g_W0lo[i] = __float2bfloat16(v - __bfloat162float(h));
    } else {                                // gates: 8 rows per block, warp each
        const int q = (blk - 5376) * 8 + (tid >> 5);
        const int lane = tid & 31;
        const float4* xr = (const float4*)(x + q * 256);
        const float4* w1 = (const float4*)(W + 1024 * 256);
        const float4* w2 = (const float4*)(W + 1025 * 256);
        float s1 = 0.f, s2 = 0.f;
#pragma unroll
        for (int i = 0; i < 2; i++) {
            const int idx = lane + i * 32;
            float4 xv = xr[idx], wa = w1[idx], wb = w2[idx];
            s1 += xv.x * wa.x + xv.y * wa.y + xv.z * wa.z + xv.w * wa.w;
            s2 += xv.x * wb.x + xv.y * wb.y + xv.z * wb.z + xv.w * wb.w;
        }
#pragma unroll
        for (int off = 16; off; off >>= 1) {
            s1 += __shfl_xor_sync(0xFFFFFFFFu, s1, off);
            s2 += __shfl_xor_sync(0xFFFFFFFFu, s2, off);
        }
        if (lane == 0) {
            g_sa[q] = 1.f / (1.f + expf(-(s1 + b[1024])));
            g_ss[q] = 1.f / (1.f + expf(-(s2 + b[1025])));
        }
    }
}

// ---------------------------------------------------------------------------
// k_wu_mma: wu[:, 0:1024] = X @ slow_W[0:1024]^T + b   (tensor, 3-term)
// grid (8 ntile, 32 mt). Epilogue routes per region:
//   ntile 0-1 -> A1 (fp32), 2-3 -> A2 (split bf16 -> g_K), 4-5 -> S1, 6-7 -> S2.
// ---------------------------------------------------------------------------
__global__ void __launch_bounds__(256, 1) k_wu_mma(const float* __restrict__ bias) {
    GEMM_PROLOGUE();
    const int mt = blockIdx.y, ntile = blockIdx.x;
    const int m0 = mt * 128, n0 = ntile * 128;
    const int region = ntile >> 1;

    const __nv_bfloat16* Ah = g_Xhi + m0 * NI;
    const __nv_bfloat16* Al = g_Xlo + m0 * NI;
    const __nv_bfloat16* Bh = g_Whi + n0 * NI;
    const __nv_bfloat16* Bl = g_Wlo + n0 * NI;
    GEMM_K256_RING(Ah, Al, Bh, Bl);

    const int g = lane >> 2, t2 = (lane & 3) * 2;
#pragma unroll
    for (int mf = 0; mf < 2; mf++) {
        const int q0 = m0 + warp_m + mf * 16 + g;
#pragma unroll
        for (int nf = 0; nf < 8; nf++) {
            const int col = n0 + warp_n + nf * 8 + t2;
            const float b0 = bias[col], b1 = bias[col + 1];
            const float* c = acc[mf][nf];
            const float v0 = c[0] + b0, v1 = c[1] + b1;
            const float w0 = c[2] + b0, w1 = c[3] + b1;
            const int cc = col & 255;
            if (region == 0) {
                *(float2*)(g_A1 + q0 * 256 + cc)       = make_float2(v0, v1);
                *(float2*)(g_A1 + (q0 + 8) * 256 + cc) = make_float2(w0, w1);
            } else if (region == 2) {
                *(float2*)(g_S1 + q0 * 256 + cc)       = make_float2(v0, v1);
                *(float2*)(g_S1 + (q0 + 8) * 256 + cc) = make_float2(w0, w1);
            } else {
                const int kr = (region == 1 ? q0 : 4096 + q0);
                __nv_bfloat16 h0 = __float2bfloat16(v0), h1 = __float2bfloat16(v1);
                *(__nv_bfloat162*)(g_Khi + kr * 256 + cc) = __nv_bfloat162(h0, h1);
                *(__nv_bfloat162*)(g_Klo + kr * 256 + cc) = __nv_bfloat162(
                    __float2bfloat16(v0 - __bfloat162float(h0)),
                    __float2bfloat16(v1 - __bfloat162float(h1)));
                __nv_bfloat16 k0 = __float2bfloat16(w0), k1 = __float2bfloat16(w1);
                *(__nv_bfloat162*)(g_Khi + (kr + 8) * 256 + cc) = __nv_bfloat162(k0, k1);
                *(__nv_bfloat162*)(g_Klo + (kr + 8) * 256 + cc) = __nv_bfloat162(
                    __float2bfloat16(w0 - __bfloat162float(k0)),
                    __float2bfloat16(w1 - __bfloat162float(k1)));
            }
        }
    }
}

// ---------------------------------------------------------------------------
// k_base_mma: out = X @ W0^T   (tensor, 3-term). grid (2 ot, 32 mt).
// ---------------------------------------------------------------------------
__global__ void __launch_bounds__(256, 1) k_base_mma(float* __restrict__ out) {
    GEMM_PROLOGUE();
    const int mt = blockIdx.y, ot = blockIdx.x;
    const int m0 = mt * 128, o0 = ot * 128;

    const __nv_bfloat16* Ah = g_Xhi + m0 * NI;
    const __nv_bfloat16* Al = g_Xlo + m0 * NI;
    const __nv_bfloat16* Bh = g_W0hi + o0 * NI;
    const __nv_bfloat16* Bl = g_W0lo + o0 * NI;
    GEMM_K256_RING(Ah, Al, Bh, Bl);

    const int g = lane >> 2, t2 = (lane & 3) * 2;
#pragma unroll
    for (int mf = 0; mf < 2; mf++) {
        const int q = m0 + warp_m + mf * 16 + g;
#pragma unroll
        for (int nf = 0; nf < 8; nf++) {
            const int o = o0 + warp_n + nf * 8 + t2;
            const float* c = acc[mf][nf];
            *(float2*)(out + q * 256 + o)       = make_float2(c[0], c[1]);
            *(float2*)(out + (q + 8) * 256 + o) = make_float2(c[2], c[3]);
        }
    }
}

// ---------------------------------------------------------------------------
// k_trans_V: g_A1/g_S1 (fp32) -> transposed split bf16 VT
// ---------------------------------------------------------------------------
__global__ void k_trans_V() {
    __shared__ float t[32][33];
    const int rz = blockIdx.z;
    const float* src = rz ? g_S1 : g_A1;
    const int k0 = blockIdx.x * 32, o0 = blockIdx.y * 32;
    const int tx = threadIdx.x, ty = threadIdx.y;   // 32 x 8
#pragma unroll
    for (int i = 0; i < 32; i += 8)
        t[ty + i][tx] = src[(k0 + ty + i) * 256 + o0 + tx];
    __syncthreads();
#pragma unroll
    for (int i = 0; i < 32; i += 8) {
        float v = t[tx][ty + i];
        __nv_bfloat16 h = __float2bfloat16(v);
        int dst = (o0 + ty + i) * KCAT + rz * ROWS + k0 + tx;
        g_VThi[dst] = h;
        g_VTlo[dst] = __float2bfloat16(v - __bfloat162float(h));
    }
}

// ---------------------------------------------------------------------------
// GEMM1: P[q, kcat] = mask * gate * (X @ [A2;S2]^T)
// grid 1056: 2 regions x lower-triangular tiles (nt <= mt) of 128x128
// ---------------------------------------------------------------------------
__global__ void __launch_bounds__(256, 1) k_gemm1() {
    GEMM_PROLOGUE();
    int i = blockIdx.x, rg = 0;
    if (i >= 528) { rg = 1; i -= 528; }
    int mt = 0;
    while ((mt + 1) * (mt + 2) / 2 <= i) mt++;
    const int nt = i - mt * (mt + 1) / 2;
    const int m0 = mt * 128;
    const int keybase = nt * 128;

    const __nv_bfloat16* Ah = g_Xhi + m0 * NI;
    const __nv_bfloat16* Al = g_Xlo + m0 * NI;
    const __nv_bfloat16* Bh = g_Khi + (rg * ROWS + keybase) * NI;
    const __nv_bfloat16* Bl = g_Klo + (rg * ROWS + keybase) * NI;
    GEMM_K256_RING(Ah, Al, Bh, Bl);

    // Epilogue: scale by causal mask * gate, split to bf16 hi/lo, store.
    const int g = lane >> 2, t2 = (lane & 3) * 2;
#pragma unroll
    for (int mf = 0; mf < 2; mf++) {
        const int q0 = m0 + warp_m + mf * 16 + g;  // second row = q0 + 8, same b
        const int s0 = q0 >> 3, b = q0 & 7;
#pragma unroll
        for (int nf = 0; nf < 8; nf++) {
            const int col = keybase + warp_n + nf * 8 + t2;   // even, region-local
            const int t = col >> 3;
            const float gv = rg ? -g_ss[t * 8 + b] : g_sa[t * 8 + b];
            const float sc0 = (t <= s0) ? gv : 0.f;
            const float sc1 = (t <= s0 + 1) ? gv : 0.f;
            const float* c = acc[mf][nf];
            const size_t p0 = (size_t)q0 * KCAT + rg * ROWS + col;
            const size_t p1 = p0 + (size_t)8 * KCAT;

            float v0 = c[0] * sc0, v1 = c[1] * sc0;
            __nv_bfloat16 h0 = __float2bfloat16(v0), h1 = __float2bfloat16(v1);
            *(__nv_bfloat162*)(g_Phi + p0) = __nv_bfloat162(h0, h1);
            *(__nv_bfloat162*)(g_Plo + p0) = __nv_bfloat162(
                __float2bfloat16(v0 - __bfloat162float(h0)),
                __float2bfloat16(v1 - __bfloat162float(h1)));

            float w0 = c[2] * sc1, w1 = c[3] * sc1;
            __nv_bfloat16 k0 = __float2bfloat16(w0), k1 = __float2bfloat16(w1);
            *(__nv_bfloat162*)(g_Phi + p1) = __nv_bfloat162(k0, k1);
            *(__nv_bfloat162*)(g_Plo + p1) = __nv_bfloat162(
                __float2bfloat16(w0 - __bfloat162float(k0)),
                __float2bfloat16(w1 - __bfloat162float(k1)));
        }
    }
}

// ---------------------------------------------------------------------------
// GEMM2: out[q, o] += P[q, :] @ [A1;S1][:, o]   (split-K + f32 atomics)
// Logical k in [0, 256*(mt+1)) maps to phys [0, half) U [4096, 4096+half).
// ---------------------------------------------------------------------------
__global__ void __launch_bounds__(256, 1) k_gemm2(float* __restrict__ out) {
    const int mt = blockIdx.x, ot = blockIdx.y, kc = blockIdx.z;
    const int nch = (mt + 4) >> 2;
    if (kc >= nch) return;
    const int klive = 256 * (mt + 1);
    const int kstart = kc * 1024;
    const int kend = (kstart + 1024 < klive) ? kstart + 1024 : klive;
    const int half = 128 * (mt + 1);
    const int m0 = mt * 128, o0 = ot * 128;
    const int nsteps = (kend - kstart) >> 5;

    GEMM_PROLOGUE();

    const __nv_bfloat16* Ah = g_Phi + (size_t)m0 * KCAT;
    const __nv_bfloat16* Al = g_Plo + (size_t)m0 * KCAT;
    const __nv_bfloat16* Bh = g_VThi + (size_t)o0 * KCAT;
    const __nv_bfloat16* Bl = g_VTlo + (size_t)o0 * KCAT;

    {
        int pk = (kstart < half) ? kstart : kstart + ROWS - half;
        load_stage(sb, Ah + pk, Al + pk, Bh + pk, Bl + pk, KCAT, KCAT, tid);
        CP_COMMIT();
        if (nsteps > 1) {
            const int lk = kstart + 32;
            pk = (lk < half) ? lk : lk + ROWS - half;
            load_stage(sb + STAGE, Ah + pk, Al + pk, Bh + pk, Bl + pk, KCAT, KCAT, tid);
        }
        CP_COMMIT();
    }
#pragma unroll 1
    for (int s = 0; s < nsteps; s++) {
        asm volatile("cp.async.wait_group 1;");
        __syncthreads();
        if (s + 2 < nsteps) {
            const int lk = kstart + (s + 2) * 32;
            const int pk = (lk < half) ? lk : lk + ROWS - half;
            load_stage(sb + ((s + 2) % 3) * STAGE, Ah + pk, Al + pk, Bh + pk, Bl + pk,
                       KCAT, KCAT, tid);
        }
        CP_COMMIT();
        compute_stage(sb + (s % 3) * STAGE, warp_m, warp_n, lane, acc);
    }

    const int g = lane >> 2, t2 = (lane & 3) * 2;
#pragma unroll
    for (int mf = 0; mf < 2; mf++) {
        const int q = m0 + warp_m + mf * 16 + g;
#pragma unroll
        for (int nf = 0; nf < 8; nf++) {
            const int o = o0 + warp_n + nf * 8 + t2;
            const float* c = acc[mf][nf];
            atomicAdd(out + q * 256 + o,           c[0]);
            atomicAdd(out + q * 256 + o + 1,       c[1]);
            atomicAdd(out + (q + 8) * 256 + o,     c[2]);
            atomicAdd(out + (q + 8) * 256 + o + 1, c[3]);
        }
    }
}

// ---------------------------------------------------------------------------
extern "C" void kernel_launch(void* const* d_in, const int* in_sizes, int n_in,
                              void* d_out, int out_size) {
    const float* x      = (const float*)d_in[0];   // (512,8,256)
    const float* slow_W = (const float*)d_in[1];   // (1026,256)
    const float* slow_b = (const float*)d_in[2];   // (1026,)
    const float* fw0    = (const float*)d_in[3];   // (256,256)
    float* out = (float*)d_out;                    // (512,8,256)

    // Unconditional every call (no static guards — harness contract).
    cudaFuncSetAttribute(k_wu_mma,   cudaFuncAttributeMaxDynamicSharedMemorySize, GEMM_SMEM);
    cudaFuncSetAttribute(k_base_mma, cudaFuncAttributeMaxDynamicSharedMemorySize, GEMM_SMEM);
    cudaFuncSetAttribute(k_gemm1,    cudaFuncAttributeMaxDynamicSharedMemorySize, GEMM_SMEM);
    cudaFuncSetAttribute(k_gemm2,    cudaFuncAttributeMaxDynamicSharedMemorySize, GEMM_SMEM);

    // 6 launches; ncu (-s 5 -c 1) lands on k_gemm2.
    k_prep    <<<5888, 256>>>(x, slow_W, fw0, slow_b);
    k_wu_mma  <<<dim3(8, 32), 256, GEMM_SMEM>>>(slow_b);
    k_base_mma<<<dim3(2, 32), 256, GEMM_SMEM>>>(out);
    k_trans_V <<<dim3(128, 8, 2), dim3(32, 8)>>>();
    k_gemm1   <<<1056, 256, GEMM_SMEM>>>();
    k_gemm2   <<<dim3(32, 2, 8), 256, GEMM_SMEM>>>(out);
}

// round 8
// speedup vs baseline: 3.1815x; 1.0330x over previous
#include <cuda_runtime.h>
#include <cuda_bf16.h>
#include <math.h>
#include <stdint.h>

#define ROWS 4096          // S*B = 512*8
#define KCAT 8192          // concat keys: [A (4096) | S (4096)]
#define NI 256
#define SLOW_OUTS 1026

// ---------------------------------------------------------------------------
// Scratch (device globals)
// ---------------------------------------------------------------------------
__device__ __align__(16) float g_A1[ROWS * NI];
__device__ __align__(16) float g_S1[ROWS * NI];
__device__ float g_sa[ROWS];
__device__ float g_ss[ROWS];

__device__ __align__(16) __nv_bfloat16 g_Xhi[ROWS * NI];
__device__ __align__(16) __nv_bfloat16 g_Xlo[ROWS * NI];
__device__ __align__(16) __nv_bfloat16 g_Whi[1024 * NI];   // slow_W rows 0..1023
__device__ __align__(16) __nv_bfloat16 g_Wlo[1024 * NI];
__device__ __align__(16) __nv_bfloat16 g_W0hi[NI * NI];    // fast_W0
__device__ __align__(16) __nv_bfloat16 g_W0lo[NI * NI];
__device__ __align__(16) __nv_bfloat16 g_Khi[KCAT * NI];   // rows: [A2 ; S2]
__device__ __align__(16) __nv_bfloat16 g_Klo[KCAT * NI];
__device__ __align__(16) __nv_bfloat16 g_VThi[NI * KCAT];  // VT[o][kcat] = [A1;S1][k][o]
__device__ __align__(16) __nv_bfloat16 g_VTlo[NI * KCAT];
__device__ __align__(16) __nv_bfloat16 g_Phi[(size_t)ROWS * KCAT];  // 64 MB
__device__ __align__(16) __nv_bfloat16 g_Plo[(size_t)ROWS * KCAT];  // 64 MB

// ---------------------------------------------------------------------------
// Helpers
// ---------------------------------------------------------------------------
__device__ __forceinline__ uint32_t smem_to_u32(const void* p) {
    uint32_t a;
    asm("{ .reg .u64 t; cvta.to.shared.u64 t, %1; cvt.u32.u64 %0, t; }" : "=r"(a) : "l"(p));
    return a;
}

__device__ __forceinline__ void cpa16(uint32_t s, const __nv_bfloat16* g) {
    asm volatile("cp.async.cg.shared.global [%0], [%1], 16;"
        :: "r"(s), "l"(__cvta_generic_to_global((const void*)g)));
}
#define CP_COMMIT() asm volatile("cp.async.commit_group;")

__device__ __forceinline__ void ldx4(uint32_t* r, uint32_t addr) {
    asm volatile("ldmatrix.sync.aligned.m8n8.x4.shared.b16 {%0,%1,%2,%3}, [%4];"
        : "=r"(r[0]), "=r"(r[1]), "=r"(r[2]), "=r"(r[3]) : "r"(addr));
}

__device__ __forceinline__ void mma16816(float* c, const uint32_t* a, const uint32_t* b) {
    asm volatile(
        "mma.sync.aligned.m16n8k16.row.col.f32.bf16.bf16.f32 "
        "{%0,%1,%2,%3}, {%4,%5,%6,%7}, {%8,%9}, {%0,%1,%2,%3};"
        : "+f"(c[0]), "+f"(c[1]), "+f"(c[2]), "+f"(c[3])
        : "r"(a[0]), "r"(a[1]), "r"(a[2]), "r"(a[3]), "r"(b[0]), "r"(b[1]));
}

// Stage layout: 4 operand arrays (Ah, Al, Bh, Bl), each 128 rows x 32 bf16,
// rows padded to 40 bf16 (80 bytes) -> conflict-free ldmatrix.
// 3-stage ring: one __syncthreads per stage, prefetch depth 2.
#define ROWB    80
#define OFF_AH  0
#define OFF_AL  10240
#define OFF_BH  20480
#define OFF_BL  30720
#define STAGE   40960
#define GEMM_SMEM (3 * STAGE)

__device__ __forceinline__ void load_stage(uint32_t st,
    const __nv_bfloat16* Ah, const __nv_bfloat16* Al,
    const __nv_bfloat16* Bh, const __nv_bfloat16* Bl,
    int sA, int sB, int tid)
{
#pragma unroll
    for (int h = 0; h < 2; h++) {
        int c = tid + h * 256;
        int row = c >> 2, seg = c & 3;
        uint32_t d = st + row * ROWB + seg * 16;
        int go = seg * 8;
        cpa16(d + OFF_AH, Ah + row * sA + go);
        cpa16(d + OFF_AL, Al + row * sA + go);
        cpa16(d + OFF_BH, Bh + row * sB + go);
        cpa16(d + OFF_BL, Bl + row * sB + go);
    }
}

// 3-term split-compensated bf16 MMA over one 32-wide K stage.
__device__ __forceinline__ void compute_stage(uint32_t st, int warp_m, int warp_n,
                                              int lane, float acc[2][8][4])
{
    const int rowsel = lane & 15;
    const uint32_t halfsel = (lane >> 4) * 16;
#pragma unroll
    for (int k16 = 0; k16 < 2; k16++) {
        const uint32_t off = k16 * 32 + halfsel;
        uint32_t ah[2][4], al[2][4], bh[8][2], bl[8][2];
#pragma unroll
        for (int mf = 0; mf < 2; mf++) {
            uint32_t base = st + (warp_m + mf * 16 + rowsel) * ROWB + off;
            ldx4(ah[mf], base + OFF_AH);
            ldx4(al[mf], base + OFF_AL);
        }
#pragma unroll
        for (int np = 0; np < 4; np++) {
            uint32_t base = st + (warp_n + np * 16 + rowsel) * ROWB + off;
            uint32_t r[4];
            ldx4(r, base + OFF_BH);
            bh[2*np][0] = r[0]; bh[2*np][1] = r[2];
            bh[2*np+1][0] = r[1]; bh[2*np+1][1] = r[3];
            ldx4(r, base + OFF_BL);
            bl[2*np][0] = r[0]; bl[2*np][1] = r[2];
            bl[2*np+1][0] = r[1]; bl[2*np+1][1] = r[3];
        }
#pragma unroll
        for (int mf = 0; mf < 2; mf++)
#pragma unroll
            for (int nf = 0; nf < 8; nf++) {
                mma16816(acc[mf][nf], ah[mf], bh[nf]);
                mma16816(acc[mf][nf], ah[mf], bl[nf]);
                mma16816(acc[mf][nf], al[mf], bh[nf]);
            }
    }
}

#define GEMM_PROLOGUE()                                                        \
    extern __shared__ char smem[];                                             \
    const uint32_t sb = smem_to_u32(smem);                                     \
    const int tid = threadIdx.x, lane = tid & 31, wid = tid >> 5;              \
    const int warp_m = (wid >> 1) * 32, warp_n = (wid & 1) * 64;               \
    float acc[2][8][4];                                                        \
    _Pragma("unroll") for (int a_ = 0; a_ < 2; a_++)                           \
    _Pragma("unroll") for (int b_ = 0; b_ < 8; b_++)                           \
    _Pragma("unroll") for (int c_ = 0; c_ < 4; c_++) acc[a_][b_][c_] = 0.f;

// 3-stage ring over K=256 (8 stages), fixed stride NI, ONE sync per stage.
#define GEMM_K256_RING(Ah, Al, Bh, Bl)                                         \
    load_stage(sb, (Ah), (Al), (Bh), (Bl), NI, NI, tid); CP_COMMIT();          \
    load_stage(sb + STAGE, (Ah) + 32, (Al) + 32, (Bh) + 32, (Bl) + 32,         \
               NI, NI, tid);                                                   \
    CP_COMMIT();                                                               \
    _Pragma("unroll 1") for (int kc = 0; kc < 8; kc++) {                       \
        asm volatile("cp.async.wait_group 1;");                                \
        __syncthreads();                                                       \
        if (kc + 2 < 8) {                                                      \
            const int ko = (kc + 2) * 32;                                      \
            load_stage(sb + ((kc + 2) % 3) * STAGE, (Ah) + ko, (Al) + ko,      \
                       (Bh) + ko, (Bl) + ko, NI, NI, tid);                     \
        }                                                                      \
        CP_COMMIT();                                                           \
        compute_stage(sb + (kc % 3) * STAGE, warp_m, warp_n, lane, acc);       \
    }

// ---------------------------------------------------------------------------
// k_prep: X split, W split, W0 split, sigmoid gates.  grid 5888 x 256.
// ---------------------------------------------------------------------------
__global__ void k_prep(const float* __restrict__ x, const float* __restrict__ W,
                       const float* __restrict__ W0, const float* __restrict__ b) {
    const int blk = blockIdx.x;
    const int tid = threadIdx.x;
    if (blk < 4096) {                       // split X
        const int i = blk * 256 + tid;
        float v = x[i];
        __nv_bfloat16 h = __float2bfloat16(v);
        g_Xhi[i] = h;
        g_Xlo[i] = __float2bfloat16(v - __bfloat162float(h));
    } else if (blk < 5120) {                // split slow_W rows 0..1023
        const int i = (blk - 4096) * 256 + tid;
        float v = W[i];
        __nv_bfloat16 h = __float2bfloat16(v);
        g_Whi[i] = h;
        g_Wlo[i] = __float2bfloat16(v - __bfloat162float(h));
    } else if (blk < 5376) {                // split fast_W0
        const int i = (blk - 5120) * 256 + tid;
        float v = W0[i];
        __nv_bfloat16 h = __float2bfloat16(v);
        g_W0hi[i] = h;
        g_W0lo[i] = __float2bfloat16(v - __bfloat162float(h));
    } else {                                // gates
        const int q = (blk - 5376) * 8 + (tid >> 5);
        const int lane = tid & 31;
        const float4* xr = (const float4*)(x + q * 256);
        const float4* w1 = (const float4*)(W + 1024 * 256);
        const float4* w2 = (const float4*)(W + 1025 * 256);
        float s1 = 0.f, s2 = 0.f;
#pragma unroll
        for (int i = 0; i < 2; i++) {
            const int idx = lane + i * 32;
            float4 xv = xr[idx], wa = w1[idx], wb = w2[idx];
            s1 += xv.x * wa.x + xv.y * wa.y + xv.z * wa.z + xv.w * wa.w;
            s2 += xv.x * wb.x + xv.y * wb.y + xv.z * wb.z + xv.w * wb.w;
        }
#pragma unroll
        for (int off = 16; off; off >>= 1) {
            s1 += __shfl_xor_sync(0xFFFFFFFFu, s1, off);
            s2 += __shfl_xor_sync(0xFFFFFFFFu, s2, off);
        }
        if (lane == 0) {
            g_sa[q] = 1.f / (1.f + expf(-(s1 + b[1024])));
            g_ss[q] = 1.f / (1.f + expf(-(s2 + b[1025])));
        }
    }
}

// ---------------------------------------------------------------------------
// k_wu_mma: wu[:, 0:1024] = X @ slow_W[0:1024]^T + b   (tensor, 3-term)
// ---------------------------------------------------------------------------
__global__ void __launch_bounds__(256, 1) k_wu_mma(const float* __restrict__ bias) {
    GEMM_PROLOGUE();
    const int mt = blockIdx.y, ntile = blockIdx.x;
    const int m0 = mt * 128, n0 = ntile * 128;
    const int region = ntile >> 1;

    const __nv_bfloat16* Ah = g_Xhi + m0 * NI;
    const __nv_bfloat16* Al = g_Xlo + m0 * NI;
    const __nv_bfloat16* Bh = g_Whi + n0 * NI;
    const __nv_bfloat16* Bl = g_Wlo + n0 * NI;
    GEMM_K256_RING(Ah, Al, Bh, Bl);

    const int g = lane >> 2, t2 = (lane & 3) * 2;
#pragma unroll
    for (int mf = 0; mf < 2; mf++) {
        const int q0 = m0 + warp_m + mf * 16 + g;
#pragma unroll
        for (int nf = 0; nf < 8; nf++) {
            const int col = n0 + warp_n + nf * 8 + t2;
            const float b0 = bias[col], b1 = bias[col + 1];
            const float* c = acc[mf][nf];
            const float v0 = c[0] + b0, v1 = c[1] + b1;
            const float w0 = c[2] + b0, w1 = c[3] + b1;
            const int cc = col & 255;
            if (region == 0) {
                *(float2*)(g_A1 + q0 * 256 + cc)       = make_float2(v0, v1);
                *(float2*)(g_A1 + (q0 + 8) * 256 + cc) = make_float2(w0, w1);
            } else if (region == 2) {
                *(float2*)(g_S1 + q0 * 256 + cc)       = make_float2(v0, v1);
                *(float2*)(g_S1 + (q0 + 8) * 256 + cc) = make_float2(w0, w1);
            } else {
                const int kr = (region == 1 ? q0 : 4096 + q0);
                __nv_bfloat16 h0 = __float2bfloat16(v0), h1 = __float2bfloat16(v1);
                *(__nv_bfloat162*)(g_Khi + kr * 256 + cc) = __nv_bfloat162(h0, h1);
                *(__nv_bfloat162*)(g_Klo + kr * 256 + cc) = __nv_bfloat162(
                    __float2bfloat16(v0 - __bfloat162float(h0)),
                    __float2bfloat16(v1 - __bfloat162float(h1)));
                __nv_bfloat16 k0 = __float2bfloat16(w0), k1 = __float2bfloat16(w1);
                *(__nv_bfloat162*)(g_Khi + (kr + 8) * 256 + cc) = __nv_bfloat162(k0, k1);
                *(__nv_bfloat162*)(g_Klo + (kr + 8) * 256 + cc) = __nv_bfloat162(
                    __float2bfloat16(w0 - __bfloat162float(k0)),
                    __float2bfloat16(w1 - __bfloat162float(k1)));
            }
        }
    }
}

// ---------------------------------------------------------------------------
// k_base_mma: out = X @ W0^T   (tensor, 3-term)
// ---------------------------------------------------------------------------
__global__ void __launch_bounds__(256, 1) k_base_mma(float* __restrict__ out) {
    GEMM_PROLOGUE();
    const int mt = blockIdx.y, ot = blockIdx.x;
    const int m0 = mt * 128, o0 = ot * 128;

    const __nv_bfloat16* Ah = g_Xhi + m0 * NI;
    const __nv_bfloat16* Al = g_Xlo + m0 * NI;
    const __nv_bfloat16* Bh = g_W0hi + o0 * NI;
    const __nv_bfloat16* Bl = g_W0lo + o0 * NI;
    GEMM_K256_RING(Ah, Al, Bh, Bl);

    const int g = lane >> 2, t2 = (lane & 3) * 2;
#pragma unroll
    for (int mf = 0; mf < 2; mf++) {
        const int q = m0 + warp_m + mf * 16 + g;
#pragma unroll
        for (int nf = 0; nf < 8; nf++) {
            const int o = o0 + warp_n + nf * 8 + t2;
            const float* c = acc[mf][nf];
            *(float2*)(out + q * 256 + o)       = make_float2(c[0], c[1]);
            *(float2*)(out + (q + 8) * 256 + o) = make_float2(c[2], c[3]);
        }
    }
}

// ---------------------------------------------------------------------------
// k_trans_V: g_A1/g_S1 (fp32) -> transposed split bf16 VT
// ---------------------------------------------------------------------------
__global__ void k_trans_V() {
    __shared__ float t[32][33];
    const int rz = blockIdx.z;
    const float* src = rz ? g_S1 : g_A1;
    const int k0 = blockIdx.x * 32, o0 = blockIdx.y * 32;
    const int tx = threadIdx.x, ty = threadIdx.y;   // 32 x 8
#pragma unroll
    for (int i = 0; i < 32; i += 8)
        t[ty + i][tx] = src[(k0 + ty + i) * 256 + o0 + tx];
    __syncthreads();
#pragma unroll
    for (int i = 0; i < 32; i += 8) {
        float v = t[tx][ty + i];
        __nv_bfloat16 h = __float2bfloat16(v);
        int dst = (o0 + ty + i) * KCAT + rz * ROWS + k0 + tx;
        g_VThi[dst] = h;
        g_VTlo[dst] = __float2bfloat16(v - __bfloat162float(h));
    }
}

// ---------------------------------------------------------------------------
// GEMM1: P[q, kcat] = mask * gate * (X @ [A2;S2]^T)
// grid 1056. Epilogue: gate+split into padded smem tile, then fully
// coalesced 16B-per-thread stores of both P arrays.
// ---------------------------------------------------------------------------
#define EPI_PITCH 136   // bf16 elems per row (272 B) -> conflict-free banks

__global__ void __launch_bounds__(256, 1) k_gemm1() {
    GEMM_PROLOGUE();
    int i = blockIdx.x, rg = 0;
    if (i >= 528) { rg = 1; i -= 528; }
    int mt = 0;
    while ((mt + 1) * (mt + 2) / 2 <= i) mt++;
    const int nt = i - mt * (mt + 1) / 2;
    const int m0 = mt * 128;
    const int keybase = nt * 128;

    const __nv_bfloat16* Ah = g_Xhi + m0 * NI;
    const __nv_bfloat16* Al = g_Xlo + m0 * NI;
    const __nv_bfloat16* Bh = g_Khi + (rg * ROWS + keybase) * NI;
    const __nv_bfloat16* Bl = g_Klo + (rg * ROWS + keybase) * NI;
    GEMM_K256_RING(Ah, Al, Bh, Bl);

    // Epilogue: gate+mask+split into smem (mainloop smem is dead after sync).
    __syncthreads();
    __nv_bfloat16* sH = (__nv_bfloat16*)smem;                         // 128 x 136
    __nv_bfloat16* sL = (__nv_bfloat16*)(smem + 128 * EPI_PITCH * 2); // +34816 B
    const int g = lane >> 2, t2 = (lane & 3) * 2;
#pragma unroll
    for (int mf = 0; mf < 2; mf++) {
        const int rloc = warp_m + mf * 16 + g;          // local row; +8 same b
        const int q0 = m0 + rloc;
        const int s0 = q0 >> 3, b = q0 & 7;
#pragma unroll
        for (int nf = 0; nf < 8; nf++) {
            const int cl = warp_n + nf * 8 + t2;        // local col (even)
            const int col = keybase + cl;
            const int t = col >> 3;
            const float gv = rg ? -g_ss[t * 8 + b] : g_sa[t * 8 + b];
            const float sc0 = (t <= s0) ? gv : 0.f;
            const float sc1 = (t <= s0 + 1) ? gv : 0.f;
            const float* c = acc[mf][nf];

            float v0 = c[0] * sc0, v1 = c[1] * sc0;
            __nv_bfloat16 h0 = __float2bfloat16(v0), h1 = __float2bfloat16(v1);
            *(__nv_bfloat162*)(sH + rloc * EPI_PITCH + cl) = __nv_bfloat162(h0, h1);
            *(__nv_bfloat162*)(sL + rloc * EPI_PITCH + cl) = __nv_bfloat162(
                __float2bfloat16(v0 - __bfloat162float(h0)),
                __float2bfloat16(v1 - __bfloat162float(h1)));

            float w0 = c[2] * sc1, w1 = c[3] * sc1;
            __nv_bfloat16 k0 = __float2bfloat16(w0), k1 = __float2bfloat16(w1);
            *(__nv_bfloat162*)(sH + (rloc + 8) * EPI_PITCH + cl) = __nv_bfloat162(k0, k1);
            *(__nv_bfloat162*)(sL + (rloc + 8) * EPI_PITCH + cl) = __nv_bfloat162(
                __float2bfloat16(w0 - __bfloat162float(k0)),
                __float2bfloat16(w1 - __bfloat162float(k1)));
        }
    }
    __syncthreads();

    // Coalesced stores: 128 rows x 128 cols, 16 chunks of 16B per row.
    const int gbase = rg * ROWS + keybase;
#pragma unroll
    for (int it = tid; it < 2048; it += 256) {
        const int row = it >> 4;
        const int c8 = (it & 15) * 8;
        uint4 vh = *(uint4*)(sH + row * EPI_PITCH + c8);
        uint4 vl = *(uint4*)(sL + row * EPI_PITCH + c8);
        *(uint4*)(g_Phi + (size_t)(m0 + row) * KCAT + gbase + c8) = vh;
        *(uint4*)(g_Plo + (size_t)(m0 + row) * KCAT + gbase + c8) = vl;
    }
}

// ---------------------------------------------------------------------------
// GEMM2: out[q, o] += P[q, :] @ [A1;S1][:, o]   (split-K + f32 atomics)
// ---------------------------------------------------------------------------
__global__ void __launch_bounds__(256, 1) k_gemm2(float* __restrict__ out) {
    const int mt = blockIdx.x, ot = blockIdx.y, kc = blockIdx.z;
    const int nch = (mt + 4) >> 2;
    if (kc >= nch) return;
    const int klive = 256 * (mt + 1);
    const int kstart = kc * 1024;
    const int kend = (kstart + 1024 < klive) ? kstart + 1024 : klive;
    const int half = 128 * (mt + 1);
    const int m0 = mt * 128, o0 = ot * 128;
    const int nsteps = (kend - kstart) >> 5;

    GEMM_PROLOGUE();

    const __nv_bfloat16* Ah = g_Phi + (size_t)m0 * KCAT;
    const __nv_bfloat16* Al = g_Plo + (size_t)m0 * KCAT;
    const __nv_bfloat16* Bh = g_VThi + (size_t)o0 * KCAT;
    const __nv_bfloat16* Bl = g_VTlo + (size_t)o0 * KCAT;

    {
        int pk = (kstart < half) ? kstart : kstart + ROWS - half;
        load_stage(sb, Ah + pk, Al + pk, Bh + pk, Bl + pk, KCAT, KCAT, tid);
        CP_COMMIT();
        if (nsteps > 1) {
            const int lk = kstart + 32;
            pk = (lk < half) ? lk : lk + ROWS - half;
            load_stage(sb + STAGE, Ah + pk, Al + pk, Bh + pk, Bl + pk, KCAT, KCAT, tid);
        }
        CP_COMMIT();
    }
#pragma unroll 1
    for (int s = 0; s < nsteps; s++) {
        asm volatile("cp.async.wait_group 1;");
        __syncthreads();
        if (s + 2 < nsteps) {
            const int lk = kstart + (s + 2) * 32;
            const int pk = (lk < half) ? lk : lk + ROWS - half;
            load_stage(sb + ((s + 2) % 3) * STAGE, Ah + pk, Al + pk, Bh + pk, Bl + pk,
                       KCAT, KCAT, tid);
        }
        CP_COMMIT();
        compute_stage(sb + (s % 3) * STAGE, warp_m, warp_n, lane, acc);
    }

    const int g = lane >> 2, t2 = (lane & 3) * 2;
#pragma unroll
    for (int mf = 0; mf < 2; mf++) {
        const int q = m0 + warp_m + mf * 16 + g;
#pragma unroll
        for (int nf = 0; nf < 8; nf++) {
            const int o = o0 + warp_n + nf * 8 + t2;
            const float* c = acc[mf][nf];
            atomicAdd(out + q * 256 + o,           c[0]);
            atomicAdd(out + q * 256 + o + 1,       c[1]);
            atomicAdd(out + (q + 8) * 256 + o,     c[2]);
            atomicAdd(out + (q + 8) * 256 + o + 1, c[3]);
        }
    }
}

// ---------------------------------------------------------------------------
extern "C" void kernel_launch(void* const* d_in, const int* in_sizes, int n_in,
                              void* d_out, int out_size) {
    const float* x      = (const float*)d_in[0];   // (512,8,256)
    const float* slow_W = (const float*)d_in[1];   // (1026,256)
    const float* slow_b = (const float*)d_in[2];   // (1026,)
    const float* fw0    = (const float*)d_in[3];   // (256,256)
    float* out = (float*)d_out;                    // (512,8,256)

    // Unconditional every call (no static guards — harness contract).
    cudaFuncSetAttribute(k_wu_mma,   cudaFuncAttributeMaxDynamicSharedMemorySize, GEMM_SMEM);
    cudaFuncSetAttribute(k_base_mma, cudaFuncAttributeMaxDynamicSharedMemorySize, GEMM_SMEM);
    cudaFuncSetAttribute(k_gemm1,    cudaFuncAttributeMaxDynamicSharedMemorySize, GEMM_SMEM);
    cudaFuncSetAttribute(k_gemm2,    cudaFuncAttributeMaxDynamicSharedMemorySize, GEMM_SMEM);

    // Launch order chosen so the profiled launch (index 3) is k_gemm1.
    // Deps: base writes `out` before gemm2's atomics; trans_V before gemm2.
    k_prep    <<<5888, 256>>>(x, slow_W, fw0, slow_b);
    k_wu_mma  <<<dim3(8, 32), 256, GEMM_SMEM>>>(slow_b);
    k_base_mma<<<dim3(2, 32), 256, GEMM_SMEM>>>(out);
    k_gemm1   <<<1056, 256, GEMM_SMEM>>>();
    k_trans_V <<<dim3(128, 8, 2), dim3(32, 8)>>>();
    k_gemm2   <<<dim3(32, 2, 8), 256, GEMM_SMEM>>>(out);
}

// round 9
// speedup vs baseline: 3.9960x; 1.2560x over previous
#include <cuda_runtime.h>
#include <cuda_bf16.h>
#include <math.h>
#include <stdint.h>

#define ROWS 4096          // S*B = 512*8
#define KCAT 8192          // concat keys: [A (4096) | S (4096)]
#define NI 256
#define SLOW_OUTS 1026

// ---------------------------------------------------------------------------
// Scratch (device globals)
// ---------------------------------------------------------------------------
__device__ __align__(16) float g_A1[ROWS * NI];
__device__ __align__(16) float g_S1[ROWS * NI];
__device__ float g_sa[ROWS];
__device__ float g_ss[ROWS];

__device__ __align__(16) __nv_bfloat16 g_Xhi[ROWS * NI];
__device__ __align__(16) __nv_bfloat16 g_Xlo[ROWS * NI];
__device__ __align__(16) __nv_bfloat16 g_Whi[1024 * NI];   // slow_W rows 0..1023
__device__ __align__(16) __nv_bfloat16 g_Wlo[1024 * NI];
__device__ __align__(16) __nv_bfloat16 g_W0hi[NI * NI];    // fast_W0
__device__ __align__(16) __nv_bfloat16 g_W0lo[NI * NI];
__device__ __align__(16) __nv_bfloat16 g_Khi[KCAT * NI];   // rows: [A2 ; S2]
__device__ __align__(16) __nv_bfloat16 g_Klo[KCAT * NI];
__device__ __align__(16) __nv_bfloat16 g_VThi[NI * KCAT];  // VT[o][kcat] = [A1;S1][k][o]
__device__ __align__(16) __nv_bfloat16 g_VTlo[NI * KCAT];
__device__ __align__(16) __nv_bfloat16 g_Phi[(size_t)ROWS * KCAT];  // 64 MB
__device__ __align__(16) __nv_bfloat16 g_Plo[(size_t)ROWS * KCAT];  // 64 MB

// ---------------------------------------------------------------------------
// Helpers
// ---------------------------------------------------------------------------
__device__ __forceinline__ uint32_t smem_to_u32(const void* p) {
    uint32_t a;
    asm("{ .reg .u64 t; cvta.to.shared.u64 t, %1; cvt.u32.u64 %0, t; }" : "=r"(a) : "l"(p));
    return a;
}

__device__ __forceinline__ void cpa16(uint32_t s, const __nv_bfloat16* g) {
    asm volatile("cp.async.cg.shared.global [%0], [%1], 16;"
        :: "r"(s), "l"(__cvta_generic_to_global((const void*)g)));
}
#define CP_COMMIT() asm volatile("cp.async.commit_group;")

__device__ __forceinline__ void ldx4(uint32_t* r, uint32_t addr) {
    asm volatile("ldmatrix.sync.aligned.m8n8.x4.shared.b16 {%0,%1,%2,%3}, [%4];"
        : "=r"(r[0]), "=r"(r[1]), "=r"(r[2]), "=r"(r[3]) : "r"(addr));
}

__device__ __forceinline__ void mma16816(float* c, const uint32_t* a, const uint32_t* b) {
    asm volatile(
        "mma.sync.aligned.m16n8k16.row.col.f32.bf16.bf16.f32 "
        "{%0,%1,%2,%3}, {%4,%5,%6,%7}, {%8,%9}, {%0,%1,%2,%3};"
        : "+f"(c[0]), "+f"(c[1]), "+f"(c[2]), "+f"(c[3])
        : "r"(a[0]), "r"(a[1]), "r"(a[2]), "r"(a[3]), "r"(b[0]), "r"(b[1]));
}

// Stage layout: 4 operand arrays (Ah, Al, Bh, Bl), each 128 rows x 32 bf16
// (64B rows, NO pad). Bank conflicts avoided by XOR swizzle of the 16B
// segment index: phys_seg = seg ^ ((row>>1)&3). Any 8 consecutive rows at a
// fixed logical segment then hit 8 distinct bank groups (even rows -> {0..3}
// permuted, odd rows -> {4..7}) => conflict-free ldmatrix and STS.128.
// 3-stage ring = 96 KB -> 2 CTAs/SM (192 KB <= 228 KB).
#define ROWB    64
#define OFF_AH  0
#define OFF_AL  8192
#define OFF_BH  16384
#define OFF_BL  24576
#define STAGE   32768
#define GEMM_SMEM (3 * STAGE)

#define SWZ(row, seg) (((seg) ^ (((row) >> 1) & 3)) << 4)

__device__ __forceinline__ void load_stage(uint32_t st,
    const __nv_bfloat16* Ah, const __nv_bfloat16* Al,
    const __nv_bfloat16* Bh, const __nv_bfloat16* Bl,
    int sA, int sB, int tid)
{
#pragma unroll
    for (int h = 0; h < 2; h++) {
        int c = tid + h * 256;
        int row = c >> 2, seg = c & 3;
        uint32_t d = st + row * ROWB + SWZ(row, seg);
        int go = seg * 8;
        cpa16(d + OFF_AH, Ah + row * sA + go);
        cpa16(d + OFF_AL, Al + row * sA + go);
        cpa16(d + OFF_BH, Bh + row * sB + go);
        cpa16(d + OFF_BL, Bl + row * sB + go);
    }
}

// 3-term split-compensated bf16 MMA over one 32-wide K stage.
// B fragments loaded per-np to keep register pressure under the 128 cap.
__device__ __forceinline__ void compute_stage(uint32_t st, int warp_m, int warp_n,
                                              int lane, float acc[2][8][4])
{
    const int rowsel = lane & 15;
    const int chalf = lane >> 4;          // 0 or 1 (16B half within k16)
#pragma unroll
    for (int k16 = 0; k16 < 2; k16++) {
        const int c0 = k16 * 2 + chalf;   // logical 16B segment 0..3
        uint32_t ah[2][4], al[2][4];
#pragma unroll
        for (int mf = 0; mf < 2; mf++) {
            const int row = warp_m + mf * 16 + rowsel;
            uint32_t base = st + row * ROWB + SWZ(row, c0);
            ldx4(ah[mf], base + OFF_AH);
            ldx4(al[mf], base + OFF_AL);
        }
#pragma unroll
        for (int np = 0; np < 4; np++) {
            const int row = warp_n + np * 16 + rowsel;
            uint32_t base = st + row * ROWB + SWZ(row, c0);
            uint32_t rbh[4], rbl[4];
            ldx4(rbh, base + OFF_BH);
            ldx4(rbl, base + OFF_BL);
            uint32_t bh0[2] = {rbh[0], rbh[2]}, bh1[2] = {rbh[1], rbh[3]};
            uint32_t bl0[2] = {rbl[0], rbl[2]}, bl1[2] = {rbl[1], rbl[3]};
#pragma unroll
            for (int mf = 0; mf < 2; mf++) {
                mma16816(acc[mf][2 * np],     ah[mf], bh0);
                mma16816(acc[mf][2 * np],     ah[mf], bl0);
                mma16816(acc[mf][2 * np],     al[mf], bh0);
                mma16816(acc[mf][2 * np + 1], ah[mf], bh1);
                mma16816(acc[mf][2 * np + 1], ah[mf], bl1);
                mma16816(acc[mf][2 * np + 1], al[mf], bh1);
            }
        }
    }
}

#define GEMM_PROLOGUE()                                                        \
    extern __shared__ char smem[];                                             \
    const uint32_t sb = smem_to_u32(smem);                                     \
    const int tid = threadIdx.x, lane = tid & 31, wid = tid >> 5;              \
    const int warp_m = (wid >> 1) * 32, warp_n = (wid & 1) * 64;               \
    float acc[2][8][4];                                                        \
    _Pragma("unroll") for (int a_ = 0; a_ < 2; a_++)                           \
    _Pragma("unroll") for (int b_ = 0; b_ < 8; b_++)                           \
    _Pragma("unroll") for (int c_ = 0; c_ < 4; c_++) acc[a_][b_][c_] = 0.f;

// 3-stage ring over K=256 (8 stages), fixed stride NI, ONE sync per stage.
#define GEMM_K256_RING(Ah, Al, Bh, Bl)                                         \
    load_stage(sb, (Ah), (Al), (Bh), (Bl), NI, NI, tid); CP_COMMIT();          \
    load_stage(sb + STAGE, (Ah) + 32, (Al) + 32, (Bh) + 32, (Bl) + 32,         \
               NI, NI, tid);                                                   \
    CP_COMMIT();                                                               \
    _Pragma("unroll 1") for (int kc = 0; kc < 8; kc++) {                       \
        asm volatile("cp.async.wait_group 1;");                                \
        __syncthreads();                                                       \
        if (kc + 2 < 8) {                                                      \
            const int ko = (kc + 2) * 32;                                      \
            load_stage(sb + ((kc + 2) % 3) * STAGE, (Ah) + ko, (Al) + ko,      \
                       (Bh) + ko, (Bl) + ko, NI, NI, tid);                     \
        }                                                                      \
        CP_COMMIT();                                                           \
        compute_stage(sb + (kc % 3) * STAGE, warp_m, warp_n, lane, acc);       \
    }

// ---------------------------------------------------------------------------
// k_prep: X split, W split, W0 split, sigmoid gates.  grid 5888 x 256.
// ---------------------------------------------------------------------------
__global__ void k_prep(const float* __restrict__ x, const float* __restrict__ W,
                       const float* __restrict__ W0, const float* __restrict__ b) {
    const int blk = blockIdx.x;
    const int tid = threadIdx.x;
    if (blk < 4096) {                       // split X
        const int i = blk * 256 + tid;
        float v = x[i];
        __nv_bfloat16 h = __float2bfloat16(v);
        g_Xhi[i] = h;
        g_Xlo[i] = __float2bfloat16(v - __bfloat162float(h));
    } else if (blk < 5120) {                // split slow_W rows 0..1023
        const int i = (blk - 4096) * 256 + tid;
        float v = W[i];
        __nv_bfloat16 h = __float2bfloat16(v);
        g_Whi[i] = h;
        g_Wlo[i] = __float2bfloat16(v - __bfloat162float(h));
    } else if (blk < 5376) {                // split fast_W0
        const int i = (blk - 5120) * 256 + tid;
        float v = W0[i];
        __nv_bfloat16 h = __float2bfloat16(v);
        g_W0hi[i] = h;
        g_W0lo[i] = __float2bfloat16(v - __bfloat162float(h));
    } else {                                // gates
        const int q = (blk - 5376) * 8 + (tid >> 5);
        const int lane = tid & 31;
        const float4* xr = (const float4*)(x + q * 256);
        const float4* w1 = (const float4*)(W + 1024 * 256);
        const float4* w2 = (const float4*)(W + 1025 * 256);
        float s1 = 0.f, s2 = 0.f;
#pragma unroll
        for (int i = 0; i < 2; i++) {
            const int idx = lane + i * 32;
            float4 xv = xr[idx], wa = w1[idx], wb = w2[idx];
            s1 += xv.x * wa.x + xv.y * wa.y + xv.z * wa.z + xv.w * wa.w;
            s2 += xv.x * wb.x + xv.y * wb.y + xv.z * wb.z + xv.w * wb.w;
        }
#pragma unroll
        for (int off = 16; off; off >>= 1) {
            s1 += __shfl_xor_sync(0xFFFFFFFFu, s1, off);
            s2 += __shfl_xor_sync(0xFFFFFFFFu, s2, off);
        }
        if (lane == 0) {
            g_sa[q] = 1.f / (1.f + expf(-(s1 + b[1024])));
            g_ss[q] = 1.f / (1.f + expf(-(s2 + b[1025])));
        }
    }
}

// ---------------------------------------------------------------------------
// k_wu_mma: wu[:, 0:1024] = X @ slow_W[0:1024]^T + b   (tensor, 3-term)
// ---------------------------------------------------------------------------
__global__ void __launch_bounds__(256, 2) k_wu_mma(const float* __restrict__ bias) {
    GEMM_PROLOGUE();
    const int mt = blockIdx.y, ntile = blockIdx.x;
    const int m0 = mt * 128, n0 = ntile * 128;
    const int region = ntile >> 1;

    const __nv_bfloat16* Ah = g_Xhi + m0 * NI;
    const __nv_bfloat16* Al = g_Xlo + m0 * NI;
    const __nv_bfloat16* Bh = g_Whi + n0 * NI;
    const __nv_bfloat16* Bl = g_Wlo + n0 * NI;
    GEMM_K256_RING(Ah, Al, Bh, Bl);

    const int g = lane >> 2, t2 = (lane & 3) * 2;
#pragma unroll
    for (int mf = 0; mf < 2; mf++) {
        const int q0 = m0 + warp_m + mf * 16 + g;
#pragma unroll
        for (int nf = 0; nf < 8; nf++) {
            const int col = n0 + warp_n + nf * 8 + t2;
            const float b0 = bias[col], b1 = bias[col + 1];
            const float* c = acc[mf][nf];
            const float v0 = c[0] + b0, v1 = c[1] + b1;
            const float w0 = c[2] + b0, w1 = c[3] + b1;
            const int cc = col & 255;
            if (region == 0) {
                *(float2*)(g_A1 + q0 * 256 + cc)       = make_float2(v0, v1);
                *(float2*)(g_A1 + (q0 + 8) * 256 + cc) = make_float2(w0, w1);
            } else if (region == 2) {
                *(float2*)(g_S1 + q0 * 256 + cc)       = make_float2(v0, v1);
                *(float2*)(g_S1 + (q0 + 8) * 256 + cc) = make_float2(w0, w1);
            } else {
                const int kr = (region == 1 ? q0 : 4096 + q0);
                __nv_bfloat16 h0 = __float2bfloat16(v0), h1 = __float2bfloat16(v1);
                *(__nv_bfloat162*)(g_Khi + kr * 256 + cc) = __nv_bfloat162(h0, h1);
                *(__nv_bfloat162*)(g_Klo + kr * 256 + cc) = __nv_bfloat162(
                    __float2bfloat16(v0 - __bfloat162float(h0)),
                    __float2bfloat16(v1 - __bfloat162float(h1)));
                __nv_bfloat16 k0 = __float2bfloat16(w0), k1 = __float2bfloat16(w1);
                *(__nv_bfloat162*)(g_Khi + (kr + 8) * 256 + cc) = __nv_bfloat162(k0, k1);
                *(__nv_bfloat162*)(g_Klo + (kr + 8) * 256 + cc) = __nv_bfloat162(
                    __float2bfloat16(w0 - __bfloat162float(k0)),
                    __float2bfloat16(w1 - __bfloat162float(k1)));
            }
        }
    }
}

// ---------------------------------------------------------------------------
// k_base_mma: out = X @ W0^T   (tensor, 3-term)
// ---------------------------------------------------------------------------
__global__ void __launch_bounds__(256, 2) k_base_mma(float* __restrict__ out) {
    GEMM_PROLOGUE();
    const int mt = blockIdx.y, ot = blockIdx.x;
    const int m0 = mt * 128, o0 = ot * 128;

    const __nv_bfloat16* Ah = g_Xhi + m0 * NI;
    const __nv_bfloat16* Al = g_Xlo + m0 * NI;
    const __nv_bfloat16* Bh = g_W0hi + o0 * NI;
    const __nv_bfloat16* Bl = g_W0lo + o0 * NI;
    GEMM_K256_RING(Ah, Al, Bh, Bl);

    const int g = lane >> 2, t2 = (lane & 3) * 2;
#pragma unroll
    for (int mf = 0; mf < 2; mf++) {
        const int q = m0 + warp_m + mf * 16 + g;
#pragma unroll
        for (int nf = 0; nf < 8; nf++) {
            const int o = o0 + warp_n + nf * 8 + t2;
            const float* c = acc[mf][nf];
            *(float2*)(out + q * 256 + o)       = make_float2(c[0], c[1]);
            *(float2*)(out + (q + 8) * 256 + o) = make_float2(c[2], c[3]);
        }
    }
}

// ---------------------------------------------------------------------------
// k_trans_V: g_A1/g_S1 (fp32) -> transposed split bf16 VT
// ---------------------------------------------------------------------------
__global__ void k_trans_V() {
    __shared__ float t[32][33];
    const int rz = blockIdx.z;
    const float* src = rz ? g_S1 : g_A1;
    const int k0 = blockIdx.x * 32, o0 = blockIdx.y * 32;
    const int tx = threadIdx.x, ty = threadIdx.y;   // 32 x 8
#pragma unroll
    for (int i = 0; i < 32; i += 8)
        t[ty + i][tx] = src[(k0 + ty + i) * 256 + o0 + tx];
    __syncthreads();
#pragma unroll
    for (int i = 0; i < 32; i += 8) {
        float v = t[tx][ty + i];
        __nv_bfloat16 h = __float2bfloat16(v);
        int dst = (o0 + ty + i) * KCAT + rz * ROWS + k0 + tx;
        g_VThi[dst] = h;
        g_VTlo[dst] = __float2bfloat16(v - __bfloat162float(h));
    }
}

// ---------------------------------------------------------------------------
// GEMM1: P[q, kcat] = mask * gate * (X @ [A2;S2]^T)
// grid 1056. Epilogue: gate+split into padded smem tile, then fully
// coalesced 16B-per-thread stores of both P arrays.
// ---------------------------------------------------------------------------
#define EPI_PITCH 136   // bf16 elems per row (272 B) -> conflict-free banks

__global__ void __launch_bounds__(256, 2) k_gemm1() {
    GEMM_PROLOGUE();
    int i = blockIdx.x, rg = 0;
    if (i >= 528) { rg = 1; i -= 528; }
    int mt = 0;
    while ((mt + 1) * (mt + 2) / 2 <= i) mt++;
    const int nt = i - mt * (mt + 1) / 2;
    const int m0 = mt * 128;
    const int keybase = nt * 128;

    const __nv_bfloat16* Ah = g_Xhi + m0 * NI;
    const __nv_bfloat16* Al = g_Xlo + m0 * NI;
    const __nv_bfloat16* Bh = g_Khi + (rg * ROWS + keybase) * NI;
    const __nv_bfloat16* Bl = g_Klo + (rg * ROWS + keybase) * NI;
    GEMM_K256_RING(Ah, Al, Bh, Bl);

    // Epilogue: gate+mask+split into smem (mainloop smem dead after sync).
    __syncthreads();
    __nv_bfloat16* sH = (__nv_bfloat16*)smem;                         // 128 x 136
    __nv_bfloat16* sL = (__nv_bfloat16*)(smem + 128 * EPI_PITCH * 2); // +34816 B
    const int g = lane >> 2, t2 = (lane & 3) * 2;
#pragma unroll
    for (int mf = 0; mf < 2; mf++) {
        const int rloc = warp_m + mf * 16 + g;          // local row; +8 same b
        const int q0 = m0 + rloc;
        const int s0 = q0 >> 3, b = q0 & 7;
#pragma unroll
        for (int nf = 0; nf < 8; nf++) {
            const int cl = warp_n + nf * 8 + t2;        // local col (even)
            const int col = keybase + cl;
            const int t = col >> 3;
            const float gv = rg ? -g_ss[t * 8 + b] : g_sa[t * 8 + b];
            const float sc0 = (t <= s0) ? gv : 0.f;
            const float sc1 = (t <= s0 + 1) ? gv : 0.f;
            const float* c = acc[mf][nf];

            float v0 = c[0] * sc0, v1 = c[1] * sc0;
            __nv_bfloat16 h0 = __float2bfloat16(v0), h1 = __float2bfloat16(v1);
            *(__nv_bfloat162*)(sH + rloc * EPI_PITCH + cl) = __nv_bfloat162(h0, h1);
            *(__nv_bfloat162*)(sL + rloc * EPI_PITCH + cl) = __nv_bfloat162(
                __float2bfloat16(v0 - __bfloat162float(h0)),
                __float2bfloat16(v1 - __bfloat162float(h1)));

            float w0 = c[2] * sc1, w1 = c[3] * sc1;
            __nv_bfloat16 k0 = __float2bfloat16(w0), k1 = __float2bfloat16(w1);
            *(__nv_bfloat162*)(sH + (rloc + 8) * EPI_PITCH + cl) = __nv_bfloat162(k0, k1);
            *(__nv_bfloat162*)(sL + (rloc + 8) * EPI_PITCH + cl) = __nv_bfloat162(
                __float2bfloat16(w0 - __bfloat162float(k0)),
                __float2bfloat16(w1 - __bfloat162float(k1)));
        }
    }
    __syncthreads();

    // Coalesced stores: 128 rows x 128 cols, 16 chunks of 16B per row.
    const int gbase = rg * ROWS + keybase;
#pragma unroll
    for (int it = tid; it < 2048; it += 256) {
        const int row = it >> 4;
        const int c8 = (it & 15) * 8;
        uint4 vh = *(uint4*)(sH + row * EPI_PITCH + c8);
        uint4 vl = *(uint4*)(sL + row * EPI_PITCH + c8);
        *(uint4*)(g_Phi + (size_t)(m0 + row) * KCAT + gbase + c8) = vh;
        *(uint4*)(g_Plo + (size_t)(m0 + row) * KCAT + gbase + c8) = vl;
    }
}

// ---------------------------------------------------------------------------
// GEMM2: out[q, o] += P[q, :] @ [A1;S1][:, o]   (split-K + f32 atomics)
// ---------------------------------------------------------------------------
__global__ void __launch_bounds__(256, 2) k_gemm2(float* __restrict__ out) {
    const int mt = blockIdx.x, ot = blockIdx.y, kc = blockIdx.z;
    const int nch = (mt + 4) >> 2;
    if (kc >= nch) return;
    const int klive = 256 * (mt + 1);
    const int kstart = kc * 1024;
    const int kend = (kstart + 1024 < klive) ? kstart + 1024 : klive;
    const int half = 128 * (mt + 1);
    const int m0 = mt * 128, o0 = ot * 128;
    const int nsteps = (kend - kstart) >> 5;

    GEMM_PROLOGUE();

    const __nv_bfloat16* Ah = g_Phi + (size_t)m0 * KCAT;
    const __nv_bfloat16* Al = g_Plo + (size_t)m0 * KCAT;
    const __nv_bfloat16* Bh = g_VThi + (size_t)o0 * KCAT;
    const __nv_bfloat16* Bl = g_VTlo + (size_t)o0 * KCAT;

    {
        int pk = (kstart < half) ? kstart : kstart + ROWS - half;
        load_stage(sb, Ah + pk, Al + pk, Bh + pk, Bl + pk, KCAT, KCAT, tid);
        CP_COMMIT();
        if (nsteps > 1) {
            const int lk = kstart + 32;
            pk = (lk < half) ? lk : lk + ROWS - half;
            load_stage(sb + STAGE, Ah + pk, Al + pk, Bh + pk, Bl + pk, KCAT, KCAT, tid);
        }
        CP_COMMIT();
    }
#pragma unroll 1
    for (int s = 0; s < nsteps; s++) {
        asm volatile("cp.async.wait_group 1;");
        __syncthreads();
        if (s + 2 < nsteps) {
            const int lk = kstart + (s + 2) * 32;
            const int pk = (lk < half) ? lk : lk + ROWS - half;
            load_stage(sb + ((s + 2) % 3) * STAGE, Ah + pk, Al + pk, Bh + pk, Bl + pk,
                       KCAT, KCAT, tid);
        }
        CP_COMMIT();
        compute_stage(sb + (s % 3) * STAGE, warp_m, warp_n, lane, acc);
    }

    const int g = lane >> 2, t2 = (lane & 3) * 2;
#pragma unroll
    for (int mf = 0; mf < 2; mf++) {
        const int q = m0 + warp_m + mf * 16 + g;
#pragma unroll
        for (int nf = 0; nf < 8; nf++) {
            const int o = o0 + warp_n + nf * 8 + t2;
            const float* c = acc[mf][nf];
            atomicAdd(out + q * 256 + o,           c[0]);
            atomicAdd(out + q * 256 + o + 1,       c[1]);
            atomicAdd(out + (q + 8) * 256 + o,     c[2]);
            atomicAdd(out + (q + 8) * 256 + o + 1, c[3]);
        }
    }
}

// ---------------------------------------------------------------------------
extern "C" void kernel_launch(void* const* d_in, const int* in_sizes, int n_in,
                              void* d_out, int out_size) {
    const float* x      = (const float*)d_in[0];   // (512,8,256)
    const float* slow_W = (const float*)d_in[1];   // (1026,256)
    const float* slow_b = (const float*)d_in[2];   // (1026,)
    const float* fw0    = (const float*)d_in[3];   // (256,256)
    float* out = (float*)d_out;                    // (512,8,256)

    // Unconditional every call (no static guards — harness contract).
    cudaFuncSetAttribute(k_wu_mma,   cudaFuncAttributeMaxDynamicSharedMemorySize, GEMM_SMEM);
    cudaFuncSetAttribute(k_base_mma, cudaFuncAttributeMaxDynamicSharedMemorySize, GEMM_SMEM);
    cudaFuncSetAttribute(k_gemm1,    cudaFuncAttributeMaxDynamicSharedMemorySize, GEMM_SMEM);
    cudaFuncSetAttribute(k_gemm2,    cudaFuncAttributeMaxDynamicSharedMemorySize, GEMM_SMEM);

    // Launch order chosen so the profiled launch (index 3) is k_gemm1.
    k_prep    <<<5888, 256>>>(x, slow_W, fw0, slow_b);
    k_wu_mma  <<<dim3(8, 32), 256, GEMM_SMEM>>>(slow_b);
    k_base_mma<<<dim3(2, 32), 256, GEMM_SMEM>>>(out);
    k_gemm1   <<<1056, 256, GEMM_SMEM>>>();
    k_trans_V <<<dim3(128, 8, 2), dim3(32, 8)>>>();
    k_gemm2   <<<dim3(32, 2, 8), 256, GEMM_SMEM>>>(out);
}

// round 11
// speedup vs baseline: 4.0342x; 1.0096x over previous
#include <cuda_runtime.h>
#include <cuda_bf16.h>
#include <math.h>
#include <stdint.h>

#define ROWS 4096          // S*B = 512*8
#define KCAT 8192          // concat keys: [A (4096) | S (4096)]
#define NI 256
#define SLOW_OUTS 1026

// ---------------------------------------------------------------------------
// Scratch (device globals)
// ---------------------------------------------------------------------------
__device__ float g_sa[ROWS];
__device__ float g_ss[ROWS];

__device__ __align__(16) __nv_bfloat16 g_Xhi[ROWS * NI];
__device__ __align__(16) __nv_bfloat16 g_Xlo[ROWS * NI];
__device__ __align__(16) __nv_bfloat16 g_Whi[1024 * NI];   // slow_W rows 0..1023
__device__ __align__(16) __nv_bfloat16 g_Wlo[1024 * NI];
__device__ __align__(16) __nv_bfloat16 g_W0hi[NI * NI];    // fast_W0
__device__ __align__(16) __nv_bfloat16 g_W0lo[NI * NI];
__device__ __align__(16) __nv_bfloat16 g_Khi[KCAT * NI];   // rows: [A2 ; S2]
__device__ __align__(16) __nv_bfloat16 g_Klo[KCAT * NI];
__device__ __align__(16) __nv_bfloat16 g_VThi[NI * KCAT];  // VT[o][kcat] = [A1;S1][k][o]
__device__ __align__(16) __nv_bfloat16 g_VTlo[NI * KCAT];
__device__ __align__(16) __nv_bfloat16 g_Phi[(size_t)ROWS * KCAT];  // 64 MB
__device__ __align__(16) __nv_bfloat16 g_Plo[(size_t)ROWS * KCAT];  // 64 MB

// ---------------------------------------------------------------------------
// Helpers
// ---------------------------------------------------------------------------
__device__ __forceinline__ uint32_t smem_to_u32(const void* p) {
    uint32_t a;
    asm("{ .reg .u64 t; cvta.to.shared.u64 t, %1; cvt.u32.u64 %0, t; }" : "=r"(a) : "l"(p));
    return a;
}

__device__ __forceinline__ void cpa16(uint32_t s, const __nv_bfloat16* g) {
    asm volatile("cp.async.cg.shared.global [%0], [%1], 16;"
        :: "r"(s), "l"(__cvta_generic_to_global((const void*)g)));
}
#define CP_COMMIT() asm volatile("cp.async.commit_group;")

__device__ __forceinline__ void ldx4(uint32_t* r, uint32_t addr) {
    asm volatile("ldmatrix.sync.aligned.m8n8.x4.shared.b16 {%0,%1,%2,%3}, [%4];"
        : "=r"(r[0]), "=r"(r[1]), "=r"(r[2]), "=r"(r[3]) : "r"(addr));
}

__device__ __forceinline__ void mma16816(float* c, const uint32_t* a, const uint32_t* b) {
    asm volatile(
        "mma.sync.aligned.m16n8k16.row.col.f32.bf16.bf16.f32 "
        "{%0,%1,%2,%3}, {%4,%5,%6,%7}, {%8,%9}, {%0,%1,%2,%3};"
        : "+f"(c[0]), "+f"(c[1]), "+f"(c[2]), "+f"(c[3])
        : "r"(a[0]), "r"(a[1]), "r"(a[2]), "r"(a[3]), "r"(b[0]), "r"(b[1]));
}

// Stage layout: 4 operand arrays (Ah, Al, Bh, Bl), each 128 rows x 32 bf16
// (64B rows). XOR swizzle of 16B segment: phys_seg = seg ^ ((row>>1)&3) ->
// conflict-free ldmatrix / STS.128. 3-stage ring = 96 KB -> 2 CTAs/SM.
#define ROWB    64
#define OFF_AH  0
#define OFF_AL  8192
#define OFF_BH  16384
#define OFF_BL  24576
#define STAGE   32768
#define GEMM_SMEM (3 * STAGE)

#define SWZ(row, seg) (((seg) ^ (((row) >> 1) & 3)) << 4)

__device__ __forceinline__ void load_stage(uint32_t st,
    const __nv_bfloat16* Ah, const __nv_bfloat16* Al,
    const __nv_bfloat16* Bh, const __nv_bfloat16* Bl,
    int sA, int sB, int tid)
{
#pragma unroll
    for (int h = 0; h < 2; h++) {
        int c = tid + h * 256;
        int row = c >> 2, seg = c & 3;
        uint32_t d = st + row * ROWB + SWZ(row, seg);
        int go = seg * 8;
        cpa16(d + OFF_AH, Ah + row * sA + go);
        cpa16(d + OFF_AL, Al + row * sA + go);
        cpa16(d + OFF_BH, Bh + row * sB + go);
        cpa16(d + OFF_BL, Bl + row * sB + go);
    }
}

// 3-term split-compensated bf16 MMA over one 32-wide K stage.
__device__ __forceinline__ void compute_stage(uint32_t st, int warp_m, int warp_n,
                                              int lane, float acc[2][8][4])
{
    const int rowsel = lane & 15;
    const int chalf = lane >> 4;          // 0 or 1 (16B half within k16)
#pragma unroll
    for (int k16 = 0; k16 < 2; k16++) {
        const int c0 = k16 * 2 + chalf;   // logical 16B segment 0..3
        uint32_t ah[2][4], al[2][4];
#pragma unroll
        for (int mf = 0; mf < 2; mf++) {
            const int row = warp_m + mf * 16 + rowsel;
            uint32_t base = st + row * ROWB + SWZ(row, c0);
            ldx4(ah[mf], base + OFF_AH);
            ldx4(al[mf], base + OFF_AL);
        }
#pragma unroll
        for (int np = 0; np < 4; np++) {
            const int row = warp_n + np * 16 + rowsel;
            uint32_t base = st + row * ROWB + SWZ(row, c0);
            uint32_t rbh[4], rbl[4];
            ldx4(rbh, base + OFF_BH);
            ldx4(rbl, base + OFF_BL);
            uint32_t bh0[2] = {rbh[0], rbh[2]}, bh1[2] = {rbh[1], rbh[3]};
            uint32_t bl0[2] = {rbl[0], rbl[2]}, bl1[2] = {rbl[1], rbl[3]};
#pragma unroll
            for (int mf = 0; mf < 2; mf++) {
                mma16816(acc[mf][2 * np],     ah[mf], bh0);
                mma16816(acc[mf][2 * np + 1], ah[mf], bh1);
                mma16816(acc[mf][2 * np],     ah[mf], bl0);
                mma16816(acc[mf][2 * np + 1], ah[mf], bl1);
                mma16816(acc[mf][2 * np],     al[mf], bh0);
                mma16816(acc[mf][2 * np + 1], al[mf], bh1);
            }
        }
    }
}

#define GEMM_PROLOGUE()                                                        \
    extern __shared__ char smem[];                                             \
    const uint32_t sb = smem_to_u32(smem);                                     \
    const int tid = threadIdx.x, lane = tid & 31, wid = tid >> 5;              \
    const int warp_m = (wid >> 1) * 32, warp_n = (wid & 1) * 64;               \
    float acc[2][8][4];                                                        \
    _Pragma("unroll") for (int a_ = 0; a_ < 2; a_++)                           \
    _Pragma("unroll") for (int b_ = 0; b_ < 8; b_++)                           \
    _Pragma("unroll") for (int c_ = 0; c_ < 4; c_++) acc[a_][b_][c_] = 0.f;

// 3-stage ring over K=256 (8 stages), ONE sync per stage.
// ORDER IS LOAD-BEARING: wait_group (own groups drained) MUST precede
// __syncthreads (publishes ALL threads' cp.async data), which precedes the
// prefetch (overwrites the buffer whose compute the sync just retired).
#define GEMM_K256_RING(Ah, Al, Bh, Bl)                                         \
    load_stage(sb, (Ah), (Al), (Bh), (Bl), NI, NI, tid); CP_COMMIT();          \
    load_stage(sb + STAGE, (Ah) + 32, (Al) + 32, (Bh) + 32, (Bl) + 32,         \
               NI, NI, tid);                                                   \
    CP_COMMIT();                                                               \
    _Pragma("unroll 1") for (int kc = 0; kc < 8; kc++) {                       \
        asm volatile("cp.async.wait_group 1;");                                \
        __syncthreads();                                                       \
        if (kc + 2 < 8) {                                                      \
            const int ko = (kc + 2) * 32;                                      \
            load_stage(sb + ((kc + 2) % 3) * STAGE, (Ah) + ko, (Al) + ko,      \
                       (Bh) + ko, (Bl) + ko, NI, NI, tid);                     \
        }                                                                      \
        CP_COMMIT();                                                           \
        compute_stage(sb + (kc % 3) * STAGE, warp_m, warp_n, lane, acc);       \
    }

// ---------------------------------------------------------------------------
// k_prep: X split, W split, W0 split, sigmoid gates.  grid 5888 x 256.
// ---------------------------------------------------------------------------
__global__ void k_prep(const float* __restrict__ x, const float* __restrict__ W,
                       const float* __restrict__ W0, const float* __restrict__ b) {
    const int blk = blockIdx.x;
    const int tid = threadIdx.x;
    if (blk < 4096) {                       // split X
        const int i = blk * 256 + tid;
        float v = x[i];
        __nv_bfloat16 h = __float2bfloat16(v);
        g_Xhi[i] = h;
        g_Xlo[i] = __float2bfloat16(v - __bfloat162float(h));
    } else if (blk < 5120) {                // split slow_W rows 0..1023
        const int i = (blk - 4096) * 256 + tid;
        float v = W[i];
        __nv_bfloat16 h = __float2bfloat16(v);
        g_Whi[i] = h;
        g_Wlo[i] = __float2bfloat16(v - __bfloat162float(h));
    } else if (blk < 5376) {                // split fast_W0
        const int i = (blk - 5120) * 256 + tid;
        float v = W0[i];
        __nv_bfloat16 h = __float2bfloat16(v);
        g_W0hi[i] = h;
        g_W0lo[i] = __float2bfloat16(v - __bfloat162float(h));
    } else {                                // gates
        const int q = (blk - 5376) * 8 + (tid >> 5);
        const int lane = tid & 31;
        const float4* xr = (const float4*)(x + q * 256);
        const float4* w1 = (const float4*)(W + 1024 * 256);
        const float4* w2 = (const float4*)(W + 1025 * 256);
        float s1 = 0.f, s2 = 0.f;
#pragma unroll
        for (int i = 0; i < 2; i++) {
            const int idx = lane + i * 32;
            float4 xv = xr[idx], wa = w1[idx], wb = w2[idx];
            s1 += xv.x * wa.x + xv.y * wa.y + xv.z * wa.z + xv.w * wa.w;
            s2 += xv.x * wb.x + xv.y * wb.y + xv.z * wb.z + xv.w * wb.w;
        }
#pragma unroll
        for (int off = 16; off; off >>= 1) {
            s1 += __shfl_xor_sync(0xFFFFFFFFu, s1, off);
            s2 += __shfl_xor_sync(0xFFFFFFFFu, s2, off);
        }
        if (lane == 0) {
            g_sa[q] = 1.f / (1.f + expf(-(s1 + b[1024])));
            g_ss[q] = 1.f / (1.f + expf(-(s2 + b[1025])));
        }
    }
}

// ---------------------------------------------------------------------------
// k_wu_mma: wu[:, 0:1024] = X @ slow_W[0:1024]^T + b   (tensor, 3-term)
// grid (8 ntile, 32 mt). Epilogue routes per region:
//   region 0 (A1) / 2 (S1): smem-transpose -> split bf16 VT (fused trans_V)
//   region 1 (A2) / 3 (S2): split bf16 -> g_Khi/g_Klo
// ---------------------------------------------------------------------------
__global__ void __launch_bounds__(256, 2) k_wu_mma(const float* __restrict__ bias) {
    GEMM_PROLOGUE();
    const int mt = blockIdx.y, ntile = blockIdx.x;
    const int m0 = mt * 128, n0 = ntile * 128;
    const int region = ntile >> 1;

    const __nv_bfloat16* Ah = g_Xhi + m0 * NI;
    const __nv_bfloat16* Al = g_Xlo + m0 * NI;
    const __nv_bfloat16* Bh = g_Whi + n0 * NI;
    const __nv_bfloat16* Bl = g_Wlo + n0 * NI;
    GEMM_K256_RING(Ah, Al, Bh, Bl);

    const int g = lane >> 2, t2 = (lane & 3) * 2;
    if (region & 1) {
        // A2 / S2 -> split bf16 into g_K rows
#pragma unroll
        for (int mf = 0; mf < 2; mf++) {
            const int q0 = m0 + warp_m + mf * 16 + g;
#pragma unroll
            for (int nf = 0; nf < 8; nf++) {
                const int col = n0 + warp_n + nf * 8 + t2;
                const float b0 = bias[col], b1 = bias[col + 1];
                const float* c = acc[mf][nf];
                const float v0 = c[0] + b0, v1 = c[1] + b1;
                const float w0 = c[2] + b0, w1 = c[3] + b1;
                const int cc = col & 255;
                const int kr = (region == 1 ? q0 : 4096 + q0);
                __nv_bfloat16 h0 = __float2bfloat16(v0), h1 = __float2bfloat16(v1);
                *(__nv_bfloat162*)(g_Khi + kr * 256 + cc) = __nv_bfloat162(h0, h1);
                *(__nv_bfloat162*)(g_Klo + kr * 256 + cc) = __nv_bfloat162(
                    __float2bfloat16(v0 - __bfloat162float(h0)),
                    __float2bfloat16(v1 - __bfloat162float(h1)));
                __nv_bfloat16 k0 = __float2bfloat16(w0), k1 = __float2bfloat16(w1);
                *(__nv_bfloat162*)(g_Khi + (kr + 8) * 256 + cc) = __nv_bfloat162(k0, k1);
                *(__nv_bfloat162*)(g_Klo + (kr + 8) * 256 + cc) = __nv_bfloat162(
                    __float2bfloat16(w0 - __bfloat162float(k0)),
                    __float2bfloat16(w1 - __bfloat162float(k1)));
            }
        }
    } else {
        // A1 / S1 -> transposed split bf16 VT via smem (fused k_trans_V)
        __syncthreads();                      // mainloop smem now dead
        float* sT = (float*)smem;             // [128 cols][pitch 132] fp32
#pragma unroll
        for (int mf = 0; mf < 2; mf++) {
            const int rloc = warp_m + mf * 16 + g;
#pragma unroll
            for (int nf = 0; nf < 8; nf++) {
                const int cl = warp_n + nf * 8 + t2;
                const int col = n0 + cl;
                const float b0 = bias[col], b1 = bias[col + 1];
                const float* c = acc[mf][nf];
                sT[cl * 132 + rloc]           = c[0] + b0;
                sT[(cl + 1) * 132 + rloc]     = c[1] + b1;
                sT[cl * 132 + rloc + 8]       = c[2] + b0;
                sT[(cl + 1) * 132 + rloc + 8] = c[3] + b1;
            }
        }
        __syncthreads();
        const int rz = region >> 1;           // 0: A1, 1: S1
        const int o_loc = tid >> 1;
        const int qh = (tid & 1) * 64;
        const int o_glob = (ntile & 1) * 128 + o_loc;
        const float* srow = sT + o_loc * 132 + qh;
        const size_t dst = (size_t)o_glob * KCAT + rz * ROWS + m0 + qh;
#pragma unroll
        for (int j8 = 0; j8 < 8; j8++) {
            union { __nv_bfloat16 h[8]; uint4 u; } H, L;
#pragma unroll
            for (int e = 0; e < 8; e++) {
                float f = srow[j8 * 8 + e];
                __nv_bfloat16 hh = __float2bfloat16(f);
                H.h[e] = hh;
                L.h[e] = __float2bfloat16(f - __bfloat162float(hh));
            }
            *(uint4*)(g_VThi + dst + j8 * 8) = H.u;
            *(uint4*)(g_VTlo + dst + j8 * 8) = L.u;
        }
    }
}

// ---------------------------------------------------------------------------
// k_base_mma: out = X @ W0^T   (tensor, 3-term)
// ---------------------------------------------------------------------------
__global__ void __launch_bounds__(256, 2) k_base_mma(float* __restrict__ out) {
    GEMM_PROLOGUE();
    const int mt = blockIdx.y, ot = blockIdx.x;
    const int m0 = mt * 128, o0 = ot * 128;

    const __nv_bfloat16* Ah = g_Xhi + m0 * NI;
    const __nv_bfloat16* Al = g_Xlo + m0 * NI;
    const __nv_bfloat16* Bh = g_W0hi + o0 * NI;
    const __nv_bfloat16* Bl = g_W0lo + o0 * NI;
    GEMM_K256_RING(Ah, Al, Bh, Bl);

    const int g = lane >> 2, t2 = (lane & 3) * 2;
#pragma unroll
    for (int mf = 0; mf < 2; mf++) {
        const int q = m0 + warp_m + mf * 16 + g;
#pragma unroll
        for (int nf = 0; nf < 8; nf++) {
            const int o = o0 + warp_n + nf * 8 + t2;
            const float* c = acc[mf][nf];
            *(float2*)(out + q * 256 + o)       = make_float2(c[0], c[1]);
            *(float2*)(out + (q + 8) * 256 + o) = make_float2(c[2], c[3]);
        }
    }
}

// ---------------------------------------------------------------------------
// GEMM1: P[q, kcat] = mask * gate * (X @ [A2;S2]^T)
// grid 1056. Epilogue: gate+split into padded smem tile, then fully
// coalesced 16B-per-thread stores of both P arrays.
// ---------------------------------------------------------------------------
#define EPI_PITCH 136   // bf16 elems per row (272 B) -> conflict-free banks

__global__ void __launch_bounds__(256, 2) k_gemm1() {
    GEMM_PROLOGUE();
    int i = blockIdx.x, rg = 0;
    if (i >= 528) { rg = 1; i -= 528; }
    int mt = 0;
    while ((mt + 1) * (mt + 2) / 2 <= i) mt++;
    const int nt = i - mt * (mt + 1) / 2;
    const int m0 = mt * 128;
    const int keybase = nt * 128;

    const __nv_bfloat16* Ah = g_Xhi + m0 * NI;
    const __nv_bfloat16* Al = g_Xlo + m0 * NI;
    const __nv_bfloat16* Bh = g_Khi + (rg * ROWS + keybase) * NI;
    const __nv_bfloat16* Bl = g_Klo + (rg * ROWS + keybase) * NI;
    GEMM_K256_RING(Ah, Al, Bh, Bl);

    // Epilogue: gate+mask+split into smem (mainloop smem dead after sync).
    __syncthreads();
    __nv_bfloat16* sH = (__nv_bfloat16*)smem;                         // 128 x 136
    __nv_bfloat16* sL = (__nv_bfloat16*)(smem + 128 * EPI_PITCH * 2); // +34816 B
    const int g = lane >> 2, t2 = (lane & 3) * 2;
#pragma unroll
    for (int mf = 0; mf < 2; mf++) {
        const int rloc = warp_m + mf * 16 + g;          // local row; +8 same b
        const int q0 = m0 + rloc;
        const int s0 = q0 >> 3, b = q0 & 7;
#pragma unroll
        for (int nf = 0; nf < 8; nf++) {
            const int cl = warp_n + nf * 8 + t2;        // local col (even)
            const int col = keybase + cl;
            const int t = col >> 3;
            const float gv = rg ? -g_ss[t * 8 + b] : g_sa[t * 8 + b];
            const float sc0 = (t <= s0) ? gv : 0.f;
            const float sc1 = (t <= s0 + 1) ? gv : 0.f;
            const float* c = acc[mf][nf];

            float v0 = c[0] * sc0, v1 = c[1] * sc0;
            __nv_bfloat16 h0 = __float2bfloat16(v0), h1 = __float2bfloat16(v1);
            *(__nv_bfloat162*)(sH + rloc * EPI_PITCH + cl) = __nv_bfloat162(h0, h1);
            *(__nv_bfloat162*)(sL + rloc * EPI_PITCH + cl) = __nv_bfloat162(
                __float2bfloat16(v0 - __bfloat162float(h0)),
                __float2bfloat16(v1 - __bfloat162float(h1)));

            float w0 = c[2] * sc1, w1 = c[3] * sc1;
            __nv_bfloat16 k0 = __float2bfloat16(w0), k1 = __float2bfloat16(w1);
            *(__nv_bfloat162*)(sH + (rloc + 8) * EPI_PITCH + cl) = __nv_bfloat162(k0, k1);
            *(__nv_bfloat162*)(sL + (rloc + 8) * EPI_PITCH + cl) = __nv_bfloat162(
                __float2bfloat16(w0 - __bfloat162float(k0)),
                __float2bfloat16(w1 - __bfloat162float(k1)));
        }
    }
    __syncthreads();

    // Coalesced stores: 128 rows x 128 cols, 16 chunks of 16B per row.
    const int gbase = rg * ROWS + keybase;
#pragma unroll
    for (int it = tid; it < 2048; it += 256) {
        const int row = it >> 4;
        const int c8 = (it & 15) * 8;
        uint4 vh = *(uint4*)(sH + row * EPI_PITCH + c8);
        uint4 vl = *(uint4*)(sL + row * EPI_PITCH + c8);
        *(uint4*)(g_Phi + (size_t)(m0 + row) * KCAT + gbase + c8) = vh;
        *(uint4*)(g_Plo + (size_t)(m0 + row) * KCAT + gbase + c8) = vl;
    }
}

// ---------------------------------------------------------------------------
// GEMM2: out[q, o] += P[q, :] @ [A1;S1][:, o]   (split-K + f32 atomics)
// Logical k in [0, 256*(mt+1)) maps to phys [0, half) U [4096, 4096+half).
// ---------------------------------------------------------------------------
__global__ void __launch_bounds__(256, 2) k_gemm2(float* __restrict__ out) {
    const int mt = blockIdx.x, ot = blockIdx.y, kc = blockIdx.z;
    const int nch = (mt + 4) >> 2;
    if (kc >= nch) return;
    const int klive = 256 * (mt + 1);
    const int kstart = kc * 1024;
    const int kend = (kstart + 1024 < klive) ? kstart + 1024 : klive;
    const int half = 128 * (mt + 1);
    const int m0 = mt * 128, o0 = ot * 128;
    const int nsteps = (kend - kstart) >> 5;

    GEMM_PROLOGUE();

    const __nv_bfloat16* Ah = g_Phi + (size_t)m0 * KCAT;
    const __nv_bfloat16* Al = g_Plo + (size_t)m0 * KCAT;
    const __nv_bfloat16* Bh = g_VThi + (size_t)o0 * KCAT;
    const __nv_bfloat16* Bl = g_VTlo + (size_t)o0 * KCAT;

    {
        int pk = (kstart < half) ? kstart : kstart + ROWS - half;
        load_stage(sb, Ah + pk, Al + pk, Bh + pk, Bl + pk, KCAT, KCAT, tid);
        CP_COMMIT();
        if (nsteps > 1) {
            const int lk = kstart + 32;
            pk = (lk < half) ? lk : lk + ROWS - half;
            load_stage(sb + STAGE, Ah + pk, Al + pk, Bh + pk, Bl + pk, KCAT, KCAT, tid);
        }
        CP_COMMIT();
    }
#pragma unroll 1
    for (int s = 0; s < nsteps; s++) {
        asm volatile("cp.async.wait_group 1;");
        __syncthreads();
        if (s + 2 < nsteps) {
            const int lk = kstart + (s + 2) * 32;
            const int pk = (lk < half) ? lk : lk + ROWS - half;
            load_stage(sb + ((s + 2) % 3) * STAGE, Ah + pk, Al + pk, Bh + pk, Bl + pk,
                       KCAT, KCAT, tid);
        }
        CP_COMMIT();
        compute_stage(sb + (s % 3) * STAGE, warp_m, warp_n, lane, acc);
    }

    const int g = lane >> 2, t2 = (lane & 3) * 2;
#pragma unroll
    for (int mf = 0; mf < 2; mf++) {
        const int q = m0 + warp_m + mf * 16 + g;
#pragma unroll
        for (int nf = 0; nf < 8; nf++) {
            const int o = o0 + warp_n + nf * 8 + t2;
            const float* c = acc[mf][nf];
            atomicAdd(out + q * 256 + o,           c[0]);
            atomicAdd(out + q * 256 + o + 1,       c[1]);
            atomicAdd(out + (q + 8) * 256 + o,     c[2]);
            atomicAdd(out + (q + 8) * 256 + o + 1, c[3]);
        }
    }
}

// ---------------------------------------------------------------------------
extern "C" void kernel_launch(void* const* d_in, const int* in_sizes, int n_in,
                              void* d_out, int out_size) {
    const float* x      = (const float*)d_in[0];   // (512,8,256)
    const float* slow_W = (const float*)d_in[1];   // (1026,256)
    const float* slow_b = (const float*)d_in[2];   // (1026,)
    const float* fw0    = (const float*)d_in[3];   // (256,256)
    float* out = (float*)d_out;                    // (512,8,256)

    // Unconditional every call (no static guards — harness contract).
    cudaFuncSetAttribute(k_wu_mma,   cudaFuncAttributeMaxDynamicSharedMemorySize, GEMM_SMEM);
    cudaFuncSetAttribute(k_base_mma, cudaFuncAttributeMaxDynamicSharedMemorySize, GEMM_SMEM);
    cudaFuncSetAttribute(k_gemm1,    cudaFuncAttributeMaxDynamicSharedMemorySize, GEMM_SMEM);
    cudaFuncSetAttribute(k_gemm2,    cudaFuncAttributeMaxDynamicSharedMemorySize, GEMM_SMEM);

    // k_gemm1 at launch index 3 (the profiled slot).
    k_prep    <<<5888, 256>>>(x, slow_W, fw0, slow_b);
    k_wu_mma  <<<dim3(8, 32), 256, GEMM_SMEM>>>(slow_b);
    k_base_mma<<<dim3(2, 32), 256, GEMM_SMEM>>>(out);
    k_gemm1   <<<1056, 256, GEMM_SMEM>>>();
    k_gemm2   <<<dim3(32, 2, 8), 256, GEMM_SMEM>>>(out);
}

// round 12
// speedup vs baseline: 4.1004x; 1.0164x over previous
#include <cuda_runtime.h>
#include <cuda_bf16.h>
#include <math.h>
#include <stdint.h>

#define ROWS 4096          // S*B = 512*8
#define KCAT 8192          // concat keys: [A (4096) | S (4096)]
#define NI 256
#define SLOW_OUTS 1026

// ---------------------------------------------------------------------------
// Scratch (device globals)
// ---------------------------------------------------------------------------
__device__ float g_sa[ROWS];
__device__ float g_ss[ROWS];

__device__ __align__(16) __nv_bfloat16 g_Xhi[ROWS * NI];
__device__ __align__(16) __nv_bfloat16 g_Xlo[ROWS * NI];
__device__ __align__(16) __nv_bfloat16 g_Whi[1024 * NI];   // slow_W rows 0..1023
__device__ __align__(16) __nv_bfloat16 g_Wlo[1024 * NI];
__device__ __align__(16) __nv_bfloat16 g_W0hi[NI * NI];    // fast_W0
__device__ __align__(16) __nv_bfloat16 g_W0lo[NI * NI];
__device__ __align__(16) __nv_bfloat16 g_Khi[KCAT * NI];   // rows: [A2 ; S2]
__device__ __align__(16) __nv_bfloat16 g_Klo[KCAT * NI];
__device__ __align__(16) __nv_bfloat16 g_VThi[NI * KCAT];  // VT[o][kcat] = [A1;S1][k][o]
__device__ __align__(16) __nv_bfloat16 g_VTlo[NI * KCAT];
__device__ __align__(16) __nv_bfloat16 g_Phi[(size_t)ROWS * KCAT];  // 64 MB
__device__ __align__(16) __nv_bfloat16 g_Plo[(size_t)ROWS * KCAT];  // 64 MB

// ---------------------------------------------------------------------------
// Helpers
// ---------------------------------------------------------------------------
__device__ __forceinline__ uint32_t smem_to_u32(const void* p) {
    uint32_t a;
    asm("{ .reg .u64 t; cvta.to.shared.u64 t, %1; cvt.u32.u64 %0, t; }" : "=r"(a) : "l"(p));
    return a;
}

__device__ __forceinline__ void cpa16(uint32_t s, const __nv_bfloat16* g) {
    asm volatile("cp.async.cg.shared.global [%0], [%1], 16;"
        :: "r"(s), "l"(__cvta_generic_to_global((const void*)g)));
}
#define CP_COMMIT() asm volatile("cp.async.commit_group;")

__device__ __forceinline__ void ldx4(uint32_t* r, uint32_t addr) {
    asm volatile("ldmatrix.sync.aligned.m8n8.x4.shared.b16 {%0,%1,%2,%3}, [%4];"
        : "=r"(r[0]), "=r"(r[1]), "=r"(r[2]), "=r"(r[3]) : "r"(addr));
}

__device__ __forceinline__ void mma16816(float* c, const uint32_t* a, const uint32_t* b) {
    asm volatile(
        "mma.sync.aligned.m16n8k16.row.col.f32.bf16.bf16.f32 "
        "{%0,%1,%2,%3}, {%4,%5,%6,%7}, {%8,%9}, {%0,%1,%2,%3};"
        : "+f"(c[0]), "+f"(c[1]), "+f"(c[2]), "+f"(c[3])
        : "r"(a[0]), "r"(a[1]), "r"(a[2]), "r"(a[3]), "r"(b[0]), "r"(b[1]));
}

// CTA tile 128(M) x 64(N), K-stage 32. Operand arrays: A 128x32, B 64x32 bf16
// (64B rows, XOR-swizzled 16B segments -> conflict-free ldmatrix / STS.128).
// Stage = 24 KB; 3-stage ring = 72 KB -> 3 CTAs/SM (24 warps).
#define ROWB    64
#define OFF_AH  0
#define OFF_AL  8192
#define OFF_BH  16384
#define OFF_BL  20480
#define STAGE   24576
#define GEMM_SMEM (3 * STAGE)

#define SWZ(row, seg) (((seg) ^ (((row) >> 1) & 3)) << 4)

__device__ __forceinline__ void load_stage(uint32_t st,
    const __nv_bfloat16* Ah, const __nv_bfloat16* Al,
    const __nv_bfloat16* Bh, const __nv_bfloat16* Bl,
    int sA, int sB, int tid)
{
#pragma unroll
    for (int h = 0; h < 2; h++) {                 // A: 128 rows x 4 segs
        int c = tid + h * 256;
        int row = c >> 2, seg = c & 3;
        uint32_t d = st + row * ROWB + SWZ(row, seg);
        int go = seg * 8;
        cpa16(d + OFF_AH, Ah + row * sA + go);
        cpa16(d + OFF_AL, Al + row * sA + go);
    }
    {                                             // B: 64 rows x 4 segs
        int row = tid >> 2, seg = tid & 3;
        uint32_t d = st + row * ROWB + SWZ(row, seg);
        int go = seg * 8;
        cpa16(d + OFF_BH, Bh + row * sB + go);
        cpa16(d + OFF_BL, Bl + row * sB + go);
    }
}

// 3-term split-compensated bf16 MMA over one 32-wide K stage.
// Warp tile 32(M) x 32(N): acc[2][4][4].
__device__ __forceinline__ void compute_stage(uint32_t st, int warp_m, int warp_n,
                                              int lane, float acc[2][4][4])
{
    const int rowsel = lane & 15;
    const int chalf = lane >> 4;          // 0 or 1 (16B half within k16)
#pragma unroll
    for (int k16 = 0; k16 < 2; k16++) {
        const int c0 = k16 * 2 + chalf;   // logical 16B segment 0..3
        uint32_t ah[2][4], al[2][4];
#pragma unroll
        for (int mf = 0; mf < 2; mf++) {
            const int row = warp_m + mf * 16 + rowsel;
            uint32_t base = st + row * ROWB + SWZ(row, c0);
            ldx4(ah[mf], base + OFF_AH);
            ldx4(al[mf], base + OFF_AL);
        }
#pragma unroll
        for (int np = 0; np < 2; np++) {
            const int row = warp_n + np * 16 + rowsel;
            uint32_t base = st + row * ROWB + SWZ(row, c0);
            uint32_t rbh[4], rbl[4];
            ldx4(rbh, base + OFF_BH);
            ldx4(rbl, base + OFF_BL);
            uint32_t bh0[2] = {rbh[0], rbh[2]}, bh1[2] = {rbh[1], rbh[3]};
            uint32_t bl0[2] = {rbl[0], rbl[2]}, bl1[2] = {rbl[1], rbl[3]};
#pragma unroll
            for (int mf = 0; mf < 2; mf++) {
                mma16816(acc[mf][2 * np],     ah[mf], bh0);
                mma16816(acc[mf][2 * np + 1], ah[mf], bh1);
                mma16816(acc[mf][2 * np],     ah[mf], bl0);
                mma16816(acc[mf][2 * np + 1], ah[mf], bl1);
                mma16816(acc[mf][2 * np],     al[mf], bh0);
                mma16816(acc[mf][2 * np + 1], al[mf], bh1);
            }
        }
    }
}

#define GEMM_PROLOGUE()                                                        \
    extern __shared__ char smem[];                                             \
    const uint32_t sb = smem_to_u32(smem);                                     \
    const int tid = threadIdx.x, lane = tid & 31, wid = tid >> 5;              \
    const int warp_m = (wid >> 1) * 32, warp_n = (wid & 1) * 32;               \
    float acc[2][4][4];                                                        \
    _Pragma("unroll") for (int a_ = 0; a_ < 2; a_++)                           \
    _Pragma("unroll") for (int b_ = 0; b_ < 4; b_++)                           \
    _Pragma("unroll") for (int c_ = 0; c_ < 4; c_++) acc[a_][b_][c_] = 0.f;

// 3-stage ring over K=256 (8 stages), ONE sync per stage.
// ORDER IS LOAD-BEARING: wait_group (own groups drained) MUST precede
// __syncthreads (publishes ALL threads' cp.async data), which precedes the
// prefetch (overwrites the buffer whose compute the sync just retired).
#define GEMM_K256_RING(Ah, Al, Bh, Bl)                                         \
    load_stage(sb, (Ah), (Al), (Bh), (Bl), NI, NI, tid); CP_COMMIT();          \
    load_stage(sb + STAGE, (Ah) + 32, (Al) + 32, (Bh) + 32, (Bl) + 32,         \
               NI, NI, tid);                                                   \
    CP_COMMIT();                                                               \
    _Pragma("unroll 1") for (int kc = 0; kc < 8; kc++) {                       \
        asm volatile("cp.async.wait_group 1;");                                \
        __syncthreads();                                                       \
        if (kc + 2 < 8) {                                                      \
            const int ko = (kc + 2) * 32;                                      \
            load_stage(sb + ((kc + 2) % 3) * STAGE, (Ah) + ko, (Al) + ko,      \
                       (Bh) + ko, (Bl) + ko, NI, NI, tid);                     \
        }                                                                      \
        CP_COMMIT();                                                           \
        compute_stage(sb + (kc % 3) * STAGE, warp_m, warp_n, lane, acc);       \
    }

// ---------------------------------------------------------------------------
// k_prep: X split, W split, W0 split, sigmoid gates.  grid 5888 x 256.
// ---------------------------------------------------------------------------
__global__ void k_prep(const float* __restrict__ x, const float* __restrict__ W,
                       const float* __restrict__ W0, const float* __restrict__ b) {
    const int blk = blockIdx.x;
    const int tid = threadIdx.x;
    if (blk < 4096) {                       // split X
        const int i = blk * 256 + tid;
        float v = x[i];
        __nv_bfloat16 h = __float2bfloat16(v);
        g_Xhi[i] = h;
        g_Xlo[i] = __float2bfloat16(v - __bfloat162float(h));
    } else if (blk < 5120) {                // split slow_W rows 0..1023
        const int i = (blk - 4096) * 256 + tid;
        float v = W[i];
        __nv_bfloat16 h = __float2bfloat16(v);
        g_Whi[i] = h;
        g_Wlo[i] = __float2bfloat16(v - __bfloat162float(h));
    } else if (blk < 5376) {                // split fast_W0
        const int i = (blk - 5120) * 256 + tid;
        float v = W0[i];
        __nv_bfloat16 h = __float2bfloat16(v);
        g_W0hi[i] = h;
        g_W0lo[i] = __float2bfloat16(v - __bfloat162float(h));
    } else {                                // gates
        const int q = (blk - 5376) * 8 + (tid >> 5);
        const int lane = tid & 31;
        const float4* xr = (const float4*)(x + q * 256);
        const float4* w1 = (const float4*)(W + 1024 * 256);
        const float4* w2 = (const float4*)(W + 1025 * 256);
        float s1 = 0.f, s2 = 0.f;
#pragma unroll
        for (int i = 0; i < 2; i++) {
            const int idx = lane + i * 32;
            float4 xv = xr[idx], wa = w1[idx], wb = w2[idx];
            s1 += xv.x * wa.x + xv.y * wa.y + xv.z * wa.z + xv.w * wa.w;
            s2 += xv.x * wb.x + xv.y * wb.y + xv.z * wb.z + xv.w * wb.w;
        }
#pragma unroll
        for (int off = 16; off; off >>= 1) {
            s1 += __shfl_xor_sync(0xFFFFFFFFu, s1, off);
            s2 += __shfl_xor_sync(0xFFFFFFFFu, s2, off);
        }
        if (lane == 0) {
            g_sa[q] = 1.f / (1.f + expf(-(s1 + b[1024])));
            g_ss[q] = 1.f / (1.f + expf(-(s2 + b[1025])));
        }
    }
}

// ---------------------------------------------------------------------------
// k_wu_mma: wu[:, 0:1024] = X @ slow_W[0:1024]^T + b   (tensor, 3-term)
// grid (16 ntile, 32 mt), tiles 128 x 64. region = ntile>>2:
//   region 0 (A1) / 2 (S1): smem-transpose -> split bf16 VT (fused trans_V)
//   region 1 (A2) / 3 (S2): split bf16 -> g_Khi/g_Klo
// ---------------------------------------------------------------------------
__global__ void __launch_bounds__(256, 3) k_wu_mma(const float* __restrict__ bias) {
    GEMM_PROLOGUE();
    const int mt = blockIdx.y, ntile = blockIdx.x;
    const int m0 = mt * 128, n0 = ntile * 64;
    const int region = ntile >> 2;

    const __nv_bfloat16* Ah = g_Xhi + m0 * NI;
    const __nv_bfloat16* Al = g_Xlo + m0 * NI;
    const __nv_bfloat16* Bh = g_Whi + n0 * NI;
    const __nv_bfloat16* Bl = g_Wlo + n0 * NI;
    GEMM_K256_RING(Ah, Al, Bh, Bl);

    const int g = lane >> 2, t2 = (lane & 3) * 2;
    if (region & 1) {
        // A2 / S2 -> split bf16 into g_K rows
#pragma unroll
        for (int mf = 0; mf < 2; mf++) {
            const int q0 = m0 + warp_m + mf * 16 + g;
#pragma unroll
            for (int nf = 0; nf < 4; nf++) {
                const int col = n0 + warp_n + nf * 8 + t2;
                const float b0 = bias[col], b1 = bias[col + 1];
                const float* c = acc[mf][nf];
                const float v0 = c[0] + b0, v1 = c[1] + b1;
                const float w0 = c[2] + b0, w1 = c[3] + b1;
                const int cc = col & 255;
                const int kr = (region == 1 ? q0 : 4096 + q0);
                __nv_bfloat16 h0 = __float2bfloat16(v0), h1 = __float2bfloat16(v1);
                *(__nv_bfloat162*)(g_Khi + kr * 256 + cc) = __nv_bfloat162(h0, h1);
                *(__nv_bfloat162*)(g_Klo + kr * 256 + cc) = __nv_bfloat162(
                    __float2bfloat16(v0 - __bfloat162float(h0)),
                    __float2bfloat16(v1 - __bfloat162float(h1)));
                __nv_bfloat16 k0 = __float2bfloat16(w0), k1 = __float2bfloat16(w1);
                *(__nv_bfloat162*)(g_Khi + (kr + 8) * 256 + cc) = __nv_bfloat162(k0, k1);
                *(__nv_bfloat162*)(g_Klo + (kr + 8) * 256 + cc) = __nv_bfloat162(
                    __float2bfloat16(w0 - __bfloat162float(k0)),
                    __float2bfloat16(w1 - __bfloat162float(k1)));
            }
        }
    } else {
        // A1 / S1 -> transposed split bf16 VT via smem (fused k_trans_V)
        __syncthreads();                      // mainloop smem now dead
        float* sT = (float*)smem;             // [64 cols][pitch 132] fp32
#pragma unroll
        for (int mf = 0; mf < 2; mf++) {
            const int rloc = warp_m + mf * 16 + g;
#pragma unroll
            for (int nf = 0; nf < 4; nf++) {
                const int cl = warp_n + nf * 8 + t2;
                const int col = n0 + cl;
                const float b0 = bias[col], b1 = bias[col + 1];
                const float* c = acc[mf][nf];
                sT[cl * 132 + rloc]           = c[0] + b0;
                sT[(cl + 1) * 132 + rloc]     = c[1] + b1;
                sT[cl * 132 + rloc + 8]       = c[2] + b0;
                sT[(cl + 1) * 132 + rloc + 8] = c[3] + b1;
            }
        }
        __syncthreads();
        const int rz = region >> 1;           // 0: A1, 1: S1
        const int o_loc = tid >> 2;           // 0..63
        const int qh = (tid & 3) * 32;        // 0,32,64,96
        const int o_glob = (ntile & 3) * 64 + o_loc;
        const float* srow = sT + o_loc * 132 + qh;
        const size_t dst = (size_t)o_glob * KCAT + rz * ROWS + m0 + qh;
#pragma unroll
        for (int j8 = 0; j8 < 4; j8++) {
            union { __nv_bfloat16 h[8]; uint4 u; } H, L;
#pragma unroll
            for (int e = 0; e < 8; e++) {
                float f = srow[j8 * 8 + e];
                __nv_bfloat16 hh = __float2bfloat16(f);
                H.h[e] = hh;
                L.h[e] = __float2bfloat16(f - __bfloat162float(hh));
            }
            *(uint4*)(g_VThi + dst + j8 * 8) = H.u;
            *(uint4*)(g_VTlo + dst + j8 * 8) = L.u;
        }
    }
}

// ---------------------------------------------------------------------------
// k_base_mma: out = X @ W0^T   (tensor, 3-term). grid (4 ot, 32 mt).
// ---------------------------------------------------------------------------
__global__ void __launch_bounds__(256, 3) k_base_mma(float* __restrict__ out) {
    GEMM_PROLOGUE();
    const int mt = blockIdx.y, ot = blockIdx.x;
    const int m0 = mt * 128, o0 = ot * 64;

    const __nv_bfloat16* Ah = g_Xhi + m0 * NI;
    const __nv_bfloat16* Al = g_Xlo + m0 * NI;
    const __nv_bfloat16* Bh = g_W0hi + o0 * NI;
    const __nv_bfloat16* Bl = g_W0lo + o0 * NI;
    GEMM_K256_RING(Ah, Al, Bh, Bl);

    const int g = lane >> 2, t2 = (lane & 3) * 2;
#pragma unroll
    for (int mf = 0; mf < 2; mf++) {
        const int q = m0 + warp_m + mf * 16 + g;
#pragma unroll
        for (int nf = 0; nf < 4; nf++) {
            const int o = o0 + warp_n + nf * 8 + t2;
            const float* c = acc[mf][nf];
            *(float2*)(out + q * 256 + o)       = make_float2(c[0], c[1]);
            *(float2*)(out + (q + 8) * 256 + o) = make_float2(c[2], c[3]);
        }
    }
}

// ---------------------------------------------------------------------------
// GEMM1: P[q, kcat] = mask * gate * (X @ [A2;S2]^T)
// grid 2112: 2 regions x causal tiles (128 q x 64 keys; nt <= 2mt+1).
// Epilogue: gate+split into padded smem, then coalesced 16B stores.
// ---------------------------------------------------------------------------
#define EPI_PITCH 72    // bf16 elems per row (144 B) -> conflict-free banks

__global__ void __launch_bounds__(256, 3) k_gemm1() {
    GEMM_PROLOGUE();
    int i = blockIdx.x, rg = 0;
    if (i >= 1056) { rg = 1; i -= 1056; }
    int mt = 0;                               // cum(mt) = mt*(mt+1)
    while ((mt + 1) * (mt + 2) <= i) mt++;
    const int nt = i - mt * (mt + 1);
    const int m0 = mt * 128;
    const int keybase = nt * 64;

    const __nv_bfloat16* Ah = g_Xhi + m0 * NI;
    const __nv_bfloat16* Al = g_Xlo + m0 * NI;
    const __nv_bfloat16* Bh = g_Khi + (rg * ROWS + keybase) * NI;
    const __nv_bfloat16* Bl = g_Klo + (rg * ROWS + keybase) * NI;
    GEMM_K256_RING(Ah, Al, Bh, Bl);

    // Epilogue: gate+mask+split into smem (mainloop smem dead after sync).
    __syncthreads();
    __nv_bfloat16* sH = (__nv_bfloat16*)smem;                         // 128 x 72
    __nv_bfloat16* sL = (__nv_bfloat16*)(smem + 128 * EPI_PITCH * 2); // +18432 B
    const int g = lane >> 2, t2 = (lane & 3) * 2;
#pragma unroll
    for (int mf = 0; mf < 2; mf++) {
        const int rloc = warp_m + mf * 16 + g;          // local row; +8 same b
        const int q0 = m0 + rloc;
        const int s0 = q0 >> 3, b = q0 & 7;
#pragma unroll
        for (int nf = 0; nf < 4; nf++) {
            const int cl = warp_n + nf * 8 + t2;        // local col (even)
            const int col = keybase + cl;
            const int t = col >> 3;
            const float gv = rg ? -g_ss[t * 8 + b] : g_sa[t * 8 + b];
            const float sc0 = (t <= s0) ? gv : 0.f;
            const float sc1 = (t <= s0 + 1) ? gv : 0.f;
            const float* c = acc[mf][nf];

            float v0 = c[0] * sc0, v1 = c[1] * sc0;
            __nv_bfloat16 h0 = __float2bfloat16(v0), h1 = __float2bfloat16(v1);
            *(__nv_bfloat162*)(sH + rloc * EPI_PITCH + cl) = __nv_bfloat162(h0, h1);
            *(__nv_bfloat162*)(sL + rloc * EPI_PITCH + cl) = __nv_bfloat162(
                __float2bfloat16(v0 - __bfloat162float(h0)),
                __float2bfloat16(v1 - __bfloat162float(h1)));

            float w0 = c[2] * sc1, w1 = c[3] * sc1;
            __nv_bfloat16 k0 = __float2bfloat16(w0), k1 = __float2bfloat16(w1);
            *(__nv_bfloat162*)(sH + (rloc + 8) * EPI_PITCH + cl) = __nv_bfloat162(k0, k1);
            *(__nv_bfloat162*)(sL + (rloc + 8) * EPI_PITCH + cl) = __nv_bfloat162(
                __float2bfloat16(w0 - __bfloat162float(k0)),
                __float2bfloat16(w1 - __bfloat162float(k1)));
        }
    }
    __syncthreads();

    // Coalesced stores: 128 rows x 64 cols, 8 chunks of 16B per row.
    const int gbase = rg * ROWS + keybase;
#pragma unroll
    for (int it = tid; it < 1024; it += 256) {
        const int row = it >> 3;
        const int c8 = (it & 7) * 8;
        uint4 vh = *(uint4*)(sH + row * EPI_PITCH + c8);
        uint4 vl = *(uint4*)(sL + row * EPI_PITCH + c8);
        *(uint4*)(g_Phi + (size_t)(m0 + row) * KCAT + gbase + c8) = vh;
        *(uint4*)(g_Plo + (size_t)(m0 + row) * KCAT + gbase + c8) = vl;
    }
}

// ---------------------------------------------------------------------------
// GEMM2: out[q, o] += P[q, :] @ [A1;S1][:, o]   (split-K + f32 atomics)
// Tiles 128(q) x 64(o). Logical k in [0, 256*(mt+1)) maps to
// phys [0, half) U [4096, 4096+half). grid (32 mt, 4 ot, 8 kc).
// ---------------------------------------------------------------------------
__global__ void __launch_bounds__(256, 3) k_gemm2(float* __restrict__ out) {
    const int mt = blockIdx.x, ot = blockIdx.y, kc = blockIdx.z;
    const int nch = (mt + 4) >> 2;
    if (kc >= nch) return;
    const int klive = 256 * (mt + 1);
    const int kstart = kc * 1024;
    const int kend = (kstart + 1024 < klive) ? kstart + 1024 : klive;
    const int half = 128 * (mt + 1);
    const int m0 = mt * 128, o0 = ot * 64;
    const int nsteps = (kend - kstart) >> 5;

    GEMM_PROLOGUE();

    const __nv_bfloat16* Ah = g_Phi + (size_t)m0 * KCAT;
    const __nv_bfloat16* Al = g_Plo + (size_t)m0 * KCAT;
    const __nv_bfloat16* Bh = g_VThi + (size_t)o0 * KCAT;
    const __nv_bfloat16* Bl = g_VTlo + (size_t)o0 * KCAT;

    {
        int pk = (kstart < half) ? kstart : kstart + ROWS - half;
        load_stage(sb, Ah + pk, Al + pk, Bh + pk, Bl + pk, KCAT, KCAT, tid);
        CP_COMMIT();
        if (nsteps > 1) {
            const int lk = kstart + 32;
            pk = (lk < half) ? lk : lk + ROWS - half;
            load_stage(sb + STAGE, Ah + pk, Al + pk, Bh + pk, Bl + pk, KCAT, KCAT, tid);
        }
        CP_COMMIT();
    }
#pragma unroll 1
    for (int s = 0; s < nsteps; s++) {
        asm volatile("cp.async.wait_group 1;");
        __syncthreads();
        if (s + 2 < nsteps) {
            const int lk = kstart + (s + 2) * 32;
            const int pk = (lk < half) ? lk : lk + ROWS - half;
            load_stage(sb + ((s + 2) % 3) * STAGE, Ah + pk, Al + pk, Bh + pk, Bl + pk,
                       KCAT, KCAT, tid);
        }
        CP_COMMIT();
        compute_stage(sb + (s % 3) * STAGE, warp_m, warp_n, lane, acc);
    }

    const int g = lane >> 2, t2 = (lane & 3) * 2;
#pragma unroll
    for (int mf = 0; mf < 2; mf++) {
        const int q = m0 + warp_m + mf * 16 + g;
#pragma unroll
        for (int nf = 0; nf < 4; nf++) {
            const int o = o0 + warp_n + nf * 8 + t2;
            const float* c = acc[mf][nf];
            atomicAdd(out + q * 256 + o,           c[0]);
            atomicAdd(out + q * 256 + o + 1,       c[1]);
            atomicAdd(out + (q + 8) * 256 + o,     c[2]);
            atomicAdd(out + (q + 8) * 256 + o + 1, c[3]);
        }
    }
}

// ---------------------------------------------------------------------------
extern "C" void kernel_launch(void* const* d_in, const int* in_sizes, int n_in,
                              void* d_out, int out_size) {
    const float* x      = (const float*)d_in[0];   // (512,8,256)
    const float* slow_W = (const float*)d_in[1];   // (1026,256)
    const float* slow_b = (const float*)d_in[2];   // (1026,)
    const float* fw0    = (const float*)d_in[3];   // (256,256)
    float* out = (float*)d_out;                    // (512,8,256)

    // Unconditional every call (no static guards — harness contract).
    cudaFuncSetAttribute(k_wu_mma,   cudaFuncAttributeMaxDynamicSharedMemorySize, GEMM_SMEM);
    cudaFuncSetAttribute(k_base_mma, cudaFuncAttributeMaxDynamicSharedMemorySize, GEMM_SMEM);
    cudaFuncSetAttribute(k_gemm1,    cudaFuncAttributeMaxDynamicSharedMemorySize, GEMM_SMEM);
    cudaFuncSetAttribute(k_gemm2,    cudaFuncAttributeMaxDynamicSharedMemorySize, GEMM_SMEM);

    // k_gemm1 at launch index 3 (the profiled slot).
    k_prep    <<<5888, 256>>>(x, slow_W, fw0, slow_b);
    k_wu_mma  <<<dim3(16, 32), 256, GEMM_SMEM>>>(slow_b);
    k_base_mma<<<dim3(4, 32), 256, GEMM_SMEM>>>(out);
    k_gemm1   <<<2112, 256, GEMM_SMEM>>>();
    k_gemm2   <<<dim3(32, 4, 8), 256, GEMM_SMEM>>>(out);
}

// round 13
// speedup vs baseline: 4.8979x; 1.1945x over previous
#include <cuda_runtime.h>
#include <cuda_bf16.h>
#include <cuda_fp16.h>
#include <math.h>
#include <stdint.h>

#define ROWS 4096          // S*B = 512*8
#define KCAT 8192          // concat keys: [A (4096) | S (4096)]
#define NI 256
#define SLOW_OUTS 1026

// ---------------------------------------------------------------------------
// Scratch (device globals)
// ---------------------------------------------------------------------------
__device__ float g_sa[ROWS];
__device__ float g_ss[ROWS];

__device__ __align__(16) __nv_bfloat16 g_Xhi[ROWS * NI];
__device__ __align__(16) __nv_bfloat16 g_Xlo[ROWS * NI];
__device__ __align__(16) __nv_bfloat16 g_Whi[1024 * NI];   // slow_W rows 0..1023
__device__ __align__(16) __nv_bfloat16 g_Wlo[1024 * NI];
__device__ __align__(16) __nv_bfloat16 g_W0hi[NI * NI];    // fast_W0
__device__ __align__(16) __nv_bfloat16 g_W0lo[NI * NI];
__device__ __align__(16) __nv_bfloat16 g_Khi[KCAT * NI];   // rows: [A2 ; S2]
__device__ __align__(16) __nv_bfloat16 g_Klo[KCAT * NI];
__device__ __align__(16) __half g_VThi[NI * KCAT];         // fp16 hi of [A1;S1]^T
__device__ __align__(16) __half g_VTlo[NI * KCAT];         // fp16 lo
__device__ __align__(16) __half g_P[(size_t)ROWS * KCAT];  // fp16 P, 64 MB

// ---------------------------------------------------------------------------
// Helpers
// ---------------------------------------------------------------------------
__device__ __forceinline__ uint32_t smem_to_u32(const void* p) {
    uint32_t a;
    asm("{ .reg .u64 t; cvta.to.shared.u64 t, %1; cvt.u32.u64 %0, t; }" : "=r"(a) : "l"(p));
    return a;
}

__device__ __forceinline__ void cpa16(uint32_t s, const void* g) {
    asm volatile("cp.async.cg.shared.global [%0], [%1], 16;"
        :: "r"(s), "l"(__cvta_generic_to_global(g)));
}
#define CP_COMMIT() asm volatile("cp.async.commit_group;")

__device__ __forceinline__ void ldx4(uint32_t* r, uint32_t addr) {
    asm volatile("ldmatrix.sync.aligned.m8n8.x4.shared.b16 {%0,%1,%2,%3}, [%4];"
        : "=r"(r[0]), "=r"(r[1]), "=r"(r[2]), "=r"(r[3]) : "r"(addr));
}

__device__ __forceinline__ void mma16816(float* c, const uint32_t* a, const uint32_t* b) {
    asm volatile(
        "mma.sync.aligned.m16n8k16.row.col.f32.bf16.bf16.f32 "
        "{%0,%1,%2,%3}, {%4,%5,%6,%7}, {%8,%9}, {%0,%1,%2,%3};"
        : "+f"(c[0]), "+f"(c[1]), "+f"(c[2]), "+f"(c[3])
        : "r"(a[0]), "r"(a[1]), "r"(a[2]), "r"(a[3]), "r"(b[0]), "r"(b[1]));
}

__device__ __forceinline__ void mma16816h(float* c, const uint32_t* a, const uint32_t* b) {
    asm volatile(
        "mma.sync.aligned.m16n8k16.row.col.f32.f16.f16.f32 "
        "{%0,%1,%2,%3}, {%4,%5,%6,%7}, {%8,%9}, {%0,%1,%2,%3};"
        : "+f"(c[0]), "+f"(c[1]), "+f"(c[2]), "+f"(c[3])
        : "r"(a[0]), "r"(a[1]), "r"(a[2]), "r"(a[3]), "r"(b[0]), "r"(b[1]));
}

// bf16 path (gemm1/wu/base): CTA tile 128(M) x 64(N), K-stage 32.
// A 128x32, B 64x32 per array (64B rows, XOR-swizzled 16B segments).
// Stage 24 KB; 3-stage ring = 72 KB -> 3 CTAs/SM.
#define ROWB    64
#define OFF_AH  0
#define OFF_AL  8192
#define OFF_BH  16384
#define OFF_BL  20480
#define STAGE   24576
#define GEMM_SMEM (3 * STAGE)

#define SWZ(row, seg) (((seg) ^ (((row) >> 1) & 3)) << 4)

__device__ __forceinline__ void load_stage(uint32_t st,
    const __nv_bfloat16* Ah, const __nv_bfloat16* Al,
    const __nv_bfloat16* Bh, const __nv_bfloat16* Bl,
    int sA, int sB, int tid)
{
#pragma unroll
    for (int h = 0; h < 2; h++) {                 // A: 128 rows x 4 segs
        int c = tid + h * 256;
        int row = c >> 2, seg = c & 3;
        uint32_t d = st + row * ROWB + SWZ(row, seg);
        int go = seg * 8;
        cpa16(d + OFF_AH, Ah + row * sA + go);
        cpa16(d + OFF_AL, Al + row * sA + go);
    }
    {                                             // B: 64 rows x 4 segs
        int row = tid >> 2, seg = tid & 3;
        uint32_t d = st + row * ROWB + SWZ(row, seg);
        int go = seg * 8;
        cpa16(d + OFF_BH, Bh + row * sB + go);
        cpa16(d + OFF_BL, Bl + row * sB + go);
    }
}

// 3-term split-compensated bf16 MMA over one 32-wide K stage (32x32 warp tile).
__device__ __forceinline__ void compute_stage(uint32_t st, int warp_m, int warp_n,
                                              int lane, float acc[2][4][4])
{
    const int rowsel = lane & 15;
    const int chalf = lane >> 4;
#pragma unroll
    for (int k16 = 0; k16 < 2; k16++) {
        const int c0 = k16 * 2 + chalf;
        uint32_t ah[2][4], al[2][4];
#pragma unroll
        for (int mf = 0; mf < 2; mf++) {
            const int row = warp_m + mf * 16 + rowsel;
            uint32_t base = st + row * ROWB + SWZ(row, c0);
            ldx4(ah[mf], base + OFF_AH);
            ldx4(al[mf], base + OFF_AL);
        }
#pragma unroll
        for (int np = 0; np < 2; np++) {
            const int row = warp_n + np * 16 + rowsel;
            uint32_t base = st + row * ROWB + SWZ(row, c0);
            uint32_t rbh[4], rbl[4];
            ldx4(rbh, base + OFF_BH);
            ldx4(rbl, base + OFF_BL);
            uint32_t bh0[2] = {rbh[0], rbh[2]}, bh1[2] = {rbh[1], rbh[3]};
            uint32_t bl0[2] = {rbl[0], rbl[2]}, bl1[2] = {rbl[1], rbl[3]};
#pragma unroll
            for (int mf = 0; mf < 2; mf++) {
                mma16816(acc[mf][2 * np],     ah[mf], bh0);
                mma16816(acc[mf][2 * np + 1], ah[mf], bh1);
                mma16816(acc[mf][2 * np],     ah[mf], bl0);
                mma16816(acc[mf][2 * np + 1], ah[mf], bl1);
                mma16816(acc[mf][2 * np],     al[mf], bh0);
                mma16816(acc[mf][2 * np + 1], al[mf], bh1);
            }
        }
    }
}

#define GEMM_PROLOGUE()                                                        \
    extern __shared__ char smem[];                                             \
    const uint32_t sb = smem_to_u32(smem);                                     \
    const int tid = threadIdx.x, lane = tid & 31, wid = tid >> 5;              \
    const int warp_m = (wid >> 1) * 32, warp_n = (wid & 1) * 32;               \
    float acc[2][4][4];                                                        \
    _Pragma("unroll") for (int a_ = 0; a_ < 2; a_++)                           \
    _Pragma("unroll") for (int b_ = 0; b_ < 4; b_++)                           \
    _Pragma("unroll") for (int c_ = 0; c_ < 4; c_++) acc[a_][b_][c_] = 0.f;

// 3-stage ring over K=256 (8 stages). ORDER IS LOAD-BEARING:
// wait_group -> __syncthreads (publishes all threads' data) -> prefetch.
#define GEMM_K256_RING(Ah, Al, Bh, Bl)                                         \
    load_stage(sb, (Ah), (Al), (Bh), (Bl), NI, NI, tid); CP_COMMIT();          \
    load_stage(sb + STAGE, (Ah) + 32, (Al) + 32, (Bh) + 32, (Bl) + 32,         \
               NI, NI, tid);                                                   \
    CP_COMMIT();                                                               \
    _Pragma("unroll 1") for (int kc = 0; kc < 8; kc++) {                       \
        asm volatile("cp.async.wait_group 1;");                                \
        __syncthreads();                                                       \
        if (kc + 2 < 8) {                                                      \
            const int ko = (kc + 2) * 32;                                      \
            load_stage(sb + ((kc + 2) % 3) * STAGE, (Ah) + ko, (Al) + ko,      \
                       (Bh) + ko, (Bl) + ko, NI, NI, tid);                     \
        }                                                                      \
        CP_COMMIT();                                                           \
        compute_stage(sb + (kc % 3) * STAGE, warp_m, warp_n, lane, acc);       \
    }

// ---------------------------------------------------------------------------
// k_prep: X split, W split, W0 split, sigmoid gates.  grid 5888 x 256.
// ---------------------------------------------------------------------------
__global__ void k_prep(const float* __restrict__ x, const float* __restrict__ W,
                       const float* __restrict__ W0, const float* __restrict__ b) {
    const int blk = blockIdx.x;
    const int tid = threadIdx.x;
    if (blk < 4096) {                       // split X
        const int i = blk * 256 + tid;
        float v = x[i];
        __nv_bfloat16 h = __float2bfloat16(v);
        g_Xhi[i] = h;
        g_Xlo[i] = __float2bfloat16(v - __bfloat162float(h));
    } else if (blk < 5120) {                // split slow_W rows 0..1023
        const int i = (blk - 4096) * 256 + tid;
        float v = W[i];
        __nv_bfloat16 h = __float2bfloat16(v);
        g_Whi[i] = h;
        g_Wlo[i] = __float2bfloat16(v - __bfloat162float(h));
    } else if (blk < 5376) {                // split fast_W0
        const int i = (blk - 5120) * 256 + tid;
        float v = W0[i];
        __nv_bfloat16 h = __float2bfloat16(v);
        g_W0hi[i] = h;
        g_W0lo[i] = __float2bfloat16(v - __bfloat162float(h));
    } else {                                // gates
        const int q = (blk - 5376) * 8 + (tid >> 5);
        const int lane = tid & 31;
        const float4* xr = (const float4*)(x + q * 256);
        const float4* w1 = (const float4*)(W + 1024 * 256);
        const float4* w2 = (const float4*)(W + 1025 * 256);
        float s1 = 0.f, s2 = 0.f;
#pragma unroll
        for (int i = 0; i < 2; i++) {
            const int idx = lane + i * 32;
            float4 xv = xr[idx], wa = w1[idx], wb = w2[idx];
            s1 += xv.x * wa.x + xv.y * wa.y + xv.z * wa.z + xv.w * wa.w;
            s2 += xv.x * wb.x + xv.y * wb.y + xv.z * wb.z + xv.w * wb.w;
        }
#pragma unroll
        for (int off = 16; off; off >>= 1) {
            s1 += __shfl_xor_sync(0xFFFFFFFFu, s1, off);
            s2 += __shfl_xor_sync(0xFFFFFFFFu, s2, off);
        }
        if (lane == 0) {
            g_sa[q] = 1.f / (1.f + expf(-(s1 + b[1024])));
            g_ss[q] = 1.f / (1.f + expf(-(s2 + b[1025])));
        }
    }
}

// ---------------------------------------------------------------------------
// k_wu_mma: wu[:, 0:1024] = X @ slow_W[0:1024]^T + b   (tensor, 3-term)
// grid (16 ntile, 32 mt), tiles 128 x 64. region = ntile>>2:
//   region 0 (A1) / 2 (S1): smem-transpose -> fp16 hi/lo VT (fused trans_V)
//   region 1 (A2) / 3 (S2): split bf16 -> g_Khi/g_Klo
// ---------------------------------------------------------------------------
__global__ void __launch_bounds__(256, 3) k_wu_mma(const float* __restrict__ bias) {
    GEMM_PROLOGUE();
    const int mt = blockIdx.y, ntile = blockIdx.x;
    const int m0 = mt * 128, n0 = ntile * 64;
    const int region = ntile >> 2;

    const __nv_bfloat16* Ah = g_Xhi + m0 * NI;
    const __nv_bfloat16* Al = g_Xlo + m0 * NI;
    const __nv_bfloat16* Bh = g_Whi + n0 * NI;
    const __nv_bfloat16* Bl = g_Wlo + n0 * NI;
    GEMM_K256_RING(Ah, Al, Bh, Bl);

    const int g = lane >> 2, t2 = (lane & 3) * 2;
    if (region & 1) {
        // A2 / S2 -> split bf16 into g_K rows
#pragma unroll
        for (int mf = 0; mf < 2; mf++) {
            const int q0 = m0 + warp_m + mf * 16 + g;
#pragma unroll
            for (int nf = 0; nf < 4; nf++) {
                const int col = n0 + warp_n + nf * 8 + t2;
                const float b0 = bias[col], b1 = bias[col + 1];
                const float* c = acc[mf][nf];
                const float v0 = c[0] + b0, v1 = c[1] + b1;
                const float w0 = c[2] + b0, w1 = c[3] + b1;
                const int cc = col & 255;
                const int kr = (region == 1 ? q0 : 4096 + q0);
                __nv_bfloat16 h0 = __float2bfloat16(v0), h1 = __float2bfloat16(v1);
                *(__nv_bfloat162*)(g_Khi + kr * 256 + cc) = __nv_bfloat162(h0, h1);
                *(__nv_bfloat162*)(g_Klo + kr * 256 + cc) = __nv_bfloat162(
                    __float2bfloat16(v0 - __bfloat162float(h0)),
                    __float2bfloat16(v1 - __bfloat162float(h1)));
                __nv_bfloat16 k0 = __float2bfloat16(w0), k1 = __float2bfloat16(w1);
                *(__nv_bfloat162*)(g_Khi + (kr + 8) * 256 + cc) = __nv_bfloat162(k0, k1);
                *(__nv_bfloat162*)(g_Klo + (kr + 8) * 256 + cc) = __nv_bfloat162(
                    __float2bfloat16(w0 - __bfloat162float(k0)),
                    __float2bfloat16(w1 - __bfloat162float(k1)));
            }
        }
    } else {
        // A1 / S1 -> transposed fp16 hi/lo VT via smem (fused k_trans_V)
        __syncthreads();                      // mainloop smem now dead
        float* sT = (float*)smem;             // [64 cols][pitch 132] fp32
#pragma unroll
        for (int mf = 0; mf < 2; mf++) {
            const int rloc = warp_m + mf * 16 + g;
#pragma unroll
            for (int nf = 0; nf < 4; nf++) {
                const int cl = warp_n + nf * 8 + t2;
                const int col = n0 + cl;
                const float b0 = bias[col], b1 = bias[col + 1];
                const float* c = acc[mf][nf];
                sT[cl * 132 + rloc]           = c[0] + b0;
                sT[(cl + 1) * 132 + rloc]     = c[1] + b1;
                sT[cl * 132 + rloc + 8]       = c[2] + b0;
                sT[(cl + 1) * 132 + rloc + 8] = c[3] + b1;
            }
        }
        __syncthreads();
        const int rz = region >> 1;           // 0: A1, 1: S1
        const int o_loc = tid >> 2;           // 0..63
        const int qh = (tid & 3) * 32;        // 0,32,64,96
        const int o_glob = (ntile & 3) * 64 + o_loc;
        const float* srow = sT + o_loc * 132 + qh;
        const size_t dst = (size_t)o_glob * KCAT + rz * ROWS + m0 + qh;
#pragma unroll
        for (int j8 = 0; j8 < 4; j8++) {
            union { __half h[8]; uint4 u; } H, L;
#pragma unroll
            for (int e = 0; e < 8; e++) {
                float f = srow[j8 * 8 + e];
                __half hh = __float2half_rn(f);
                H.h[e] = hh;
                L.h[e] = __float2half_rn(f - __half2float(hh));
            }
            *(uint4*)(g_VThi + dst + j8 * 8) = H.u;
            *(uint4*)(g_VTlo + dst + j8 * 8) = L.u;
        }
    }
}

// ---------------------------------------------------------------------------
// k_base_mma: out = X @ W0^T   (tensor, 3-term). grid (4 ot, 32 mt).
// ---------------------------------------------------------------------------
__global__ void __launch_bounds__(256, 3) k_base_mma(float* __restrict__ out) {
    GEMM_PROLOGUE();
    const int mt = blockIdx.y, ot = blockIdx.x;
    const int m0 = mt * 128, o0 = ot * 64;

    const __nv_bfloat16* Ah = g_Xhi + m0 * NI;
    const __nv_bfloat16* Al = g_Xlo + m0 * NI;
    const __nv_bfloat16* Bh = g_W0hi + o0 * NI;
    const __nv_bfloat16* Bl = g_W0lo + o0 * NI;
    GEMM_K256_RING(Ah, Al, Bh, Bl);

    const int g = lane >> 2, t2 = (lane & 3) * 2;
#pragma unroll
    for (int mf = 0; mf < 2; mf++) {
        const int q = m0 + warp_m + mf * 16 + g;
#pragma unroll
        for (int nf = 0; nf < 4; nf++) {
            const int o = o0 + warp_n + nf * 8 + t2;
            const float* c = acc[mf][nf];
            *(float2*)(out + q * 256 + o)       = make_float2(c[0], c[1]);
            *(float2*)(out + (q + 8) * 256 + o) = make_float2(c[2], c[3]);
        }
    }
}

// ---------------------------------------------------------------------------
// GEMM1: P[q, kcat] = fp16( mask * gate * (X @ [A2;S2]^T) )
// grid 2112: 2 regions x causal tiles (128 q x 64 keys; nt <= 2mt+1).
// ---------------------------------------------------------------------------
#define EPI_PITCH 72    // fp16 elems per row (144 B, 16B-aligned rows)

__global__ void __launch_bounds__(256, 3) k_gemm1() {
    GEMM_PROLOGUE();
    int i = blockIdx.x, rg = 0;
    if (i >= 1056) { rg = 1; i -= 1056; }
    int mt = 0;                               // cum(mt) = mt*(mt+1)
    while ((mt + 1) * (mt + 2) <= i) mt++;
    const int nt = i - mt * (mt + 1);
    const int m0 = mt * 128;
    const int keybase = nt * 64;

    const __nv_bfloat16* Ah = g_Xhi + m0 * NI;
    const __nv_bfloat16* Al = g_Xlo + m0 * NI;
    const __nv_bfloat16* Bh = g_Khi + (rg * ROWS + keybase) * NI;
    const __nv_bfloat16* Bl = g_Klo + (rg * ROWS + keybase) * NI;
    GEMM_K256_RING(Ah, Al, Bh, Bl);

    // Epilogue: gate+mask -> fp16 into smem, then coalesced 16B stores.
    __syncthreads();
    __half* sH = (__half*)smem;               // 128 x 72 fp16
    const int g = lane >> 2, t2 = (lane & 3) * 2;
#pragma unroll
    for (int mf = 0; mf < 2; mf++) {
        const int rloc = warp_m + mf * 16 + g;          // local row; +8 same b
        const int q0 = m0 + rloc;
        const int s0 = q0 >> 3, b = q0 & 7;
#pragma unroll
        for (int nf = 0; nf < 4; nf++) {
            const int cl = warp_n + nf * 8 + t2;        // local col (even)
            const int col = keybase + cl;
            const int t = col >> 3;
            const float gv = rg ? -g_ss[t * 8 + b] : g_sa[t * 8 + b];
            const float sc0 = (t <= s0) ? gv : 0.f;
            const float sc1 = (t <= s0 + 1) ? gv : 0.f;
            const float* c = acc[mf][nf];
            *(__half2*)(sH + rloc * EPI_PITCH + cl) =
                __floats2half2_rn(c[0] * sc0, c[1] * sc0);
            *(__half2*)(sH + (rloc + 8) * EPI_PITCH + cl) =
                __floats2half2_rn(c[2] * sc1, c[3] * sc1);
        }
    }
    __syncthreads();

    // Coalesced stores: 128 rows x 64 cols fp16, 8 chunks of 16B per row.
    const int gbase = rg * ROWS + keybase;
#pragma unroll
    for (int it = tid; it < 1024; it += 256) {
        const int row = it >> 3;
        const int c8 = (it & 7) * 8;
        uint4 v = *(uint4*)(sH + row * EPI_PITCH + c8);
        *(uint4*)(g_P + (size_t)(m0 + row) * KCAT + gbase + c8) = v;
    }
}

// ---------------------------------------------------------------------------
// GEMM2 (fp16, 2-term): out[q,o] += P @ [Vhi + Vlo]
// A = P (fp16 single), B = VT hi/lo fp16. Stage 16 KB, 3-ring 48 KB.
// Tiles 128(q) x 64(o), split-K + f32 atomics.
// ---------------------------------------------------------------------------
#define OFF2_A  0
#define OFF2_BH 8192
#define OFF2_BL 12288
#define STAGE2  16384
#define GEMM2_SMEM (3 * STAGE2)

__device__ __forceinline__ void load_stage2(uint32_t st,
    const __half* A, const __half* Bh, const __half* Bl, int tid)
{
#pragma unroll
    for (int h = 0; h < 2; h++) {                 // A: 128 rows x 4 segs
        int c = tid + h * 256;
        int row = c >> 2, seg = c & 3;
        cpa16(st + OFF2_A + row * ROWB + SWZ(row, seg), A + row * KCAT + seg * 8);
    }
    {                                             // B: 64 rows x 4 segs
        int row = tid >> 2, seg = tid & 3;
        uint32_t d = st + row * ROWB + SWZ(row, seg);
        int go = seg * 8;
        cpa16(d + OFF2_BH, Bh + row * KCAT + go);
        cpa16(d + OFF2_BL, Bl + row * KCAT + go);
    }
}

__device__ __forceinline__ void compute_stage2(uint32_t st, int warp_m, int warp_n,
                                               int lane, float acc[2][4][4])
{
    const int rowsel = lane & 15;
    const int chalf = lane >> 4;
#pragma unroll
    for (int k16 = 0; k16 < 2; k16++) {
        const int c0 = k16 * 2 + chalf;
        uint32_t ah[2][4];
#pragma unroll
        for (int mf = 0; mf < 2; mf++) {
            const int row = warp_m + mf * 16 + rowsel;
            ldx4(ah[mf], st + OFF2_A + row * ROWB + SWZ(row, c0));
        }
#pragma unroll
        for (int np = 0; np < 2; np++) {
            const int row = warp_n + np * 16 + rowsel;
            uint32_t base = st + row * ROWB + SWZ(row, c0);
            uint32_t rbh[4], rbl[4];
            ldx4(rbh, base + OFF2_BH);
            ldx4(rbl, base + OFF2_BL);
            uint32_t bh0[2] = {rbh[0], rbh[2]}, bh1[2] = {rbh[1], rbh[3]};
            uint32_t bl0[2] = {rbl[0], rbl[2]}, bl1[2] = {rbl[1], rbl[3]};
#pragma unroll
            for (int mf = 0; mf < 2; mf++) {
                mma16816h(acc[mf][2 * np],     ah[mf], bh0);
                mma16816h(acc[mf][2 * np + 1], ah[mf], bh1);
                mma16816h(acc[mf][2 * np],     ah[mf], bl0);
                mma16816h(acc[mf][2 * np + 1], ah[mf], bl1);
            }
        }
    }
}

__global__ void __launch_bounds__(256, 3) k_gemm2(float* __restrict__ out) {
    const int mt = blockIdx.x, ot = blockIdx.y, kc = blockIdx.z;
    const int nch = (mt + 4) >> 2;
    if (kc >= nch) return;
    const int klive = 256 * (mt + 1);
    const int kstart = kc * 1024;
    const int kend = (kstart + 1024 < klive) ? kstart + 1024 : klive;
    const int half = 128 * (mt + 1);
    const int m0 = mt * 128, o0 = ot * 64;
    const int nsteps = (kend - kstart) >> 5;

    extern __shared__ char smem[];
    const uint32_t sb = smem_to_u32(smem);
    const int tid = threadIdx.x, lane = tid & 31, wid = tid >> 5;
    const int warp_m = (wid >> 1) * 32, warp_n = (wid & 1) * 32;
    float acc[2][4][4];
#pragma unroll
    for (int a_ = 0; a_ < 2; a_++)
#pragma unroll
        for (int b_ = 0; b_ < 4; b_++)
#pragma unroll
            for (int c_ = 0; c_ < 4; c_++) acc[a_][b_][c_] = 0.f;

    const __half* A  = g_P + (size_t)m0 * KCAT;
    const __half* Bh = g_VThi + (size_t)o0 * KCAT;
    const __half* Bl = g_VTlo + (size_t)o0 * KCAT;

    {
        int pk = (kstart < half) ? kstart : kstart + ROWS - half;
        load_stage2(sb, A + pk, Bh + pk, Bl + pk, tid);
        CP_COMMIT();
        if (nsteps > 1) {
            const int lk = kstart + 32;
            pk = (lk < half) ? lk : lk + ROWS - half;
            load_stage2(sb + STAGE2, A + pk, Bh + pk, Bl + pk, tid);
        }
        CP_COMMIT();
    }
#pragma unroll 1
    for (int s = 0; s < nsteps; s++) {
        asm volatile("cp.async.wait_group 1;");
        __syncthreads();
        if (s + 2 < nsteps) {
            const int lk = kstart + (s + 2) * 32;
            const int pk = (lk < half) ? lk : lk + ROWS - half;
            load_stage2(sb + ((s + 2) % 3) * STAGE2, A + pk, Bh + pk, Bl + pk, tid);
        }
        CP_COMMIT();
        compute_stage2(sb + (s % 3) * STAGE2, warp_m, warp_n, lane, acc);
    }

    const int g = lane >> 2, t2 = (lane & 3) * 2;
#pragma unroll
    for (int mf = 0; mf < 2; mf++) {
        const int q = m0 + warp_m + mf * 16 + g;
#pragma unroll
        for (int nf = 0; nf < 4; nf++) {
            const int o = o0 + warp_n + nf * 8 + t2;
            const float* c = acc[mf][nf];
            atomicAdd(out + q * 256 + o,           c[0]);
            atomicAdd(out + q * 256 + o + 1,       c[1]);
            atomicAdd(out + (q + 8) * 256 + o,     c[2]);
            atomicAdd(out + (q + 8) * 256 + o + 1, c[3]);
        }
    }
}

// ---------------------------------------------------------------------------
extern "C" void kernel_launch(void* const* d_in, const int* in_sizes, int n_in,
                              void* d_out, int out_size) {
    const float* x      = (const float*)d_in[0];   // (512,8,256)
    const float* slow_W = (const float*)d_in[1];   // (1026,256)
    const float* slow_b = (const float*)d_in[2];   // (1026,)
    const float* fw0    = (const float*)d_in[3];   // (256,256)
    float* out = (float*)d_out;                    // (512,8,256)

    // Unconditional every call (no static guards — harness contract).
    cudaFuncSetAttribute(k_wu_mma,   cudaFuncAttributeMaxDynamicSharedMemorySize, GEMM_SMEM);
    cudaFuncSetAttribute(k_base_mma, cudaFuncAttributeMaxDynamicSharedMemorySize, GEMM_SMEM);
    cudaFuncSetAttribute(k_gemm1,    cudaFuncAttributeMaxDynamicSharedMemorySize, GEMM_SMEM);
    cudaFuncSetAttribute(k_gemm2,    cudaFuncAttributeMaxDynamicSharedMemorySize, GEMM2_SMEM);

    // k_gemm1 at launch index 3 (the profiled slot).
    k_prep    <<<5888, 256>>>(x, slow_W, fw0, slow_b);
    k_wu_mma  <<<dim3(16, 32), 256, GEMM_SMEM>>>(slow_b);
    k_base_mma<<<dim3(4, 32), 256, GEMM_SMEM>>>(out);
    k_gemm1   <<<2112, 256, GEMM_SMEM>>>();
    k_gemm2   <<<dim3(32, 4, 8), 256, GEMM2_SMEM>>>(out);
}

// round 14
// speedup vs baseline: 6.4234x; 1.3115x over previous
#include <cuda_runtime.h>
#include <cuda_fp16.h>
#include <math.h>
#include <stdint.h>

#define ROWS 4096          // S*B = 512*8
#define KCAT 8192          // concat keys: [A (4096) | S (4096)]
#define NI 256
#define SLOW_OUTS 1026

// ---------------------------------------------------------------------------
// Scratch (device globals) — all fp16 operand storage
// ---------------------------------------------------------------------------
__device__ float g_sa[ROWS];
__device__ float g_ss[ROWS];

__device__ __align__(16) __half g_Xh[ROWS * NI];
__device__ __align__(16) __half g_Xl[ROWS * NI];
__device__ __align__(16) __half g_Wh[1024 * NI];     // slow_W rows 0..1023
__device__ __align__(16) __half g_Wl[1024 * NI];
__device__ __align__(16) __half g_W0h[NI * NI];      // fast_W0
__device__ __align__(16) __half g_W0l[NI * NI];
__device__ __align__(16) __half g_K[KCAT * NI];      // [A2 ; S2], single fp16
__device__ __align__(16) __half g_VT[NI * KCAT];     // [A1;S1]^T, single fp16
__device__ __align__(16) __half g_P[(size_t)ROWS * KCAT];  // fp16 P, 64 MB

// ---------------------------------------------------------------------------
// Helpers
// ---------------------------------------------------------------------------
__device__ __forceinline__ uint32_t smem_to_u32(const void* p) {
    uint32_t a;
    asm("{ .reg .u64 t; cvta.to.shared.u64 t, %1; cvt.u32.u64 %0, t; }" : "=r"(a) : "l"(p));
    return a;
}

__device__ __forceinline__ void cpa16(uint32_t s, const void* g) {
    asm volatile("cp.async.cg.shared.global [%0], [%1], 16;"
        :: "r"(s), "l"(__cvta_generic_to_global(g)));
}
#define CP_COMMIT() asm volatile("cp.async.commit_group;")

__device__ __forceinline__ void ldx4(uint32_t* r, uint32_t addr) {
    asm volatile("ldmatrix.sync.aligned.m8n8.x4.shared.b16 {%0,%1,%2,%3}, [%4];"
        : "=r"(r[0]), "=r"(r[1]), "=r"(r[2]), "=r"(r[3]) : "r"(addr));
}

__device__ __forceinline__ void mmah(float* c, const uint32_t* a, const uint32_t* b) {
    asm volatile(
        "mma.sync.aligned.m16n8k16.row.col.f32.f16.f16.f32 "
        "{%0,%1,%2,%3}, {%4,%5,%6,%7}, {%8,%9}, {%0,%1,%2,%3};"
        : "+f"(c[0]), "+f"(c[1]), "+f"(c[2]), "+f"(c[3])
        : "r"(a[0]), "r"(a[1]), "r"(a[2]), "r"(a[3]), "r"(b[0]), "r"(b[1]));
}

// CTA tile 128(M) x 64(N), K-stage 32, 64B rows, XOR-swizzled 16B segments.
#define ROWB    64
#define SWZ(row, seg) (((seg) ^ (((row) >> 1) & 3)) << 4)

// ---- 3-term path (wu/base): A hi/lo + B hi/lo, stage 24 KB ----
#define OFF_AH  0
#define OFF_AL  8192
#define OFF_BH  16384
#define OFF_BL  20480
#define STAGE   24576
#define GEMM_SMEM (3 * STAGE)

__device__ __forceinline__ void load_stage(uint32_t st,
    const __half* Ah, const __half* Al,
    const __half* Bh, const __half* Bl, int tid)
{
#pragma unroll
    for (int h = 0; h < 2; h++) {                 // A: 128 rows x 4 segs
        int c = tid + h * 256;
        int row = c >> 2, seg = c & 3;
        uint32_t d = st + row * ROWB + SWZ(row, seg);
        int go = seg * 8;
        cpa16(d + OFF_AH, Ah + row * NI + go);
        cpa16(d + OFF_AL, Al + row * NI + go);
    }
    {                                             // B: 64 rows x 4 segs
        int row = tid >> 2, seg = tid & 3;
        uint32_t d = st + row * ROWB + SWZ(row, seg);
        int go = seg * 8;
        cpa16(d + OFF_BH, Bh + row * NI + go);
        cpa16(d + OFF_BL, Bl + row * NI + go);
    }
}

__device__ __forceinline__ void compute_stage(uint32_t st, int warp_m, int warp_n,
                                              int lane, float acc[2][4][4])
{
    const int rowsel = lane & 15;
    const int chalf = lane >> 4;
#pragma unroll
    for (int k16 = 0; k16 < 2; k16++) {
        const int c0 = k16 * 2 + chalf;
        uint32_t ah[2][4], al[2][4];
#pragma unroll
        for (int mf = 0; mf < 2; mf++) {
            const int row = warp_m + mf * 16 + rowsel;
            uint32_t base = st + row * ROWB + SWZ(row, c0);
            ldx4(ah[mf], base + OFF_AH);
            ldx4(al[mf], base + OFF_AL);
        }
#pragma unroll
        for (int np = 0; np < 2; np++) {
            const int row = warp_n + np * 16 + rowsel;
            uint32_t base = st + row * ROWB + SWZ(row, c0);
            uint32_t rbh[4], rbl[4];
            ldx4(rbh, base + OFF_BH);
            ldx4(rbl, base + OFF_BL);
            uint32_t bh0[2] = {rbh[0], rbh[2]}, bh1[2] = {rbh[1], rbh[3]};
            uint32_t bl0[2] = {rbl[0], rbl[2]}, bl1[2] = {rbl[1], rbl[3]};
#pragma unroll
            for (int mf = 0; mf < 2; mf++) {
                mmah(acc[mf][2 * np],     ah[mf], bh0);
                mmah(acc[mf][2 * np + 1], ah[mf], bh1);
                mmah(acc[mf][2 * np],     ah[mf], bl0);
                mmah(acc[mf][2 * np + 1], ah[mf], bl1);
                mmah(acc[mf][2 * np],     al[mf], bh0);
                mmah(acc[mf][2 * np + 1], al[mf], bh1);
            }
        }
    }
}

#define GEMM_PROLOGUE()                                                        \
    extern __shared__ char smem[];                                             \
    const uint32_t sb = smem_to_u32(smem);                                     \
    const int tid = threadIdx.x, lane = tid & 31, wid = tid >> 5;              \
    const int warp_m = (wid >> 1) * 32, warp_n = (wid & 1) * 32;               \
    float acc[2][4][4];                                                        \
    _Pragma("unroll") for (int a_ = 0; a_ < 2; a_++)                           \
    _Pragma("unroll") for (int b_ = 0; b_ < 4; b_++)                           \
    _Pragma("unroll") for (int c_ = 0; c_ < 4; c_++) acc[a_][b_][c_] = 0.f;

// 3-stage ring over K=256 (8 stages). ORDER IS LOAD-BEARING:
// wait_group -> __syncthreads (publishes all threads' data) -> prefetch.
#define GEMM_K256_RING(Ah, Al, Bh, Bl)                                         \
    load_stage(sb, (Ah), (Al), (Bh), (Bl), tid); CP_COMMIT();                  \
    load_stage(sb + STAGE, (Ah) + 32, (Al) + 32, (Bh) + 32, (Bl) + 32, tid);   \
    CP_COMMIT();                                                               \
    _Pragma("unroll 1") for (int kc = 0; kc < 8; kc++) {                       \
        asm volatile("cp.async.wait_group 1;");                                \
        __syncthreads();                                                       \
        if (kc + 2 < 8) {                                                      \
            const int ko = (kc + 2) * 32;                                      \
            load_stage(sb + ((kc + 2) % 3) * STAGE, (Ah) + ko, (Al) + ko,      \
                       (Bh) + ko, (Bl) + ko, tid);                             \
        }                                                                      \
        CP_COMMIT();                                                           \
        compute_stage(sb + (kc % 3) * STAGE, warp_m, warp_n, lane, acc);       \
    }

// ---------------------------------------------------------------------------
// k_prep: fp16 hi/lo splits of X, W, W0 + sigmoid gates. grid 5888 x 256.
// ---------------------------------------------------------------------------
__global__ void k_prep(const float* __restrict__ x, const float* __restrict__ W,
                       const float* __restrict__ W0, const float* __restrict__ b) {
    const int blk = blockIdx.x;
    const int tid = threadIdx.x;
    if (blk < 4096) {                       // split X
        const int i = blk * 256 + tid;
        float v = x[i];
        __half h = __float2half_rn(v);
        g_Xh[i] = h;
        g_Xl[i] = __float2half_rn(v - __half2float(h));
    } else if (blk < 5120) {                // split slow_W rows 0..1023
        const int i = (blk - 4096) * 256 + tid;
        float v = W[i];
        __half h = __float2half_rn(v);
        g_Wh[i] = h;
        g_Wl[i] = __float2half_rn(v - __half2float(h));
    } else if (blk < 5376) {                // split fast_W0
        const int i = (blk - 5120) * 256 + tid;
        float v = W0[i];
        __half h = __float2half_rn(v);
        g_W0h[i] = h;
        g_W0l[i] = __float2half_rn(v - __half2float(h));
    } else {                                // gates (fp32 exact)
        const int q = (blk - 5376) * 8 + (tid >> 5);
        const int lane = tid & 31;
        const float4* xr = (const float4*)(x + q * 256);
        const float4* w1 = (const float4*)(W + 1024 * 256);
        const float4* w2 = (const float4*)(W + 1025 * 256);
        float s1 = 0.f, s2 = 0.f;
#pragma unroll
        for (int i = 0; i < 2; i++) {
            const int idx = lane + i * 32;
            float4 xv = xr[idx], wa = w1[idx], wb = w2[idx];
            s1 += xv.x * wa.x + xv.y * wa.y + xv.z * wa.z + xv.w * wa.w;
            s2 += xv.x * wb.x + xv.y * wb.y + xv.z * wb.z + xv.w * wb.w;
        }
#pragma unroll
        for (int off = 16; off; off >>= 1) {
            s1 += __shfl_xor_sync(0xFFFFFFFFu, s1, off);
            s2 += __shfl_xor_sync(0xFFFFFFFFu, s2, off);
        }
        if (lane == 0) {
            g_sa[q] = 1.f / (1.f + expf(-(s1 + b[1024])));
            g_ss[q] = 1.f / (1.f + expf(-(s2 + b[1025])));
        }
    }
}

// ---------------------------------------------------------------------------
// k_wu_mma: wu[:, 0:1024] = X @ slow_W[0:1024]^T + b (fp16 3-term, ~2^-22)
// grid (16 ntile, 32 mt), tiles 128 x 64. region = ntile>>2:
//   region 0 (A1) / 2 (S1): smem-transpose -> single fp16 VT
//   region 1 (A2) / 3 (S2): single fp16 -> g_K
// ---------------------------------------------------------------------------
__global__ void __launch_bounds__(256, 3) k_wu_mma(const float* __restrict__ bias) {
    GEMM_PROLOGUE();
    const int mt = blockIdx.y, ntile = blockIdx.x;
    const int m0 = mt * 128, n0 = ntile * 64;
    const int region = ntile >> 2;

    GEMM_K256_RING(g_Xh + m0 * NI, g_Xl + m0 * NI, g_Wh + n0 * NI, g_Wl + n0 * NI);

    const int g = lane >> 2, t2 = (lane & 3) * 2;
    if (region & 1) {
        // A2 / S2 -> single fp16 into g_K rows
#pragma unroll
        for (int mf = 0; mf < 2; mf++) {
            const int q0 = m0 + warp_m + mf * 16 + g;
#pragma unroll
            for (int nf = 0; nf < 4; nf++) {
                const int col = n0 + warp_n + nf * 8 + t2;
                const float b0 = bias[col], b1 = bias[col + 1];
                const float* c = acc[mf][nf];
                const int cc = col & 255;
                const int kr = (region == 1 ? q0 : 4096 + q0);
                *(__half2*)(g_K + kr * 256 + cc) =
                    __floats2half2_rn(c[0] + b0, c[1] + b1);
                *(__half2*)(g_K + (kr + 8) * 256 + cc) =
                    __floats2half2_rn(c[2] + b0, c[3] + b1);
            }
        }
    } else {
        // A1 / S1 -> transposed single fp16 VT via smem (fused trans_V)
        __syncthreads();                      // mainloop smem now dead
        float* sT = (float*)smem;             // [64 cols][pitch 132] fp32
#pragma unroll
        for (int mf = 0; mf < 2; mf++) {
            const int rloc = warp_m + mf * 16 + g;
#pragma unroll
            for (int nf = 0; nf < 4; nf++) {
                const int cl = warp_n + nf * 8 + t2;
                const int col = n0 + cl;
                const float b0 = bias[col], b1 = bias[col + 1];
                const float* c = acc[mf][nf];
                sT[cl * 132 + rloc]           = c[0] + b0;
                sT[(cl + 1) * 132 + rloc]     = c[1] + b1;
                sT[cl * 132 + rloc + 8]       = c[2] + b0;
                sT[(cl + 1) * 132 + rloc + 8] = c[3] + b1;
            }
        }
        __syncthreads();
        const int rz = region >> 1;           // 0: A1, 1: S1
        const int o_loc = tid >> 2;           // 0..63
        const int qh = (tid & 3) * 32;        // 0,32,64,96
        const int o_glob = (ntile & 3) * 64 + o_loc;
        const float* srow = sT + o_loc * 132 + qh;
        const size_t dst = (size_t)o_glob * KCAT + rz * ROWS + m0 + qh;
#pragma unroll
        for (int j8 = 0; j8 < 4; j8++) {
            union { __half h[8]; uint4 u; } H;
#pragma unroll
            for (int e = 0; e < 8; e++)
                H.h[e] = __float2half_rn(srow[j8 * 8 + e]);
            *(uint4*)(g_VT + dst + j8 * 8) = H.u;
        }
    }
}

// ---------------------------------------------------------------------------
// k_base_mma: out = X @ W0^T   (fp16 3-term). grid (4 ot, 32 mt).
// ---------------------------------------------------------------------------
__global__ void __launch_bounds__(256, 3) k_base_mma(float* __restrict__ out) {
    GEMM_PROLOGUE();
    const int mt = blockIdx.y, ot = blockIdx.x;
    const int m0 = mt * 128, o0 = ot * 64;

    GEMM_K256_RING(g_Xh + m0 * NI, g_Xl + m0 * NI, g_W0h + o0 * NI, g_W0l + o0 * NI);

    const int g = lane >> 2, t2 = (lane & 3) * 2;
#pragma unroll
    for (int mf = 0; mf < 2; mf++) {
        const int q = m0 + warp_m + mf * 16 + g;
#pragma unroll
        for (int nf = 0; nf < 4; nf++) {
            const int o = o0 + warp_n + nf * 8 + t2;
            const float* c = acc[mf][nf];
            *(float2*)(out + q * 256 + o)       = make_float2(c[0], c[1]);
            *(float2*)(out + (q + 8) * 256 + o) = make_float2(c[2], c[3]);
        }
    }
}

// ---------------------------------------------------------------------------
// GEMM1 (2-term): P[q,kcat] = fp16( mask*gate * ((Xh+Xl) @ K^T) )
// A = X fp16 hi/lo, B = K single fp16. Stage 20 KB, ring 60 KB.
// grid 2112: 2 regions x causal tiles (128 q x 64 keys; nt <= 2mt+1).
// ---------------------------------------------------------------------------
#define OFF1_AH 0
#define OFF1_AL 8192
#define OFF1_B  16384
#define STAGE1  20480
#define GEMM1_SMEM (3 * STAGE1)
#define EPI_PITCH 72    // fp16 elems per row (144 B, 16B-aligned rows)

__device__ __forceinline__ void load_stage1(uint32_t st,
    const __half* Ah, const __half* Al, const __half* B, int tid)
{
#pragma unroll
    for (int h = 0; h < 2; h++) {                 // A: 128 rows x 4 segs
        int c = tid + h * 256;
        int row = c >> 2, seg = c & 3;
        uint32_t d = st + row * ROWB + SWZ(row, seg);
        int go = seg * 8;
        cpa16(d + OFF1_AH, Ah + row * NI + go);
        cpa16(d + OFF1_AL, Al + row * NI + go);
    }
    {                                             // B: 64 rows x 4 segs
        int row = tid >> 2, seg = tid & 3;
        cpa16(st + OFF1_B + row * ROWB + SWZ(row, seg), B + row * NI + seg * 8);
    }
}

__device__ __forceinline__ void compute_stage1(uint32_t st, int warp_m, int warp_n,
                                               int lane, float acc[2][4][4])
{
    const int rowsel = lane & 15;
    const int chalf = lane >> 4;
#pragma unroll
    for (int k16 = 0; k16 < 2; k16++) {
        const int c0 = k16 * 2 + chalf;
        uint32_t ah[2][4], al[2][4];
#pragma unroll
        for (int mf = 0; mf < 2; mf++) {
            const int row = warp_m + mf * 16 + rowsel;
            uint32_t base = st + row * ROWB + SWZ(row, c0);
            ldx4(ah[mf], base + OFF1_AH);
            ldx4(al[mf], base + OFF1_AL);
        }
#pragma unroll
        for (int np = 0; np < 2; np++) {
            const int row = warp_n + np * 16 + rowsel;
            uint32_t rb[4];
            ldx4(rb, st + OFF1_B + row * ROWB + SWZ(row, c0));
            uint32_t b0[2] = {rb[0], rb[2]}, b1[2] = {rb[1], rb[3]};
#pragma unroll
            for (int mf = 0; mf < 2; mf++) {
                mmah(acc[mf][2 * np],     ah[mf], b0);
                mmah(acc[mf][2 * np + 1], ah[mf], b1);
                mmah(acc[mf][2 * np],     al[mf], b0);
                mmah(acc[mf][2 * np + 1], al[mf], b1);
            }
        }
    }
}

__global__ void __launch_bounds__(256, 3) k_gemm1() {
    GEMM_PROLOGUE();
    int i = blockIdx.x, rg = 0;
    if (i >= 1056) { rg = 1; i -= 1056; }
    int mt = 0;                               // cum(mt) = mt*(mt+1)
    while ((mt + 1) * (mt + 2) <= i) mt++;
    const int nt = i - mt * (mt + 1);
    const int m0 = mt * 128;
    const int keybase = nt * 64;

    const __half* Ah = g_Xh + m0 * NI;
    const __half* Al = g_Xl + m0 * NI;
    const __half* B  = g_K + (rg * ROWS + keybase) * NI;

    load_stage1(sb, Ah, Al, B, tid); CP_COMMIT();
    load_stage1(sb + STAGE1, Ah + 32, Al + 32, B + 32, tid); CP_COMMIT();
#pragma unroll 1
    for (int kc = 0; kc < 8; kc++) {
        asm volatile("cp.async.wait_group 1;");
        __syncthreads();
        if (kc + 2 < 8) {
            const int ko = (kc + 2) * 32;
            load_stage1(sb + ((kc + 2) % 3) * STAGE1, Ah + ko, Al + ko, B + ko, tid);
        }
        CP_COMMIT();
        compute_stage1(sb + (kc % 3) * STAGE1, warp_m, warp_n, lane, acc);
    }

    // Epilogue: gate+mask -> fp16 into smem, then coalesced 16B stores.
    __syncthreads();
    __half* sH = (__half*)smem;               // 128 x 72 fp16
    const int g = lane >> 2, t2 = (lane & 3) * 2;
#pragma unroll
    for (int mf = 0; mf < 2; mf++) {
        const int rloc = warp_m + mf * 16 + g;          // local row; +8 same b
        const int q0 = m0 + rloc;
        const int s0 = q0 >> 3, b = q0 & 7;
#pragma unroll
        for (int nf = 0; nf < 4; nf++) {
            const int cl = warp_n + nf * 8 + t2;        // local col (even)
            const int col = keybase + cl;
            const int t = col >> 3;
            const float gv = rg ? -g_ss[t * 8 + b] : g_sa[t * 8 + b];
            const float sc0 = (t <= s0) ? gv : 0.f;
            const float sc1 = (t <= s0 + 1) ? gv : 0.f;
            const float* c = acc[mf][nf];
            *(__half2*)(sH + rloc * EPI_PITCH + cl) =
                __floats2half2_rn(c[0] * sc0, c[1] * sc0);
            *(__half2*)(sH + (rloc + 8) * EPI_PITCH + cl) =
                __floats2half2_rn(c[2] * sc1, c[3] * sc1);
        }
    }
    __syncthreads();

    const int gbase = rg * ROWS + keybase;
#pragma unroll
    for (int it = tid; it < 1024; it += 256) {
        const int row = it >> 3;
        const int c8 = (it & 7) * 8;
        uint4 v = *(uint4*)(sH + row * EPI_PITCH + c8);
        *(uint4*)(g_P + (size_t)(m0 + row) * KCAT + gbase + c8) = v;
    }
}

// ---------------------------------------------------------------------------
// GEMM2 (1-term fp16): out[q,o] += P @ VT^T. Stage 12 KB, ring 36 KB.
// Tiles 128(q) x 64(o), split-K + f32 atomics.
// ---------------------------------------------------------------------------
#define OFF2_A  0
#define OFF2_B  8192
#define STAGE2  12288
#define GEMM2_SMEM (3 * STAGE2)

__device__ __forceinline__ void load_stage2(uint32_t st,
    const __half* A, const __half* B, int tid)
{
#pragma unroll
    for (int h = 0; h < 2; h++) {                 // A: 128 rows x 4 segs
        int c = tid + h * 256;
        int row = c >> 2, seg = c & 3;
        cpa16(st + OFF2_A + row * ROWB + SWZ(row, seg), A + row * KCAT + seg * 8);
    }
    {                                             // B: 64 rows x 4 segs
        int row = tid >> 2, seg = tid & 3;
        cpa16(st + OFF2_B + row * ROWB + SWZ(row, seg), B + row * KCAT + seg * 8);
    }
}

__device__ __forceinline__ void compute_stage2(uint32_t st, int warp_m, int warp_n,
                                               int lane, float acc[2][4][4])
{
    const int rowsel = lane & 15;
    const int chalf = lane >> 4;
#pragma unroll
    for (int k16 = 0; k16 < 2; k16++) {
        const int c0 = k16 * 2 + chalf;
        uint32_t ah[2][4];
#pragma unroll
        for (int mf = 0; mf < 2; mf++) {
            const int row = warp_m + mf * 16 + rowsel;
            ldx4(ah[mf], st + OFF2_A + row * ROWB + SWZ(row, c0));
        }
#pragma unroll
        for (int np = 0; np < 2; np++) {
            const int row = warp_n + np * 16 + rowsel;
            uint32_t rb[4];
            ldx4(rb, st + OFF2_B + row * ROWB + SWZ(row, c0));
            uint32_t b0[2] = {rb[0], rb[2]}, b1[2] = {rb[1], rb[3]};
#pragma unroll
            for (int mf = 0; mf < 2; mf++) {
                mmah(acc[mf][2 * np],     ah[mf], b0);
                mmah(acc[mf][2 * np + 1], ah[mf], b1);
            }
        }
    }
}

__global__ void __launch_bounds__(256, 3) k_gemm2(float* __restrict__ out) {
    const int mt = blockIdx.x, ot = blockIdx.y, kc = blockIdx.z;
    const int nch = (mt + 4) >> 2;
    if (kc >= nch) return;
    const int klive = 256 * (mt + 1);
    const int kstart = kc * 1024;
    const int kend = (kstart + 1024 < klive) ? kstart + 1024 : klive;
    const int half = 128 * (mt + 1);
    const int m0 = mt * 128, o0 = ot * 64;
    const int nsteps = (kend - kstart) >> 5;

    GEMM_PROLOGUE();

    const __half* A = g_P + (size_t)m0 * KCAT;
    const __half* B = g_VT + (size_t)o0 * KCAT;

    {
        int pk = (kstart < half) ? kstart : kstart + ROWS - half;
        load_stage2(sb, A + pk, B + pk, tid);
        CP_COMMIT();
        if (nsteps > 1) {
            const int lk = kstart + 32;
            pk = (lk < half) ? lk : lk + ROWS - half;
            load_stage2(sb + STAGE2, A + pk, B + pk, tid);
        }
        CP_COMMIT();
    }
#pragma unroll 1
    for (int s = 0; s < nsteps; s++) {
        asm volatile("cp.async.wait_group 1;");
        __syncthreads();
        if (s + 2 < nsteps) {
            const int lk = kstart + (s + 2) * 32;
            const int pk = (lk < half) ? lk : lk + ROWS - half;
            load_stage2(sb + ((s + 2) % 3) * STAGE2, A + pk, B + pk, tid);
        }
        CP_COMMIT();
        compute_stage2(sb + (s % 3) * STAGE2, warp_m, warp_n, lane, acc);
    }

    const int g = lane >> 2, t2 = (lane & 3) * 2;
#pragma unroll
    for (int mf = 0; mf < 2; mf++) {
        const int q = m0 + warp_m + mf * 16 + g;
#pragma unroll
        for (int nf = 0; nf < 4; nf++) {
            const int o = o0 + warp_n + nf * 8 + t2;
            const float* c = acc[mf][nf];
            atomicAdd(out + q * 256 + o,           c[0]);
            atomicAdd(out + q * 256 + o + 1,       c[1]);
            atomicAdd(out + (q + 8) * 256 + o,     c[2]);
            atomicAdd(out + (q + 8) * 256 + o + 1, c[3]);
        }
    }
}

// ---------------------------------------------------------------------------
extern "C" void kernel_launch(void* const* d_in, const int* in_sizes, int n_in,
                              void* d_out, int out_size) {
    const float* x      = (const float*)d_in[0];   // (512,8,256)
    const float* slow_W = (const float*)d_in[1];   // (1026,256)
    const float* slow_b = (const float*)d_in[2];   // (1026,)
    const float* fw0    = (const float*)d_in[3];   // (256,256)
    float* out = (float*)d_out;                    // (512,8,256)

    // Unconditional every call (no static guards — harness contract).
    cudaFuncSetAttribute(k_wu_mma,   cudaFuncAttributeMaxDynamicSharedMemorySize, GEMM_SMEM);
    cudaFuncSetAttribute(k_base_mma, cudaFuncAttributeMaxDynamicSharedMemorySize, GEMM_SMEM);
    cudaFuncSetAttribute(k_gemm1,    cudaFuncAttributeMaxDynamicSharedMemorySize, GEMM1_SMEM);
    cudaFuncSetAttribute(k_gemm2,    cudaFuncAttributeMaxDynamicSharedMemorySize, GEMM2_SMEM);

    // k_gemm1 at launch index 3 (the profiled slot).
    k_prep    <<<5888, 256>>>(x, slow_W, fw0, slow_b);
    k_wu_mma  <<<dim3(16, 32), 256, GEMM_SMEM>>>(slow_b);
    k_base_mma<<<dim3(4, 32), 256, GEMM_SMEM>>>(out);
    k_gemm1   <<<2112, 256, GEMM1_SMEM>>>();
    k_gemm2   <<<dim3(32, 4, 8), 256, GEMM2_SMEM>>>(out);
}

// round 15
// speedup vs baseline: 8.0076x; 1.2466x over previous
#include <cuda_runtime.h>
#include <cuda_fp16.h>
#include <math.h>
#include <stdint.h>

#define ROWS 4096          // S*B = 512*8
#define KCAT 8192          // concat keys: [A (4096) | S (4096)]
#define NI 256
#define SLOW_OUTS 1026

// ---------------------------------------------------------------------------
// Scratch (device globals) — fp16 operand storage
// ---------------------------------------------------------------------------
__device__ float g_sa[ROWS];
__device__ float g_ss[ROWS];

__device__ __align__(16) __half g_Xh[ROWS * NI];     // X single fp16
__device__ __align__(16) __half g_Wh[1024 * NI];     // slow_W rows 0..1023 hi
__device__ __align__(16) __half g_Wl[1024 * NI];     // lo
__device__ __align__(16) __half g_W0h[NI * NI];      // fast_W0 hi
__device__ __align__(16) __half g_W0l[NI * NI];      // lo
__device__ __align__(16) __half g_K[KCAT * NI];      // [A2 ; S2], single fp16
__device__ __align__(16) __half g_VT[NI * KCAT];     // [A1;S1]^T, single fp16
__device__ __align__(16) __half g_P[(size_t)ROWS * KCAT];  // fp16 P, 64 MB

// ---------------------------------------------------------------------------
// Helpers
// ---------------------------------------------------------------------------
__device__ __forceinline__ uint32_t smem_to_u32(const void* p) {
    uint32_t a;
    asm("{ .reg .u64 t; cvta.to.shared.u64 t, %1; cvt.u32.u64 %0, t; }" : "=r"(a) : "l"(p));
    return a;
}

__device__ __forceinline__ void cpa16(uint32_t s, const void* g) {
    asm volatile("cp.async.cg.shared.global [%0], [%1], 16;"
        :: "r"(s), "l"(__cvta_generic_to_global(g)));
}
#define CP_COMMIT() asm volatile("cp.async.commit_group;")

__device__ __forceinline__ void ldx4(uint32_t* r, uint32_t addr) {
    asm volatile("ldmatrix.sync.aligned.m8n8.x4.shared.b16 {%0,%1,%2,%3}, [%4];"
        : "=r"(r[0]), "=r"(r[1]), "=r"(r[2]), "=r"(r[3]) : "r"(addr));
}

__device__ __forceinline__ void mmah(float* c, const uint32_t* a, const uint32_t* b) {
    asm volatile(
        "mma.sync.aligned.m16n8k16.row.col.f32.f16.f16.f32 "
        "{%0,%1,%2,%3}, {%4,%5,%6,%7}, {%8,%9}, {%0,%1,%2,%3};"
        : "+f"(c[0]), "+f"(c[1]), "+f"(c[2]), "+f"(c[3])
        : "r"(a[0]), "r"(a[1]), "r"(a[2]), "r"(a[3]), "r"(b[0]), "r"(b[1]));
}

// CTA tile 128(M) x 64(N), K-stage 32, 64B rows, XOR-swizzled 16B segments:
// phys_seg = seg ^ ((row>>1)&3)  -> conflict-free ldmatrix / STS.128.
#define ROWB    64
#define SWZ(row, seg) (((seg) ^ (((row) >> 1) & 3)) << 4)

// ---- 2-term layout (wu/base): A single (128r), B hi/lo (64r each), 16 KB ----
#define O2T_A   0
#define O2T_BH  8192
#define O2T_BL  12288
#define STAGE_2T 16384
#define SMEM_2T (3 * STAGE_2T)

// ---- 1-term layout (gemm1/gemm2): A single (128r), B single (64r), 12 KB ----
#define O1T_A   0
#define O1T_B   8192
#define STAGE_1T 12288
#define SMEM_1T (3 * STAGE_1T)

__device__ __forceinline__ void load_stage_2t(uint32_t st,
    const __half* A, const __half* Bh, const __half* Bl, int tid)
{
#pragma unroll
    for (int h = 0; h < 2; h++) {                 // A: 128 rows x 4 segs
        int c = tid + h * 256;
        int row = c >> 2, seg = c & 3;
        cpa16(st + O2T_A + row * ROWB + SWZ(row, seg), A + row * NI + seg * 8);
    }
    {                                             // B: 64 rows x 4 segs
        int row = tid >> 2, seg = tid & 3;
        uint32_t d = st + row * ROWB + SWZ(row, seg);
        int go = seg * 8;
        cpa16(d + O2T_BH, Bh + row * NI + go);
        cpa16(d + O2T_BL, Bl + row * NI + go);
    }
}

__device__ __forceinline__ void load_stage_1t(uint32_t st,
    const __half* A, const __half* B, int sA, int sB, int tid)
{
#pragma unroll
    for (int h = 0; h < 2; h++) {                 // A: 128 rows x 4 segs
        int c = tid + h * 256;
        int row = c >> 2, seg = c & 3;
        cpa16(st + O1T_A + row * ROWB + SWZ(row, seg), A + row * sA + seg * 8);
    }
    {                                             // B: 64 rows x 4 segs
        int row = tid >> 2, seg = tid & 3;
        cpa16(st + O1T_B + row * ROWB + SWZ(row, seg), B + row * sB + seg * 8);
    }
}

// 2-term: acc += A*(Bh) + A*(Bl). Warp tile 32x32.
__device__ __forceinline__ void compute_stage_2t(uint32_t st, int warp_m, int warp_n,
                                                 int lane, float acc[2][4][4])
{
    const int rowsel = lane & 15;
    const int chalf = lane >> 4;
#pragma unroll
    for (int k16 = 0; k16 < 2; k16++) {
        const int c0 = k16 * 2 + chalf;
        uint32_t a[2][4];
#pragma unroll
        for (int mf = 0; mf < 2; mf++) {
            const int row = warp_m + mf * 16 + rowsel;
            ldx4(a[mf], st + O2T_A + row * ROWB + SWZ(row, c0));
        }
#pragma unroll
        for (int np = 0; np < 2; np++) {
            const int row = warp_n + np * 16 + rowsel;
            uint32_t base = st + row * ROWB + SWZ(row, c0);
            uint32_t rbh[4], rbl[4];
            ldx4(rbh, base + O2T_BH);
            ldx4(rbl, base + O2T_BL);
            uint32_t bh0[2] = {rbh[0], rbh[2]}, bh1[2] = {rbh[1], rbh[3]};
            uint32_t bl0[2] = {rbl[0], rbl[2]}, bl1[2] = {rbl[1], rbl[3]};
#pragma unroll
            for (int mf = 0; mf < 2; mf++) {
                mmah(acc[mf][2 * np],     a[mf], bh0);
                mmah(acc[mf][2 * np + 1], a[mf], bh1);
                mmah(acc[mf][2 * np],     a[mf], bl0);
                mmah(acc[mf][2 * np + 1], a[mf], bl1);
            }
        }
    }
}

// 1-term: acc += A*B.
__device__ __forceinline__ void compute_stage_1t(uint32_t st, int warp_m, int warp_n,
                                                 int lane, float acc[2][4][4])
{
    const int rowsel = lane & 15;
    const int chalf = lane >> 4;
#pragma unroll
    for (int k16 = 0; k16 < 2; k16++) {
        const int c0 = k16 * 2 + chalf;
        uint32_t a[2][4];
#pragma unroll
        for (int mf = 0; mf < 2; mf++) {
            const int row = warp_m + mf * 16 + rowsel;
            ldx4(a[mf], st + O1T_A + row * ROWB + SWZ(row, c0));
        }
#pragma unroll
        for (int np = 0; np < 2; np++) {
            const int row = warp_n + np * 16 + rowsel;
            uint32_t rb[4];
            ldx4(rb, st + O1T_B + row * ROWB + SWZ(row, c0));
            uint32_t b0[2] = {rb[0], rb[2]}, b1[2] = {rb[1], rb[3]};
#pragma unroll
            for (int mf = 0; mf < 2; mf++) {
                mmah(acc[mf][2 * np],     a[mf], b0);
                mmah(acc[mf][2 * np + 1], a[mf], b1);
            }
        }
    }
}

#define GEMM_PROLOGUE()                                                        \
    extern __shared__ char smem[];                                             \
    const uint32_t sb = smem_to_u32(smem);                                     \
    const int tid = threadIdx.x, lane = tid & 31, wid = tid >> 5;              \
    const int warp_m = (wid >> 1) * 32, warp_n = (wid & 1) * 32;               \
    float acc[2][4][4];                                                        \
    _Pragma("unroll") for (int a_ = 0; a_ < 2; a_++)                           \
    _Pragma("unroll") for (int b_ = 0; b_ < 4; b_++)                           \
    _Pragma("unroll") for (int c_ = 0; c_ < 4; c_++) acc[a_][b_][c_] = 0.f;

// 3-stage rings, K=256 (8 stages). ORDER IS LOAD-BEARING:
// wait_group -> __syncthreads (publishes all threads' data) -> prefetch.
#define RING_2T(A, Bh, Bl)                                                     \
    load_stage_2t(sb, (A), (Bh), (Bl), tid); CP_COMMIT();                      \
    load_stage_2t(sb + STAGE_2T, (A) + 32, (Bh) + 32, (Bl) + 32, tid);         \
    CP_COMMIT();                                                               \
    _Pragma("unroll 1") for (int kc = 0; kc < 8; kc++) {                       \
        asm volatile("cp.async.wait_group 1;");                                \
        __syncthreads();                                                       \
        if (kc + 2 < 8) {                                                      \
            const int ko = (kc + 2) * 32;                                      \
            load_stage_2t(sb + ((kc + 2) % 3) * STAGE_2T, (A) + ko,            \
                          (Bh) + ko, (Bl) + ko, tid);                          \
        }                                                                      \
        CP_COMMIT();                                                           \
        compute_stage_2t(sb + (kc % 3) * STAGE_2T, warp_m, warp_n, lane, acc); \
    }

// ---------------------------------------------------------------------------
// k_prep: X->fp16, W/W0 hi-lo splits, sigmoid gates. grid 5888 x 256.
// ---------------------------------------------------------------------------
__global__ void k_prep(const float* __restrict__ x, const float* __restrict__ W,
                       const float* __restrict__ W0, const float* __restrict__ b) {
    const int blk = blockIdx.x;
    const int tid = threadIdx.x;
    if (blk < 4096) {                       // X -> single fp16
        const int i = blk * 256 + tid;
        g_Xh[i] = __float2half_rn(x[i]);
    } else if (blk < 5120) {                // split slow_W rows 0..1023
        const int i = (blk - 4096) * 256 + tid;
        float v = W[i];
        __half h = __float2half_rn(v);
        g_Wh[i] = h;
        g_Wl[i] = __float2half_rn(v - __half2float(h));
    } else if (blk < 5376) {                // split fast_W0
        const int i = (blk - 5120) * 256 + tid;
        float v = W0[i];
        __half h = __float2half_rn(v);
        g_W0h[i] = h;
        g_W0l[i] = __float2half_rn(v - __half2float(h));
    } else {                                // gates (fp32 exact)
        const int q = (blk - 5376) * 8 + (tid >> 5);
        const int lane = tid & 31;
        const float4* xr = (const float4*)(x + q * 256);
        const float4* w1 = (const float4*)(W + 1024 * 256);
        const float4* w2 = (const float4*)(W + 1025 * 256);
        float s1 = 0.f, s2 = 0.f;
#pragma unroll
        for (int i = 0; i < 2; i++) {
            const int idx = lane + i * 32;
            float4 xv = xr[idx], wa = w1[idx], wb = w2[idx];
            s1 += xv.x * wa.x + xv.y * wa.y + xv.z * wa.z + xv.w * wa.w;
            s2 += xv.x * wb.x + xv.y * wb.y + xv.z * wb.z + xv.w * wb.w;
        }
#pragma unroll
        for (int off = 16; off; off >>= 1) {
            s1 += __shfl_xor_sync(0xFFFFFFFFu, s1, off);
            s2 += __shfl_xor_sync(0xFFFFFFFFu, s2, off);
        }
        if (lane == 0) {
            g_sa[q] = 1.f / (1.f + expf(-(s1 + b[1024])));
            g_ss[q] = 1.f / (1.f + expf(-(s2 + b[1025])));
        }
    }
}

// ---------------------------------------------------------------------------
// k_wu_mma: wu[:, 0:1024] = Xh @ (Wh+Wl)^T + b   (fp16 2-term)
// grid (16 ntile, 32 mt), tiles 128 x 64. region = ntile>>2:
//   region 0 (A1) / 2 (S1): smem-transpose -> single fp16 VT
//   region 1 (A2) / 3 (S2): single fp16 -> g_K
// ---------------------------------------------------------------------------
__global__ void __launch_bounds__(256, 3) k_wu_mma(const float* __restrict__ bias) {
    GEMM_PROLOGUE();
    const int mt = blockIdx.y, ntile = blockIdx.x;
    const int m0 = mt * 128, n0 = ntile * 64;
    const int region = ntile >> 2;

    RING_2T(g_Xh + m0 * NI, g_Wh + n0 * NI, g_Wl + n0 * NI);

    const int g = lane >> 2, t2 = (lane & 3) * 2;
    if (region & 1) {
        // A2 / S2 -> single fp16 into g_K rows
#pragma unroll
        for (int mf = 0; mf < 2; mf++) {
            const int q0 = m0 + warp_m + mf * 16 + g;
#pragma unroll
            for (int nf = 0; nf < 4; nf++) {
                const int col = n0 + warp_n + nf * 8 + t2;
                const float b0 = bias[col], b1 = bias[col + 1];
                const float* c = acc[mf][nf];
                const int cc = col & 255;
                const int kr = (region == 1 ? q0 : 4096 + q0);
                *(__half2*)(g_K + kr * 256 + cc) =
                    __floats2half2_rn(c[0] + b0, c[1] + b1);
                *(__half2*)(g_K + (kr + 8) * 256 + cc) =
                    __floats2half2_rn(c[2] + b0, c[3] + b1);
            }
        }
    } else {
        // A1 / S1 -> transposed single fp16 VT via smem (fused trans_V)
        __syncthreads();                      // mainloop smem now dead
        float* sT = (float*)smem;             // [64 cols][pitch 132] fp32
#pragma unroll
        for (int mf = 0; mf < 2; mf++) {
            const int rloc = warp_m + mf * 16 + g;
#pragma unroll
            for (int nf = 0; nf < 4; nf++) {
                const int cl = warp_n + nf * 8 + t2;
                const int col = n0 + cl;
                const float b0 = bias[col], b1 = bias[col + 1];
                const float* c = acc[mf][nf];
                sT[cl * 132 + rloc]           = c[0] + b0;
                sT[(cl + 1) * 132 + rloc]     = c[1] + b1;
                sT[cl * 132 + rloc + 8]       = c[2] + b0;
                sT[(cl + 1) * 132 + rloc + 8] = c[3] + b1;
            }
        }
        __syncthreads();
        const int rz = region >> 1;           // 0: A1, 1: S1
        const int o_loc = tid >> 2;           // 0..63
        const int qh = (tid & 3) * 32;        // 0,32,64,96
        const int o_glob = (ntile & 3) * 64 + o_loc;
        const float* srow = sT + o_loc * 132 + qh;
        const size_t dst = (size_t)o_glob * KCAT + rz * ROWS + m0 + qh;
#pragma unroll
        for (int j8 = 0; j8 < 4; j8++) {
            union { __half h[8]; uint4 u; } H;
#pragma unroll
            for (int e = 0; e < 8; e++)
                H.h[e] = __float2half_rn(srow[j8 * 8 + e]);
            *(uint4*)(g_VT + dst + j8 * 8) = H.u;
        }
    }
}

// ---------------------------------------------------------------------------
// k_base_mma: out = Xh @ (W0h+W0l)^T   (fp16 2-term). grid (4 ot, 32 mt).
// ---------------------------------------------------------------------------
__global__ void __launch_bounds__(256, 3) k_base_mma(float* __restrict__ out) {
    GEMM_PROLOGUE();
    const int mt = blockIdx.y, ot = blockIdx.x;
    const int m0 = mt * 128, o0 = ot * 64;

    RING_2T(g_Xh + m0 * NI, g_W0h + o0 * NI, g_W0l + o0 * NI);

    const int g = lane >> 2, t2 = (lane & 3) * 2;
#pragma unroll
    for (int mf = 0; mf < 2; mf++) {
        const int q = m0 + warp_m + mf * 16 + g;
#pragma unroll
        for (int nf = 0; nf < 4; nf++) {
            const int o = o0 + warp_n + nf * 8 + t2;
            const float* c = acc[mf][nf];
            *(float2*)(out + q * 256 + o)       = make_float2(c[0], c[1]);
            *(float2*)(out + (q + 8) * 256 + o) = make_float2(c[2], c[3]);
        }
    }
}

// ---------------------------------------------------------------------------
// GEMM1 (1-term fp16): P[q,kcat] = fp16( mask*gate * (Xh @ K^T) )
// grid 2112: 2 regions x causal tiles (128 q x 64 keys; nt <= 2mt+1).
// ---------------------------------------------------------------------------
#define EPI_PITCH 72    // fp16 elems per row (144 B, 16B-aligned rows)

__global__ void __launch_bounds__(256, 3) k_gemm1() {
    GEMM_PROLOGUE();
    int i = blockIdx.x, rg = 0;
    if (i >= 1056) { rg = 1; i -= 1056; }
    int mt = 0;                               // cum(mt) = mt*(mt+1)
    while ((mt + 1) * (mt + 2) <= i) mt++;
    const int nt = i - mt * (mt + 1);
    const int m0 = mt * 128;
    const int keybase = nt * 64;

    const __half* A = g_Xh + m0 * NI;
    const __half* B = g_K + (rg * ROWS + keybase) * NI;

    load_stage_1t(sb, A, B, NI, NI, tid); CP_COMMIT();
    load_stage_1t(sb + STAGE_1T, A + 32, B + 32, NI, NI, tid); CP_COMMIT();
#pragma unroll 1
    for (int kc = 0; kc < 8; kc++) {
        asm volatile("cp.async.wait_group 1;");
        __syncthreads();
        if (kc + 2 < 8) {
            const int ko = (kc + 2) * 32;
            load_stage_1t(sb + ((kc + 2) % 3) * STAGE_1T, A + ko, B + ko, NI, NI, tid);
        }
        CP_COMMIT();
        compute_stage_1t(sb + (kc % 3) * STAGE_1T, warp_m, warp_n, lane, acc);
    }

    // Epilogue: gate+mask -> fp16 into smem, then coalesced 16B stores.
    __syncthreads();
    __half* sH = (__half*)smem;               // 128 x 72 fp16
    const int g = lane >> 2, t2 = (lane & 3) * 2;
#pragma unroll
    for (int mf = 0; mf < 2; mf++) {
        const int rloc = warp_m + mf * 16 + g;          // local row; +8 same b
        const int q0 = m0 + rloc;
        const int s0 = q0 >> 3, b = q0 & 7;
#pragma unroll
        for (int nf = 0; nf < 4; nf++) {
            const int cl = warp_n + nf * 8 + t2;        // local col (even)
            const int col = keybase + cl;
            const int t = col >> 3;
            const float gv = rg ? -g_ss[t * 8 + b] : g_sa[t * 8 + b];
            const float sc0 = (t <= s0) ? gv : 0.f;
            const float sc1 = (t <= s0 + 1) ? gv : 0.f;
            const float* c = acc[mf][nf];
            *(__half2*)(sH + rloc * EPI_PITCH + cl) =
                __floats2half2_rn(c[0] * sc0, c[1] * sc0);
            *(__half2*)(sH + (rloc + 8) * EPI_PITCH + cl) =
                __floats2half2_rn(c[2] * sc1, c[3] * sc1);
        }
    }
    __syncthreads();

    const int gbase = rg * ROWS + keybase;
#pragma unroll
    for (int it = tid; it < 1024; it += 256) {
        const int row = it >> 3;
        const int c8 = (it & 7) * 8;
        uint4 v = *(uint4*)(sH + row * EPI_PITCH + c8);
        *(uint4*)(g_P + (size_t)(m0 + row) * KCAT + gbase + c8) = v;
    }
}

// ---------------------------------------------------------------------------
// GEMM2 (1-term fp16): out[q,o] += P @ VT^T. Stage 12 KB, ring 36 KB.
// Tiles 128(q) x 64(o), split-K + f32 atomics.
// Logical k in [0, 256*(mt+1)) maps to phys [0, half) U [4096, 4096+half).
// ---------------------------------------------------------------------------
__global__ void __launch_bounds__(256, 3) k_gemm2(float* __restrict__ out) {
    const int mt = blockIdx.x, ot = blockIdx.y, kc = blockIdx.z;
    const int nch = (mt + 4) >> 2;
    if (kc >= nch) return;
    const int klive = 256 * (mt + 1);
    const int kstart = kc * 1024;
    const int kend = (kstart + 1024 < klive) ? kstart + 1024 : klive;
    const int half = 128 * (mt + 1);
    const int m0 = mt * 128, o0 = ot * 64;
    const int nsteps = (kend - kstart) >> 5;

    GEMM_PROLOGUE();

    const __half* A = g_P + (size_t)m0 * KCAT;
    const __half* B = g_VT + (size_t)o0 * KCAT;

    {
        int pk = (kstart < half) ? kstart : kstart + ROWS - half;
        load_stage_1t(sb, A + pk, B + pk, KCAT, KCAT, tid);
        CP_COMMIT();
        if (nsteps > 1) {
            const int lk = kstart + 32;
            pk = (lk < half) ? lk : lk + ROWS - half;
            load_stage_1t(sb + STAGE_1T, A + pk, B + pk, KCAT, KCAT, tid);
        }
        CP_COMMIT();
    }
#pragma unroll 1
    for (int s = 0; s < nsteps; s++) {
        asm volatile("cp.async.wait_group 1;");
        __syncthreads();
        if (s + 2 < nsteps) {
            const int lk = kstart + (s + 2) * 32;
            const int pk = (lk < half) ? lk : lk + ROWS - half;
            load_stage_1t(sb + ((s + 2) % 3) * STAGE_1T, A + pk, B + pk,
                          KCAT, KCAT, tid);
        }
        CP_COMMIT();
        compute_stage_1t(sb + (s % 3) * STAGE_1T, warp_m, warp_n, lane, acc);
    }

    const int g = lane >> 2, t2 = (lane & 3) * 2;
#pragma unroll
    for (int mf = 0; mf < 2; mf++) {
        const int q = m0 + warp_m + mf * 16 + g;
#pragma unroll
        for (int nf = 0; nf < 4; nf++) {
            const int o = o0 + warp_n + nf * 8 + t2;
            const float* c = acc[mf][nf];
            atomicAdd(out + q * 256 + o,           c[0]);
            atomicAdd(out + q * 256 + o + 1,       c[1]);
            atomicAdd(out + (q + 8) * 256 + o,     c[2]);
            atomicAdd(out + (q + 8) * 256 + o + 1, c[3]);
        }
    }
}

// ---------------------------------------------------------------------------
extern "C" void kernel_launch(void* const* d_in, const int* in_sizes, int n_in,
                              void* d_out, int out_size) {
    const float* x      = (const float*)d_in[0];   // (512,8,256)
    const float* slow_W = (const float*)d_in[1];   // (1026,256)
    const float* slow_b = (const float*)d_in[2];   // (1026,)
    const float* fw0    = (const float*)d_in[3];   // (256,256)
    float* out = (float*)d_out;                    // (512,8,256)

    // Unconditional every call (no static guards — harness contract).
    cudaFuncSetAttribute(k_wu_mma,   cudaFuncAttributeMaxDynamicSharedMemorySize, SMEM_2T);
    cudaFuncSetAttribute(k_base_mma, cudaFuncAttributeMaxDynamicSharedMemorySize, SMEM_2T);
    cudaFuncSetAttribute(k_gemm1,    cudaFuncAttributeMaxDynamicSharedMemorySize, SMEM_1T);
    cudaFuncSetAttribute(k_gemm2,    cudaFuncAttributeMaxDynamicSharedMemorySize, SMEM_1T);

    // k_gemm1 at launch index 3 (the profiled slot).
    k_prep    <<<5888, 256>>>(x, slow_W, fw0, slow_b);
    k_wu_mma  <<<dim3(16, 32), 256, SMEM_2T>>>(slow_b);
    k_base_mma<<<dim3(4, 32), 256, SMEM_2T>>>(out);
    k_gemm1   <<<2112, 256, SMEM_1T>>>();
    k_gemm2   <<<dim3(32, 4, 8), 256, SMEM_1T>>>(out);
}

// round 17
// speedup vs baseline: 8.2837x; 1.0345x over previous
#include <cuda_runtime.h>
#include <cuda_fp16.h>
#include <math.h>
#include <stdint.h>

#define ROWS 4096          // S*B = 512*8
#define KCAT 8192          // concat keys: [A (4096) | S (4096)]
#define NI 256
#define SLOW_OUTS 1026

// ---------------------------------------------------------------------------
// Scratch (device globals) — fp16 operand storage
// ---------------------------------------------------------------------------
__device__ float g_sa[ROWS];
__device__ float g_ss[ROWS];

__device__ __align__(16) __half g_Xh[ROWS * NI];     // X single fp16
__device__ __align__(16) __half g_Wh[1024 * NI];     // slow_W rows 0..1023 hi
__device__ __align__(16) __half g_Wl[1024 * NI];     // lo
__device__ __align__(16) __half g_W0h[NI * NI];      // fast_W0 hi
__device__ __align__(16) __half g_W0l[NI * NI];      // lo
__device__ __align__(16) __half g_K[KCAT * NI];      // [A2 ; S2], single fp16
__device__ __align__(16) __half g_VT[NI * KCAT];     // [A1;S1]^T, single fp16
__device__ __align__(16) __half g_P[(size_t)ROWS * KCAT];  // fp16 P, 64 MB

// ---------------------------------------------------------------------------
// Helpers
// ---------------------------------------------------------------------------
__device__ __forceinline__ uint32_t smem_to_u32(const void* p) {
    uint32_t a;
    asm("{ .reg .u64 t; cvta.to.shared.u64 t, %1; cvt.u32.u64 %0, t; }" : "=r"(a) : "l"(p));
    return a;
}

__device__ __forceinline__ void cpa16(uint32_t s, const void* g) {
    asm volatile("cp.async.cg.shared.global [%0], [%1], 16;"
        :: "r"(s), "l"(__cvta_generic_to_global(g)));
}
#define CP_COMMIT() asm volatile("cp.async.commit_group;")

__device__ __forceinline__ void ldx4(uint32_t* r, uint32_t addr) {
    asm volatile("ldmatrix.sync.aligned.m8n8.x4.shared.b16 {%0,%1,%2,%3}, [%4];"
        : "=r"(r[0]), "=r"(r[1]), "=r"(r[2]), "=r"(r[3]) : "r"(addr));
}

__device__ __forceinline__ void mmah(float* c, const uint32_t* a, const uint32_t* b) {
    asm volatile(
        "mma.sync.aligned.m16n8k16.row.col.f32.f16.f16.f32 "
        "{%0,%1,%2,%3}, {%4,%5,%6,%7}, {%8,%9}, {%0,%1,%2,%3};"
        : "+f"(c[0]), "+f"(c[1]), "+f"(c[2]), "+f"(c[3])
        : "r"(a[0]), "r"(a[1]), "r"(a[2]), "r"(a[3]), "r"(b[0]), "r"(b[1]));
}

// CTA tile 128(M) x 128(N), 8 warps of 32(M) x 64(N). K-stage 32.
// 64B rows, XOR-swizzled 16B segments -> conflict-free ldmatrix / STS.128.
#define ROWB    64
#define SWZ(row, seg) (((seg) ^ (((row) >> 1) & 3)) << 4)

// ---- 1-term layout (gemm1/gemm2): A 128r + B 128r, stage 16 KB ----
#define O1T_A   0
#define O1T_B   8192
#define STAGE_1T 16384
#define SMEM_1T (3 * STAGE_1T)

// ---- 2-term layout (wu/base): A 128r + Bh 128r + Bl 128r, stage 24 KB ----
#define O2T_A   0
#define O2T_BH  8192
#define O2T_BL  16384
#define STAGE_2T 24576
#define SMEM_2T (3 * STAGE_2T)

__device__ __forceinline__ void load_stage_1t(uint32_t st,
    const __half* A, const __half* B, int sA, int sB, int tid)
{
#pragma unroll
    for (int h = 0; h < 2; h++) {                 // 128 rows x 4 segs each
        int c = tid + h * 256;
        int row = c >> 2, seg = c & 3;
        uint32_t off = row * ROWB + SWZ(row, seg);
        int go = seg * 8;
        cpa16(st + O1T_A + off, A + row * sA + go);
        cpa16(st + O1T_B + off, B + row * sB + go);
    }
}

__device__ __forceinline__ void load_stage_2t(uint32_t st,
    const __half* A, const __half* Bh, const __half* Bl, int tid)
{
#pragma unroll
    for (int h = 0; h < 2; h++) {
        int c = tid + h * 256;
        int row = c >> 2, seg = c & 3;
        uint32_t off = row * ROWB + SWZ(row, seg);
        int go = seg * 8;
        cpa16(st + O2T_A + off, A + row * NI + go);
        cpa16(st + O2T_BH + off, Bh + row * NI + go);
        cpa16(st + O2T_BL + off, Bl + row * NI + go);
    }
}

// 1-term: acc += A*B. Warp tile 32x64: acc[2][8][4].
__device__ __forceinline__ void compute_stage_1t(uint32_t st, int warp_m, int warp_n,
                                                 int lane, float acc[2][8][4])
{
    const int rowsel = lane & 15;
    const int chalf = lane >> 4;
#pragma unroll
    for (int k16 = 0; k16 < 2; k16++) {
        const int c0 = k16 * 2 + chalf;
        uint32_t a[2][4];
#pragma unroll
        for (int mf = 0; mf < 2; mf++) {
            const int row = warp_m + mf * 16 + rowsel;
            ldx4(a[mf], st + O1T_A + row * ROWB + SWZ(row, c0));
        }
#pragma unroll
        for (int np = 0; np < 4; np++) {
            const int row = warp_n + np * 16 + rowsel;
            uint32_t rb[4];
            ldx4(rb, st + O1T_B + row * ROWB + SWZ(row, c0));
            uint32_t b0[2] = {rb[0], rb[2]}, b1[2] = {rb[1], rb[3]};
#pragma unroll
            for (int mf = 0; mf < 2; mf++) {
                mmah(acc[mf][2 * np],     a[mf], b0);
                mmah(acc[mf][2 * np + 1], a[mf], b1);
            }
        }
    }
}

// 2-term: acc += A*Bh + A*Bl.
__device__ __forceinline__ void compute_stage_2t(uint32_t st, int warp_m, int warp_n,
                                                 int lane, float acc[2][8][4])
{
    const int rowsel = lane & 15;
    const int chalf = lane >> 4;
#pragma unroll
    for (int k16 = 0; k16 < 2; k16++) {
        const int c0 = k16 * 2 + chalf;
        uint32_t a[2][4];
#pragma unroll
        for (int mf = 0; mf < 2; mf++) {
            const int row = warp_m + mf * 16 + rowsel;
            ldx4(a[mf], st + O2T_A + row * ROWB + SWZ(row, c0));
        }
#pragma unroll
        for (int np = 0; np < 4; np++) {
            const int row = warp_n + np * 16 + rowsel;
            uint32_t off = row * ROWB + SWZ(row, c0);
            uint32_t rbh[4], rbl[4];
            ldx4(rbh, st + O2T_BH + off);
            ldx4(rbl, st + O2T_BL + off);
            uint32_t bh0[2] = {rbh[0], rbh[2]}, bh1[2] = {rbh[1], rbh[3]};
            uint32_t bl0[2] = {rbl[0], rbl[2]}, bl1[2] = {rbl[1], rbl[3]};
#pragma unroll
            for (int mf = 0; mf < 2; mf++) {
                mmah(acc[mf][2 * np],     a[mf], bh0);
                mmah(acc[mf][2 * np + 1], a[mf], bh1);
                mmah(acc[mf][2 * np],     a[mf], bl0);
                mmah(acc[mf][2 * np + 1], a[mf], bl1);
            }
        }
    }
}

#define GEMM_PROLOGUE()                                                        \
    extern __shared__ char smem[];                                             \
    const uint32_t sb = smem_to_u32(smem);                                     \
    const int tid = threadIdx.x, lane = tid & 31, wid = tid >> 5;              \
    const int warp_m = (wid >> 1) * 32, warp_n = (wid & 1) * 64;               \
    float acc[2][8][4];                                                        \
    _Pragma("unroll") for (int a_ = 0; a_ < 2; a_++)                           \
    _Pragma("unroll") for (int b_ = 0; b_ < 8; b_++)                           \
    _Pragma("unroll") for (int c_ = 0; c_ < 4; c_++) acc[a_][b_][c_] = 0.f;

// 3-stage rings, K=256 (8 stages). ORDER IS LOAD-BEARING:
// wait_group -> __syncthreads (publishes all threads' data) -> prefetch.
#define RING_2T(A, Bh, Bl)                                                     \
    load_stage_2t(sb, (A), (Bh), (Bl), tid); CP_COMMIT();                      \
    load_stage_2t(sb + STAGE_2T, (A) + 32, (Bh) + 32, (Bl) + 32, tid);         \
    CP_COMMIT();                                                               \
    _Pragma("unroll 1") for (int kc = 0; kc < 8; kc++) {                       \
        asm volatile("cp.async.wait_group 1;");                                \
        __syncthreads();                                                       \
        if (kc + 2 < 8) {                                                      \
            const int ko = (kc + 2) * 32;                                      \
            load_stage_2t(sb + ((kc + 2) % 3) * STAGE_2T, (A) + ko,            \
                          (Bh) + ko, (Bl) + ko, tid);                          \
        }                                                                      \
        CP_COMMIT();                                                           \
        compute_stage_2t(sb + (kc % 3) * STAGE_2T, warp_m, warp_n, lane, acc); \
    }

// ---------------------------------------------------------------------------
// k_prep: X->fp16, W/W0 hi-lo splits, sigmoid gates. grid 5888 x 256.
// ---------------------------------------------------------------------------
__global__ void k_prep(const float* __restrict__ x, const float* __restrict__ W,
                       const float* __restrict__ W0, const float* __restrict__ b) {
    const int blk = blockIdx.x;
    const int tid = threadIdx.x;
    if (blk < 4096) {                       // X -> single fp16
        const int i = blk * 256 + tid;
        g_Xh[i] = __float2half_rn(x[i]);
    } else if (blk < 5120) {                // split slow_W rows 0..1023
        const int i = (blk - 4096) * 256 + tid;
        float v = W[i];
        __half h = __float2half_rn(v);
        g_Wh[i] = h;
        g_Wl[i] = __float2half_rn(v - __half2float(h));
    } else if (blk < 5376) {                // split fast_W0
        const int i = (blk - 5120) * 256 + tid;
        float v = W0[i];
        __half h = __float2half_rn(v);
        g_W0h[i] = h;
        g_W0l[i] = __float2half_rn(v - __half2float(h));
    } else {                                // gates (fp32 exact)
        const int q = (blk - 5376) * 8 + (tid >> 5);
        const int lane = tid & 31;
        const float4* xr = (const float4*)(x + q * 256);
        const float4* w1 = (const float4*)(W + 1024 * 256);
        const float4* w2 = (const float4*)(W + 1025 * 256);
        float s1 = 0.f, s2 = 0.f;
#pragma unroll
        for (int i = 0; i < 2; i++) {
            const int idx = lane + i * 32;
            float4 xv = xr[idx], wa = w1[idx], wb = w2[idx];
            s1 += xv.x * wa.x + xv.y * wa.y + xv.z * wa.z + xv.w * wa.w;
            s2 += xv.x * wb.x + xv.y * wb.y + xv.z * wb.z + xv.w * wb.w;
        }
#pragma unroll
        for (int off = 16; off; off >>= 1) {
            s1 += __shfl_xor_sync(0xFFFFFFFFu, s1, off);
            s2 += __shfl_xor_sync(0xFFFFFFFFu, s2, off);
        }
        if (lane == 0) {
            g_sa[q] = 1.f / (1.f + expf(-(s1 + b[1024])));
            g_ss[q] = 1.f / (1.f + expf(-(s2 + b[1025])));
        }
    }
}

// ---------------------------------------------------------------------------
// k_wu_mma: wu[:, 0:1024] = Xh @ (Wh+Wl)^T + b   (fp16 2-term)
// grid (8 ntile, 32 mt), tiles 128 x 128. region = ntile>>1:
//   region 0 (A1) / 2 (S1): smem-transpose -> single fp16 VT
//   region 1 (A2) / 3 (S2): single fp16 -> g_K
// ---------------------------------------------------------------------------
__global__ void __launch_bounds__(256, 2) k_wu_mma(const float* __restrict__ bias) {
    GEMM_PROLOGUE();
    const int mt = blockIdx.y, ntile = blockIdx.x;
    const int m0 = mt * 128, n0 = ntile * 128;
    const int region = ntile >> 1;

    RING_2T(g_Xh + m0 * NI, g_Wh + n0 * NI, g_Wl + n0 * NI);

    const int g = lane >> 2, t2 = (lane & 3) * 2;
    if (region & 1) {
        // A2 / S2 -> single fp16 into g_K rows
#pragma unroll
        for (int mf = 0; mf < 2; mf++) {
            const int q0 = m0 + warp_m + mf * 16 + g;
#pragma unroll
            for (int nf = 0; nf < 8; nf++) {
                const int col = n0 + warp_n + nf * 8 + t2;
                const float b0 = bias[col], b1 = bias[col + 1];
                const float* c = acc[mf][nf];
                const int cc = col & 255;
                const int kr = (region == 1 ? q0 : 4096 + q0);
                *(__half2*)(g_K + kr * 256 + cc) =
                    __floats2half2_rn(c[0] + b0, c[1] + b1);
                *(__half2*)(g_K + (kr + 8) * 256 + cc) =
                    __floats2half2_rn(c[2] + b0, c[3] + b1);
            }
        }
    } else {
        // A1 / S1 -> transposed single fp16 VT via smem (fused trans_V)
        __syncthreads();                      // mainloop smem now dead
        float* sT = (float*)smem;             // [128 cols][pitch 132] fp32
#pragma unroll
        for (int mf = 0; mf < 2; mf++) {
            const int rloc = warp_m + mf * 16 + g;
#pragma unroll
            for (int nf = 0; nf < 8; nf++) {
                const int cl = warp_n + nf * 8 + t2;
                const int col = n0 + cl;
                const float b0 = bias[col], b1 = bias[col + 1];
                const float* c = acc[mf][nf];
                sT[cl * 132 + rloc]           = c[0] + b0;
                sT[(cl + 1) * 132 + rloc]     = c[1] + b1;
                sT[cl * 132 + rloc + 8]       = c[2] + b0;
                sT[(cl + 1) * 132 + rloc + 8] = c[3] + b1;
            }
        }
        __syncthreads();
        const int rz = region >> 1;           // 0: A1, 1: S1
        const int o_loc = tid >> 1;           // 0..127
        const int qh = (tid & 1) * 64;        // 0 or 64
        const int o_glob = (ntile & 1) * 128 + o_loc;
        const float* srow = sT + o_loc * 132 + qh;
        const size_t dst = (size_t)o_glob * KCAT + rz * ROWS + m0 + qh;
#pragma unroll
        for (int j8 = 0; j8 < 8; j8++) {
            union { __half h[8]; uint4 u; } H;
#pragma unroll
            for (int e = 0; e < 8; e++)
                H.h[e] = __float2half_rn(srow[j8 * 8 + e]);
            *(uint4*)(g_VT + dst + j8 * 8) = H.u;
        }
    }
}

// ---------------------------------------------------------------------------
// k_base_mma: out = Xh @ (W0h+W0l)^T   (fp16 2-term). grid (2 ot, 32 mt).
// ---------------------------------------------------------------------------
__global__ void __launch_bounds__(256, 2) k_base_mma(float* __restrict__ out) {
    GEMM_PROLOGUE();
    const int mt = blockIdx.y, ot = blockIdx.x;
    const int m0 = mt * 128, o0 = ot * 128;

    RING_2T(g_Xh + m0 * NI, g_W0h + o0 * NI, g_W0l + o0 * NI);

    const int g = lane >> 2, t2 = (lane & 3) * 2;
#pragma unroll
    for (int mf = 0; mf < 2; mf++) {
        const int q = m0 + warp_m + mf * 16 + g;
#pragma unroll
        for (int nf = 0; nf < 8; nf++) {
            const int o = o0 + warp_n + nf * 8 + t2;
            const float* c = acc[mf][nf];
            *(float2*)(out + q * 256 + o)       = make_float2(c[0], c[1]);
            *(float2*)(out + (q + 8) * 256 + o) = make_float2(c[2], c[3]);
        }
    }
}

// ---------------------------------------------------------------------------
// GEMM1 (1-term fp16): P[q,kcat] = fp16( mask*gate * (Xh @ K^T) )
// grid 1056: 2 regions x lower-triangular 128x128 tiles (nt <= mt).
// ---------------------------------------------------------------------------
#define EPI_PITCH 136   // fp16 elems per row (272 B, 16B-aligned rows)

__global__ void __launch_bounds__(256, 2) k_gemm1() {
    GEMM_PROLOGUE();
    int i = blockIdx.x, rg = 0;
    if (i >= 528) { rg = 1; i -= 528; }
    int mt = 0;                               // cum(mt) = mt*(mt+1)/2
    while ((mt + 1) * (mt + 2) / 2 <= i) mt++;
    const int nt = i - mt * (mt + 1) / 2;
    const int m0 = mt * 128;
    const int keybase = nt * 128;

    const __half* A = g_Xh + m0 * NI;
    const __half* B = g_K + (rg * ROWS + keybase) * NI;

    load_stage_1t(sb, A, B, NI, NI, tid); CP_COMMIT();
    load_stage_1t(sb + STAGE_1T, A + 32, B + 32, NI, NI, tid); CP_COMMIT();
#pragma unroll 1
    for (int kc = 0; kc < 8; kc++) {
        asm volatile("cp.async.wait_group 1;");
        __syncthreads();
        if (kc + 2 < 8) {
            const int ko = (kc + 2) * 32;
            load_stage_1t(sb + ((kc + 2) % 3) * STAGE_1T, A + ko, B + ko, NI, NI, tid);
        }
        CP_COMMIT();
        compute_stage_1t(sb + (kc % 3) * STAGE_1T, warp_m, warp_n, lane, acc);
    }

    // Epilogue: gate+mask -> fp16 into smem, then coalesced 16B stores.
    __syncthreads();
    __half* sH = (__half*)smem;               // 128 x 136 fp16 (34816 B)
    const int g = lane >> 2, t2 = (lane & 3) * 2;
#pragma unroll
    for (int mf = 0; mf < 2; mf++) {
        const int rloc = warp_m + mf * 16 + g;          // local row; +8 same b
        const int q0 = m0 + rloc;
        const int s0 = q0 >> 3, b = q0 & 7;
#pragma unroll
        for (int nf = 0; nf < 8; nf++) {
            const int cl = warp_n + nf * 8 + t2;        // local col (even)
            const int col = keybase + cl;
            const int t = col >> 3;
            const float gv = rg ? -g_ss[t * 8 + b] : g_sa[t * 8 + b];
            const float sc0 = (t <= s0) ? gv : 0.f;
            const float sc1 = (t <= s0 + 1) ? gv : 0.f;
            const float* c = acc[mf][nf];
            *(__half2*)(sH + rloc * EPI_PITCH + cl) =
                __floats2half2_rn(c[0] * sc0, c[1] * sc0);
            *(__half2*)(sH + (rloc + 8) * EPI_PITCH + cl) =
                __floats2half2_rn(c[2] * sc1, c[3] * sc1);
        }
    }
    __syncthreads();

    const int gbase = rg * ROWS + keybase;
#pragma unroll
    for (int it = tid; it < 2048; it += 256) {
        const int row = it >> 4;
        const int c8 = (it & 15) * 8;
        uint4 v = *(uint4*)(sH + row * EPI_PITCH + c8);
        *(uint4*)(g_P + (size_t)(m0 + row) * KCAT + gbase + c8) = v;
    }
}

// ---------------------------------------------------------------------------
// GEMM2 (1-term fp16): out[q,o] += P @ VT^T. Tiles 128(q) x 128(o).
// Split-K + f32 atomics. Logical k in [0, 256*(mt+1)) maps to
// phys [0, half) U [4096, 4096+half). grid (32 mt, 2 ot, 8 kc).
// ---------------------------------------------------------------------------
__global__ void __launch_bounds__(256, 2) k_gemm2(float* __restrict__ out) {
    const int mt = blockIdx.x, ot = blockIdx.y, kc = blockIdx.z;
    const int nch = (mt + 4) >> 2;
    if (kc >= nch) return;
    const int klive = 256 * (mt + 1);
    const int kstart = kc * 1024;
    const int kend = (kstart + 1024 < klive) ? kstart + 1024 : klive;
    const int half = 128 * (mt + 1);
    const int m0 = mt * 128, o0 = ot * 128;
    const int nsteps = (kend - kstart) >> 5;

    GEMM_PROLOGUE();

    const __half* A = g_P + (size_t)m0 * KCAT;
    const __half* B = g_VT + (size_t)o0 * KCAT;

    {
        int pk = (kstart < half) ? kstart : kstart + ROWS - half;
        load_stage_1t(sb, A + pk, B + pk, KCAT, KCAT, tid);
        CP_COMMIT();
        if (nsteps > 1) {
            const int lk = kstart + 32;
            pk = (lk < half) ? lk : lk + ROWS - half;
            load_stage_1t(sb + STAGE_1T, A + pk, B + pk, KCAT, KCAT, tid);
        }
        CP_COMMIT();
    }
#pragma unroll 1
    for (int s = 0; s < nsteps; s++) {
        asm volatile("cp.async.wait_group 1;");
        __syncthreads();
        if (s + 2 < nsteps) {
            const int lk = kstart + (s + 2) * 32;
            const int pk = (lk < half) ? lk : lk + ROWS - half;
            load_stage_1t(sb + ((s + 2) % 3) * STAGE_1T, A + pk, B + pk,
                          KCAT, KCAT, tid);
        }
        CP_COMMIT();
        compute_stage_1t(sb + (s % 3) * STAGE_1T, warp_m, warp_n, lane, acc);
    }

    const int g = lane >> 2, t2 = (lane & 3) * 2;
#pragma unroll
    for (int mf = 0; mf < 2; mf++) {
        const int q = m0 + warp_m + mf * 16 + g;
#pragma unroll
        for (int nf = 0; nf < 8; nf++) {
            const int o = o0 + warp_n + nf * 8 + t2;
            const float* c = acc[mf][nf];
            atomicAdd(out + q * 256 + o,           c[0]);
            atomicAdd(out + q * 256 + o + 1,       c[1]);
            atomicAdd(out + (q + 8) * 256 + o,     c[2]);
            atomicAdd(out + (q + 8) * 256 + o + 1, c[3]);
        }
    }
}

// ---------------------------------------------------------------------------
extern "C" void kernel_launch(void* const* d_in, const int* in_sizes, int n_in,
                              void* d_out, int out_size) {
    const float* x      = (const float*)d_in[0];   // (512,8,256)
    const float* slow_W = (const float*)d_in[1];   // (1026,256)
    const float* slow_b = (const float*)d_in[2];   // (1026,)
    const float* fw0    = (const float*)d_in[3];   // (256,256)
    float* out = (float*)d_out;                    // (512,8,256)

    // Unconditional every call (no static guards — harness contract).
    cudaFuncSetAttribute(k_wu_mma,   cudaFuncAttributeMaxDynamicSharedMemorySize, SMEM_2T);
    cudaFuncSetAttribute(k_base_mma, cudaFuncAttributeMaxDynamicSharedMemorySize, SMEM_2T);
    cudaFuncSetAttribute(k_gemm1,    cudaFuncAttributeMaxDynamicSharedMemorySize, SMEM_1T);
    cudaFuncSetAttribute(k_gemm2,    cudaFuncAttributeMaxDynamicSharedMemorySize, SMEM_1T);

    // k_gemm1 at launch index 3 (the profiled slot).
    k_prep    <<<5888, 256>>>(x, slow_W, fw0, slow_b);
    k_wu_mma  <<<dim3(8, 32), 256, SMEM_2T>>>(slow_b);
    k_base_mma<<<dim3(2, 32), 256, SMEM_2T>>>(out);
    k_gemm1   <<<1056, 256, SMEM_1T>>>();
    k_gemm2   <<<dim3(32, 2, 8), 256, SMEM_1T>>>(out);
}